// round 4
// baseline (speedup 1.0000x reference)
#include <cuda_runtime.h>
#include <cuda_bf16.h>
#include <math.h>
#include <stdint.h>

#define BB 4
#define NN 8192
#define DIMV 256
#define HH 8
#define HD 32
#define INTERNAL 256
#define MROWS (BB * NN)        // 32768
#define QKVO_COLS 1024
#define SCALE_F 0.17677669529663687f

// ---------------- persistent device scratch (no allocations) ----------------
__device__ float g_qkvo[(size_t)MROWS * QKVO_COLS];   // 134 MB
__device__ float g_pre [(size_t)MROWS * INTERNAL];    // 33.5 MB
__device__ float g_kv  [BB * HH * HD * HD];
__device__ float g_ksum[BB * HH * HD];
__device__ float g_vsum[BB * HH * HD];

__device__ __forceinline__ uint32_t smem_u32(const void* p) {
    uint32_t a;
    asm("{ .reg .u64 t; cvta.to.shared.u64 t, %1; cvt.u32.u64 %0, t; }"
        : "=r"(a) : "l"(p));
    return a;
}

__device__ __forceinline__ void split2(float a, float b, uint32_t& hi, uint32_t& lo) {
    __nv_bfloat162 h = __floats2bfloat162_rn(a, b);
    float ra = a - __bfloat162float(h.x);
    float rb = b - __bfloat162float(h.y);
    __nv_bfloat162 l = __floats2bfloat162_rn(ra, rb);
    hi = *reinterpret_cast<uint32_t*>(&h);
    lo = *reinterpret_cast<uint32_t*>(&l);
}

__device__ __forceinline__ void ldmx4(uint32_t* r, uint32_t addr) {
    asm volatile("ldmatrix.sync.aligned.m8n8.x4.shared.b16 {%0,%1,%2,%3}, [%4];"
        : "=r"(r[0]), "=r"(r[1]), "=r"(r[2]), "=r"(r[3]) : "r"(addr));
}

__device__ __forceinline__ void mma16816(float* d, const uint32_t* a,
                                         uint32_t b0, uint32_t b1) {
    asm volatile(
        "mma.sync.aligned.m16n8k16.row.col.f32.bf16.bf16.f32 "
        "{%0,%1,%2,%3}, {%4,%5,%6,%7}, {%8,%9}, {%0,%1,%2,%3};"
        : "+f"(d[0]), "+f"(d[1]), "+f"(d[2]), "+f"(d[3])
        : "r"(a[0]), "r"(a[1]), "r"(a[2]), "r"(a[3]), "r"(b0), "r"(b1));
}

// =================== HMMA GEMM: C[M,Nn] = A[M,K] @ Bw[Nn,K]^T + bias ========
#define ROWB 80
#define A_HI 0
#define A_LO 10240
#define B_HI 20480
#define B_LO 30720
#define BUFB 40960
#define GEMM_SMEM_BYTES (2 * BUFB)   // 80 KB

__global__ void __launch_bounds__(256)
gemm_mma_kernel(const float* __restrict__ A, const float* __restrict__ Bw,
                const float* __restrict__ bias, float* __restrict__ C,
                int M, int Nn, int K)
{
    extern __shared__ char sm[];
    const uint32_t smb = smem_u32(sm);
    const int tid  = threadIdx.x;
    const int wid  = tid >> 5;
    const int lane = tid & 31;
    const int m0 = blockIdx.y * 128;
    const int n0 = blockIdx.x * 128;
    const int wm0 = (wid & 3) * 32;
    const int wn0 = (wid >> 2) * 64;

    const int a_row = (lane & 7) + ((lane >> 3) & 1) * 8;
    const int a_kh  = (lane >> 4) * 8;
    const int b_row = (lane & 7) + ((lane >> 4) & 1) * 8;
    const int b_kh  = ((lane >> 3) & 1) * 8;

    float acc[2][8][4];
#pragma unroll
    for (int i = 0; i < 2; i++)
#pragma unroll
        for (int j = 0; j < 8; j++)
#pragma unroll
            for (int l = 0; l < 4; l++) acc[i][j][l] = 0.f;

    const int NCH = K / 32;
    const int row_g = tid >> 3;
    const int q_g   = tid & 7;

    float4 stA[4], stB[4];

#pragma unroll
    for (int i = 0; i < 4; i++) {
        int r = row_g + i * 32;
        stA[i] = *(const float4*)&A [(size_t)(m0 + r) * K + q_g * 4];
        stB[i] = *(const float4*)&Bw[(size_t)(n0 + r) * K + q_g * 4];
    }
    {
        char* buf = sm;
#pragma unroll
        for (int i = 0; i < 4; i++) {
            int r = row_g + i * 32;
            uint2 hi, lo;
            split2(stA[i].x, stA[i].y, hi.x, lo.x);
            split2(stA[i].z, stA[i].w, hi.y, lo.y);
            *(uint2*)(buf + A_HI + r * ROWB + q_g * 8) = hi;
            *(uint2*)(buf + A_LO + r * ROWB + q_g * 8) = lo;
            split2(stB[i].x, stB[i].y, hi.x, lo.x);
            split2(stB[i].z, stB[i].w, hi.y, lo.y);
            *(uint2*)(buf + B_HI + r * ROWB + q_g * 8) = hi;
            *(uint2*)(buf + B_LO + r * ROWB + q_g * 8) = lo;
        }
    }
    __syncthreads();

    for (int c = 0; c < NCH; c++) {
        if (c + 1 < NCH) {
            int k0 = (c + 1) * 32;
#pragma unroll
            for (int i = 0; i < 4; i++) {
                int r = row_g + i * 32;
                stA[i] = *(const float4*)&A [(size_t)(m0 + r) * K + k0 + q_g * 4];
                stB[i] = *(const float4*)&Bw[(size_t)(n0 + r) * K + k0 + q_g * 4];
            }
        }

        const uint32_t base = smb + (c & 1) * BUFB;
#pragma unroll
        for (int ks = 0; ks < 2; ks++) {
            uint32_t ah[2][4], al[2][4];
#pragma unroll
            for (int mf = 0; mf < 2; mf++) {
                uint32_t ao = base + (wm0 + mf * 16 + a_row) * ROWB
                            + (ks * 16 + a_kh) * 2;
                ldmx4(ah[mf], ao + A_HI);
                ldmx4(al[mf], ao + A_LO);
            }
#pragma unroll
            for (int nf2 = 0; nf2 < 4; nf2++) {
                uint32_t bo = base + (wn0 + nf2 * 16 + b_row) * ROWB
                            + (ks * 16 + b_kh) * 2;
                uint32_t bh[4], bl[4];
                ldmx4(bh, bo + B_HI);
                ldmx4(bl, bo + B_LO);
#pragma unroll
                for (int mf = 0; mf < 2; mf++) {
#pragma unroll
                    for (int s = 0; s < 2; s++) {
                        float* d = acc[mf][nf2 * 2 + s];
                        mma16816(d, ah[mf], bh[s * 2], bh[s * 2 + 1]);
                        mma16816(d, al[mf], bh[s * 2], bh[s * 2 + 1]);
                        mma16816(d, ah[mf], bl[s * 2], bl[s * 2 + 1]);
                    }
                }
            }
        }

        if (c + 1 < NCH) {
            char* buf = sm + ((c + 1) & 1) * BUFB;
#pragma unroll
            for (int i = 0; i < 4; i++) {
                int r = row_g + i * 32;
                uint2 hi, lo;
                split2(stA[i].x, stA[i].y, hi.x, lo.x);
                split2(stA[i].z, stA[i].w, hi.y, lo.y);
                *(uint2*)(buf + A_HI + r * ROWB + q_g * 8) = hi;
                *(uint2*)(buf + A_LO + r * ROWB + q_g * 8) = lo;
                split2(stB[i].x, stB[i].y, hi.x, lo.x);
                split2(stB[i].z, stB[i].w, hi.y, lo.y);
                *(uint2*)(buf + B_HI + r * ROWB + q_g * 8) = hi;
                *(uint2*)(buf + B_LO + r * ROWB + q_g * 8) = lo;
            }
        }
        __syncthreads();
    }

    const int rr = lane >> 2;
    const int cc = (lane & 3) * 2;
#pragma unroll
    for (int mf = 0; mf < 2; mf++) {
        int r0 = m0 + wm0 + mf * 16 + rr;
#pragma unroll
        for (int nf = 0; nf < 8; nf++) {
            int col = n0 + wn0 + nf * 8 + cc;
            float b0 = bias[col], b1 = bias[col + 1];
            float2 v0 = {acc[mf][nf][0] + b0, acc[mf][nf][1] + b1};
            float2 v1 = {acc[mf][nf][2] + b0, acc[mf][nf][3] + b1};
            *(float2*)&C[(size_t)r0 * Nn + col] = v0;
            *(float2*)&C[(size_t)(r0 + 8) * Nn + col] = v1;
        }
    }
}

// ---------------- zero accumulators ----------------------------------------
__global__ void zero_kernel() {
    int i = blockIdx.x * 256 + threadIdx.x;
    if (i < BB * HH * HD * HD) g_kv[i] = 0.f;
    if (i < BB * HH * HD) { g_ksum[i] = 0.f; g_vsum[i] = 0.f; }
}

// ---------------- stats: kv_state / ksum / vsum per (b,h) ------------------
__global__ void __launch_bounds__(256)
stats_kernel(const float* __restrict__ qkvo,
             const float* __restrict__ sinp, const float* __restrict__ cosp)
{
    __shared__ float sks[8][32];
    __shared__ float svh[8][32];

    const int bh = blockIdx.x;
    const int split = blockIdx.y;
    const int b = bh >> 3, h = bh & 7;
    const int w = threadIdx.x >> 5;
    const int lane = threadIdx.x & 31;
    const int n_start = split * (NN / 32);

    const int dA = threadIdx.x >> 3;
    const int e4 = (threadIdx.x & 7) * 4;

    float kv0 = 0.f, kv1 = 0.f, kv2 = 0.f, kv3 = 0.f;
    float ksum_acc = 0.f, vsum_acc = 0.f;

    for (int c0 = 0; c0 < NN / 32; c0 += 8) {
        int n = n_start + c0 + w;
        size_t row = (size_t)(b * NN + n) * QKVO_COLS;
        float kraw = qkvo[row + 256 + h * 32 + lane];
        float v    = qkvo[row + 512 + h * 32 + lane];
        float kh = (kraw > 0.f) ? (kraw + 1.f) : expf(kraw);
        ksum_acc += kh;
        vsum_acc += v;
        float partner = __shfl_xor_sync(0xffffffffu, kh, 1);
        float sv = sinp[n * HD + lane];
        float cv = cosp[n * HD + lane];
        float rot = (lane & 1) ? partner : -partner;
        float ks = kh * cv + rot * sv;
        sks[w][lane] = ks;
        svh[w][lane] = v;
        __syncthreads();
#pragma unroll
        for (int j = 0; j < 8; j++) {
            float a = sks[j][dA];
            float4 vv = *(const float4*)&svh[j][e4];
            kv0 += a * vv.x;
            kv1 += a * vv.y;
            kv2 += a * vv.z;
            kv3 += a * vv.w;
        }
        __syncthreads();
    }

    float* kvdst = &g_kv[bh * (HD * HD) + dA * HD + e4];
    atomicAdd(kvdst + 0, kv0);
    atomicAdd(kvdst + 1, kv1);
    atomicAdd(kvdst + 2, kv2);
    atomicAdd(kvdst + 3, kv3);
    atomicAdd(&g_ksum[bh * HD + lane], ksum_acc);
    atomicAdd(&g_vsum[bh * HD + lane], vsum_acc);
}

// ---------------- fused per-token epilogue (lane-per-token) -> g_pre --------
// Block: 32 tokens x 8 heads. Warp = one head; lane = one token.
// All of elu / z-dot / theta-shift are in-lane. Matvec uses LDS broadcast.
__global__ void __launch_bounds__(256)
fuse_kernel(const float* __restrict__ qkvo,
            const float* __restrict__ sinp, const float* __restrict__ cosp,
            const float* __restrict__ W_lepe, const float* __restrict__ b_lepe,
            float* __restrict__ pre)
{
    __shared__ float skv[HH * HD * HD];        // scaled kv, 32 KB
    __shared__ float sksum[INTERNAL];          // raw k sums
    __shared__ float svm[INTERNAL];            // v means
    __shared__ float sw0[INTERNAL], sw1[INTERNAL], sw2[INTERNAL], sbl[INTERNAL];
    __shared__ float ssin[32][33], scos[32][33];

    const int tid  = threadIdx.x;
    const int wid  = tid >> 5;                 // head
    const int lane = tid & 31;                 // token within tile
    const int nb   = blockIdx.x * 32;          // global row base (never straddles batch)
    const int b    = nb / NN;
    const int nloc0 = nb - b * NN;
    const int nloc = nloc0 + lane;
    const size_t nrow = (size_t)(nb + lane);
    const float inv_scale_n = SCALE_F / (float)NN;

    // ---- stage shared data ----
    for (int i = tid; i < HH * HD * HD; i += 256)
        skv[i] = g_kv[b * HH * HD * HD + i] * inv_scale_n;
    sksum[tid] = g_ksum[b * INTERNAL + tid];
    svm[tid]   = g_vsum[b * INTERNAL + tid] * (1.f / NN);
    sw0[tid] = W_lepe[tid * 3 + 0];
    sw1[tid] = W_lepe[tid * 3 + 1];
    sw2[tid] = W_lepe[tid * 3 + 2];
    sbl[tid] = b_lepe[tid];
#pragma unroll
    for (int i = tid; i < 32 * 32; i += 256) {
        int r = i >> 5, d = i & 31;
        ssin[r][d] = sinp[(size_t)(nloc0 + r) * HD + d];
        scos[r][d] = cosp[(size_t)(nloc0 + r) * HD + d];
    }
    __syncthreads();

    const float* qrow = &qkvo[nrow * QKVO_COLS + wid * HD];
    const float* vrow = qrow + 512;
    const float* orow = qrow + 768;

    // ---- qh = elu(q) + 1 (front-batched loads for MLP) ----
    float qh[32];
#pragma unroll
    for (int i = 0; i < 8; i++) {
        float4 t = *(const float4*)&qrow[i * 4];
        qh[i * 4 + 0] = (t.x > 0.f) ? (t.x + 1.f) : __expf(t.x);
        qh[i * 4 + 1] = (t.y > 0.f) ? (t.y + 1.f) : __expf(t.y);
        qh[i * 4 + 2] = (t.z > 0.f) ? (t.z + 1.f) : __expf(t.z);
        qh[i * 4 + 3] = (t.w > 0.f) ? (t.w + 1.f) : __expf(t.w);
    }

    // ---- z (fully in-lane) ----
    float z = 0.f;
#pragma unroll
    for (int d = 0; d < 32; d++) z += qh[d] * sksum[wid * HD + d];
    z *= inv_scale_n;
    const float coef = 1.f + 1.f / (z + 1e-6f);

    // ---- theta shift (pairs in-lane) ----
    float qs[32];
#pragma unroll
    for (int i = 0; i < 16; i++) {
        float c0 = scos[lane][2 * i],     s0 = ssin[lane][2 * i];
        float c1 = scos[lane][2 * i + 1], s1 = ssin[lane][2 * i + 1];
        qs[2 * i]     = qh[2 * i] * c0 - qh[2 * i + 1] * s0;
        qs[2 * i + 1] = qh[2 * i + 1] * c1 + qh[2 * i] * s1;
    }

    // ---- matvec: acc[e] = sum_d qs[d] * kv[d][e]  (LDS broadcast on kv) ----
    float acc[32];
#pragma unroll
    for (int e = 0; e < 32; e++) acc[e] = 0.f;
    const float* kvh = &skv[wid * HD * HD];
#pragma unroll
    for (int d = 0; d < 32; d++) {
        float qd = qs[d];
#pragma unroll
        for (int e4 = 0; e4 < 8; e4++) {
            float4 kv = *(const float4*)&kvh[d * HD + e4 * 4];
            acc[e4 * 4 + 0] += qd * kv.x;
            acc[e4 * 4 + 1] += qd * kv.y;
            acc[e4 * 4 + 2] += qd * kv.z;
            acc[e4 * 4 + 3] += qd * kv.w;
        }
    }

    // ---- epilogue: lepe (shfl neighbors) + gate + store ----
#pragma unroll
    for (int e4 = 0; e4 < 8; e4++) {
        float4 vc = *(const float4*)&vrow[e4 * 4];
        float4 vp, vn;
        vp.x = __shfl_up_sync(0xffffffffu, vc.x, 1);
        vp.y = __shfl_up_sync(0xffffffffu, vc.y, 1);
        vp.z = __shfl_up_sync(0xffffffffu, vc.z, 1);
        vp.w = __shfl_up_sync(0xffffffffu, vc.w, 1);
        vn.x = __shfl_down_sync(0xffffffffu, vc.x, 1);
        vn.y = __shfl_down_sync(0xffffffffu, vc.y, 1);
        vn.z = __shfl_down_sync(0xffffffffu, vc.z, 1);
        vn.w = __shfl_down_sync(0xffffffffu, vc.w, 1);
        if (lane == 0) {
            if (nloc > 0) vp = *(const float4*)&qkvo[(nrow - 1) * QKVO_COLS + 512 + wid * HD + e4 * 4];
            else vp = make_float4(0.f, 0.f, 0.f, 0.f);
        }
        if (lane == 31) {
            if (nloc < NN - 1) vn = *(const float4*)&qkvo[(nrow + 1) * QKVO_COLS + 512 + wid * HD + e4 * 4];
            else vn = make_float4(0.f, 0.f, 0.f, 0.f);
        }
        float4 o4 = *(const float4*)&orow[e4 * 4];
        int c = wid * HD + e4 * 4;
        float4 r;
        r.x = (acc[e4*4+0] * coef - z * svm[c+0] + vp.x * sw0[c+0] + vc.x * sw1[c+0] + vn.x * sw2[c+0] + sbl[c+0]) * o4.x;
        r.y = (acc[e4*4+1] * coef - z * svm[c+1] + vp.y * sw0[c+1] + vc.y * sw1[c+1] + vn.y * sw2[c+1] + sbl[c+1]) * o4.y;
        r.z = (acc[e4*4+2] * coef - z * svm[c+2] + vp.z * sw0[c+2] + vc.z * sw1[c+2] + vn.z * sw2[c+2] + sbl[c+2]) * o4.z;
        r.w = (acc[e4*4+3] * coef - z * svm[c+3] + vp.w * sw0[c+3] + vc.w * sw1[c+3] + vn.w * sw2[c+3] + sbl[c+3]) * o4.w;
        *(float4*)&pre[nrow * INTERNAL + c] = r;
    }
}

// ---------------- launch -----------------------------------------------------
extern "C" void kernel_launch(void* const* d_in, const int* in_sizes, int n_in,
                              void* d_out, int out_size)
{
    const float* x       = (const float*)d_in[0];
    const float* sinp    = (const float*)d_in[1];
    const float* cosp    = (const float*)d_in[2];
    const float* W_qkvo  = (const float*)d_in[3];
    const float* b_qkvo  = (const float*)d_in[4];
    const float* W_lepe  = (const float*)d_in[5];
    const float* b_lepe  = (const float*)d_in[6];
    const float* W_proj  = (const float*)d_in[7];
    const float* b_proj  = (const float*)d_in[8];
    float* out = (float*)d_out;

    float *qkvo_p, *pre_p;
    cudaGetSymbolAddress((void**)&qkvo_p, g_qkvo);
    cudaGetSymbolAddress((void**)&pre_p,  g_pre);

    cudaFuncSetAttribute(gemm_mma_kernel,
                         cudaFuncAttributeMaxDynamicSharedMemorySize, GEMM_SMEM_BYTES);

    zero_kernel<<<(BB * HH * HD * HD + 255) / 256, 256>>>();

    // GEMM1: qkvo = x @ W_qkvo^T + b_qkvo   [32768 x 1024]
    gemm_mma_kernel<<<dim3(QKVO_COLS / 128, MROWS / 128), 256, GEMM_SMEM_BYTES>>>(
        x, W_qkvo, b_qkvo, qkvo_p, MROWS, QKVO_COLS, DIMV);

    // per-(b,h) reductions
    stats_kernel<<<dim3(BB * HH, 32), 256>>>(qkvo_p, sinp, cosp);

    // fused epilogue -> pre   (32 tokens per block)
    fuse_kernel<<<MROWS / 32, 256>>>(qkvo_p, sinp, cosp, W_lepe, b_lepe, pre_p);

    // GEMM2: out = pre @ W_proj^T + b_proj  [32768 x 256]
    gemm_mma_kernel<<<dim3(INTERNAL / 128, MROWS / 128), 256, GEMM_SMEM_BYTES>>>(
        pre_p, W_proj, b_proj, out, MROWS, INTERNAL, DIMV);
}

// round 5
// speedup vs baseline: 1.3376x; 1.3376x over previous
#include <cuda_runtime.h>
#include <cuda_bf16.h>
#include <math.h>
#include <stdint.h>

#define BB 4
#define NN 8192
#define DIMV 256
#define HH 8
#define HD 32
#define INTERNAL 256
#define MROWS (BB * NN)        // 32768
#define QKVO_COLS 1024
#define SCALE_F 0.17677669529663687f

// ---------------- persistent device scratch (no allocations) ----------------
__device__ float g_qkvo[(size_t)MROWS * QKVO_COLS];        // 134 MB fp32
__device__ __nv_bfloat16 g_xhi[(size_t)MROWS * DIMV];      // 16.7 MB
__device__ __nv_bfloat16 g_xlo[(size_t)MROWS * DIMV];
__device__ __nv_bfloat16 g_phi[(size_t)MROWS * INTERNAL];  // fuse output hi
__device__ __nv_bfloat16 g_plo[(size_t)MROWS * INTERNAL];
__device__ __nv_bfloat16 g_wqhi[(size_t)QKVO_COLS * DIMV];
__device__ __nv_bfloat16 g_wqlo[(size_t)QKVO_COLS * DIMV];
__device__ __nv_bfloat16 g_pwhi[(size_t)DIMV * INTERNAL];
__device__ __nv_bfloat16 g_pwlo[(size_t)DIMV * INTERNAL];
__device__ float g_kv  [BB * HH * HD * HD];
__device__ float g_ksum[BB * HH * HD];
__device__ float g_vsum[BB * HH * HD];

__device__ __forceinline__ uint32_t smem_u32(const void* p) {
    uint32_t a;
    asm("{ .reg .u64 t; cvta.to.shared.u64 t, %1; cvt.u32.u64 %0, t; }"
        : "=r"(a) : "l"(p));
    return a;
}

__device__ __forceinline__ void split2(float a, float b, uint32_t& hi, uint32_t& lo) {
    __nv_bfloat162 h = __floats2bfloat162_rn(a, b);
    float ra = a - __bfloat162float(h.x);
    float rb = b - __bfloat162float(h.y);
    __nv_bfloat162 l = __floats2bfloat162_rn(ra, rb);
    hi = *reinterpret_cast<uint32_t*>(&h);
    lo = *reinterpret_cast<uint32_t*>(&l);
}

__device__ __forceinline__ void ldmx4(uint32_t* r, uint32_t addr) {
    asm volatile("ldmatrix.sync.aligned.m8n8.x4.shared.b16 {%0,%1,%2,%3}, [%4];"
        : "=r"(r[0]), "=r"(r[1]), "=r"(r[2]), "=r"(r[3]) : "r"(addr));
}

__device__ __forceinline__ void mma16816(float* d, const uint32_t* a,
                                         uint32_t b0, uint32_t b1) {
    asm volatile(
        "mma.sync.aligned.m16n8k16.row.col.f32.bf16.bf16.f32 "
        "{%0,%1,%2,%3}, {%4,%5,%6,%7}, {%8,%9}, {%0,%1,%2,%3};"
        : "+f"(d[0]), "+f"(d[1]), "+f"(d[2]), "+f"(d[3])
        : "r"(a[0]), "r"(a[1]), "r"(a[2]), "r"(a[3]), "r"(b0), "r"(b1));
}

__device__ __forceinline__ void cp16(uint32_t saddr, const void* gaddr) {
    asm volatile("cp.async.cg.shared.global [%0], [%1], 16;"
        :: "r"(saddr), "l"(gaddr) : "memory");
}
#define CP_COMMIT() asm volatile("cp.async.commit_group;" ::: "memory")
#define CP_WAIT(n)  asm volatile("cp.async.wait_group %0;" :: "n"(n) : "memory")

// ---------------- fp32 -> bf16 hi/lo conversion -----------------------------
__global__ void __launch_bounds__(256)
cvt_kernel(const float* __restrict__ src, __nv_bfloat16* __restrict__ hi,
           __nv_bfloat16* __restrict__ lo, int n4)
{
    int i = blockIdx.x * 256 + threadIdx.x;
    if (i >= n4) return;
    float4 v = ((const float4*)src)[i];
    uint2 h, l;
    split2(v.x, v.y, h.x, l.x);
    split2(v.z, v.w, h.y, l.y);
    ((uint2*)hi)[i] = h;
    ((uint2*)lo)[i] = l;
}

// =================== HMMA GEMM (bf16 hi/lo inputs, cp.async pipeline) =======
// C[M,Nn] = (Ahi+Alo)[M,K] @ (Bhi+Blo)[Nn,K]^T + bias ; 3-term split product.
// 128x128 tile, BK=32, 8 warps (4M x 2N), 2-stage cp.async pipeline.
#define ROWB 80
#define ST_A_HI 0
#define ST_A_LO 10240
#define ST_B_HI 20480
#define ST_B_LO 30720
#define STAGEB 40960
#define GEMM_SMEM_BYTES (2 * STAGEB)   // 80 KB

__global__ void __launch_bounds__(256)
gemm_bf16_kernel(const __nv_bfloat16* __restrict__ Ahi,
                 const __nv_bfloat16* __restrict__ Alo,
                 const __nv_bfloat16* __restrict__ Bhi,
                 const __nv_bfloat16* __restrict__ Blo,
                 const float* __restrict__ bias, float* __restrict__ C,
                 int M, int Nn, int K)
{
    extern __shared__ char sm[];
    const uint32_t smb = smem_u32(sm);
    const int tid  = threadIdx.x;
    const int wid  = tid >> 5;
    const int lane = tid & 31;
    const int m0 = blockIdx.y * 128;
    const int n0 = blockIdx.x * 128;
    const int wm0 = (wid & 3) * 32;
    const int wn0 = (wid >> 2) * 64;

    const int a_row = (lane & 7) + ((lane >> 3) & 1) * 8;
    const int a_kh  = (lane >> 4) * 8;
    const int b_row = (lane & 7) + ((lane >> 4) & 1) * 8;
    const int b_kh  = ((lane >> 3) & 1) * 8;

    float acc[2][8][4];
#pragma unroll
    for (int i = 0; i < 2; i++)
#pragma unroll
        for (int j = 0; j < 8; j++)
#pragma unroll
            for (int l = 0; l < 4; l++) acc[i][j][l] = 0.f;

    const int NCH = K / 32;
    const int row2 = tid >> 2;          // 0..63
    const int seg  = tid & 3;           // 16B segment within 64B row

    // stage loader: rows row2 and row2+64 of each of the 4 buffers
#define LOAD_STAGE(c, buf) do {                                              \
    int k0 = (c) * 32;                                                       \
    uint32_t base = smb + (buf) * STAGEB;                                    \
    _Pragma("unroll")                                                        \
    for (int i = 0; i < 2; i++) {                                            \
        int r = row2 + i * 64;                                               \
        uint32_t so = r * ROWB + seg * 16;                                   \
        size_t ga = (size_t)(m0 + r) * K + k0 + seg * 8;                     \
        size_t gb = (size_t)(n0 + r) * K + k0 + seg * 8;                     \
        cp16(base + ST_A_HI + so, Ahi + ga);                                 \
        cp16(base + ST_A_LO + so, Alo + ga);                                 \
        cp16(base + ST_B_HI + so, Bhi + gb);                                 \
        cp16(base + ST_B_LO + so, Blo + gb);                                 \
    }                                                                        \
    CP_COMMIT();                                                             \
} while (0)

    LOAD_STAGE(0, 0);
    if (NCH > 1) LOAD_STAGE(1, 1);
    CP_WAIT(1);
    __syncthreads();

    for (int c = 0; c < NCH; c++) {
        const uint32_t base = smb + (c & 1) * STAGEB;
#pragma unroll
        for (int ks = 0; ks < 2; ks++) {
            uint32_t ah[2][4], al[2][4];
#pragma unroll
            for (int mf = 0; mf < 2; mf++) {
                uint32_t ao = base + (wm0 + mf * 16 + a_row) * ROWB
                            + (ks * 16 + a_kh) * 2;
                ldmx4(ah[mf], ao + ST_A_HI);
                ldmx4(al[mf], ao + ST_A_LO);
            }
#pragma unroll
            for (int nf2 = 0; nf2 < 4; nf2++) {
                uint32_t bo = base + (wn0 + nf2 * 16 + b_row) * ROWB
                            + (ks * 16 + b_kh) * 2;
                uint32_t bh[4], bl[4];
                ldmx4(bh, bo + ST_B_HI);
                ldmx4(bl, bo + ST_B_LO);
#pragma unroll
                for (int mf = 0; mf < 2; mf++) {
#pragma unroll
                    for (int s = 0; s < 2; s++) {
                        float* d = acc[mf][nf2 * 2 + s];
                        mma16816(d, ah[mf], bh[s * 2], bh[s * 2 + 1]);
                        mma16816(d, al[mf], bh[s * 2], bh[s * 2 + 1]);
                        mma16816(d, ah[mf], bl[s * 2], bl[s * 2 + 1]);
                    }
                }
            }
        }
        __syncthreads();              // everyone done reading buf (c&1)
        if (c + 2 < NCH) {
            LOAD_STAGE(c + 2, c & 1);
            CP_WAIT(1);               // stage c+1 complete
        } else {
            CP_WAIT(0);
        }
        __syncthreads();
    }
#undef LOAD_STAGE

    const int rr = lane >> 2;
    const int cc = (lane & 3) * 2;
#pragma unroll
    for (int mf = 0; mf < 2; mf++) {
        int r0 = m0 + wm0 + mf * 16 + rr;
#pragma unroll
        for (int nf = 0; nf < 8; nf++) {
            int col = n0 + wn0 + nf * 8 + cc;
            float b0 = bias[col], b1 = bias[col + 1];
            float2 v0 = {acc[mf][nf][0] + b0, acc[mf][nf][1] + b1};
            float2 v1 = {acc[mf][nf][2] + b0, acc[mf][nf][3] + b1};
            *(float2*)&C[(size_t)r0 * Nn + col] = v0;
            *(float2*)&C[(size_t)(r0 + 8) * Nn + col] = v1;
        }
    }
}

// ---------------- zero accumulators ----------------------------------------
__global__ void zero_kernel() {
    int i = blockIdx.x * 256 + threadIdx.x;
    if (i < BB * HH * HD * HD) g_kv[i] = 0.f;
    if (i < BB * HH * HD) { g_ksum[i] = 0.f; g_vsum[i] = 0.f; }
}

// ---------------- stats: kv_state / ksum / vsum per (b,h) ------------------
__global__ void __launch_bounds__(256)
stats_kernel(const float* __restrict__ qkvo,
             const float* __restrict__ sinp, const float* __restrict__ cosp)
{
    __shared__ float sks[8][32];
    __shared__ float svh[8][32];

    const int bh = blockIdx.x;
    const int split = blockIdx.y;
    const int b = bh >> 3, h = bh & 7;
    const int w = threadIdx.x >> 5;
    const int lane = threadIdx.x & 31;
    const int n_start = split * (NN / 32);

    const int dA = threadIdx.x >> 3;
    const int e4 = (threadIdx.x & 7) * 4;

    float kv0 = 0.f, kv1 = 0.f, kv2 = 0.f, kv3 = 0.f;
    float ksum_acc = 0.f, vsum_acc = 0.f;

    for (int c0 = 0; c0 < NN / 32; c0 += 8) {
        int n = n_start + c0 + w;
        size_t row = (size_t)(b * NN + n) * QKVO_COLS;
        float kraw = qkvo[row + 256 + h * 32 + lane];
        float v    = qkvo[row + 512 + h * 32 + lane];
        float kh = (kraw > 0.f) ? (kraw + 1.f) : expf(kraw);
        ksum_acc += kh;
        vsum_acc += v;
        float partner = __shfl_xor_sync(0xffffffffu, kh, 1);
        float sv = sinp[n * HD + lane];
        float cv = cosp[n * HD + lane];
        float rot = (lane & 1) ? partner : -partner;
        float ks = kh * cv + rot * sv;
        sks[w][lane] = ks;
        svh[w][lane] = v;
        __syncthreads();
#pragma unroll
        for (int j = 0; j < 8; j++) {
            float a = sks[j][dA];
            float4 vv = *(const float4*)&svh[j][e4];
            kv0 += a * vv.x;
            kv1 += a * vv.y;
            kv2 += a * vv.z;
            kv3 += a * vv.w;
        }
        __syncthreads();
    }

    float* kvdst = &g_kv[bh * (HD * HD) + dA * HD + e4];
    atomicAdd(kvdst + 0, kv0);
    atomicAdd(kvdst + 1, kv1);
    atomicAdd(kvdst + 2, kv2);
    atomicAdd(kvdst + 3, kv3);
    atomicAdd(&g_ksum[bh * HD + lane], ksum_acc);
    atomicAdd(&g_vsum[bh * HD + lane], vsum_acc);
}

// ---------------- fused per-token epilogue (R3 form) -> bf16 hi/lo ----------
#define TILE_ROWS 64
__global__ void __launch_bounds__(256)
fuse_kernel(const float* __restrict__ qkvo,
            const float* __restrict__ sinp, const float* __restrict__ cosp,
            const float* __restrict__ W_lepe, const float* __restrict__ b_lepe,
            __nv_bfloat16* __restrict__ phi, __nv_bfloat16* __restrict__ plo)
{
    __shared__ float skv[HH * HD * HD];

    const int tile = blockIdx.x;
    const int b  = tile / (NN / TILE_ROWS);
    const int t  = tile % (NN / TILE_ROWS);
    const int n0 = t * TILE_ROWS;
    const int c  = threadIdx.x;
    const int h  = c >> 5;
    const int d  = c & 31;
    const float inv_scale_n = SCALE_F / (float)NN;

    const int base_kv = b * HH * HD * HD;
    for (int i = c; i < HH * HD * HD; i += 256)
        skv[i] = g_kv[base_kv + i] * inv_scale_n;

    const float km = g_ksum[(b * HH + h) * HD + d];
    const float vm = g_vsum[(b * HH + h) * HD + d] * (1.f / NN);
    __syncthreads();

    const float w0 = W_lepe[c * 3 + 0];
    const float w1 = W_lepe[c * 3 + 1];
    const float w2 = W_lepe[c * 3 + 2];
    const float bl = b_lepe[c];

    size_t rowbase = (size_t)(b * NN + n0) * QKVO_COLS;
    float v_prev = (n0 > 0) ? qkvo[rowbase - QKVO_COLS + 512 + c] : 0.f;
    float v_cur  = qkvo[rowbase + 512 + c];

    const float* kvh = &skv[h * HD * HD];

    for (int r = 0; r < TILE_ROWS; r++) {
        int n = n0 + r;
        size_t row = (size_t)(b * NN + n) * QKVO_COLS;
        float v_next = (n + 1 < NN) ? qkvo[row + QKVO_COLS + 512 + c] : 0.f;

        float q  = qkvo[row + c];
        float qh = (q > 0.f) ? (q + 1.f) : expf(q);

        float zp = qh * km;
#pragma unroll
        for (int off = 16; off > 0; off >>= 1)
            zp += __shfl_xor_sync(0xffffffffu, zp, off);
        float z = zp * inv_scale_n;

        float partner = __shfl_xor_sync(0xffffffffu, qh, 1);
        float sv = sinp[n * HD + d];
        float cv = cosp[n * HD + d];
        float rot = (d & 1) ? partner : -partner;
        float qs = qh * cv + rot * sv;

        float acc = 0.f;
#pragma unroll
        for (int dd = 0; dd < 32; dd++) {
            float qsd = __shfl_sync(0xffffffffu, qs, dd);
            acc += qsd * kvh[dd * HD + d];
        }

        float coef = 1.f + 1.f / (z + 1e-6f);
        float res  = acc * coef - z * vm;
        float lepe = v_prev * w0 + v_cur * w1 + v_next * w2 + bl;
        float o    = qkvo[row + 768 + c];

        float val = (res + lepe) * o;
        __nv_bfloat16 vh = __float2bfloat16(val);
        __nv_bfloat16 vl = __float2bfloat16(val - __bfloat162float(vh));
        size_t oidx = (size_t)(b * NN + n) * INTERNAL + c;
        phi[oidx] = vh;
        plo[oidx] = vl;

        v_prev = v_cur;
        v_cur  = v_next;
    }
}

// ---------------- launch -----------------------------------------------------
extern "C" void kernel_launch(void* const* d_in, const int* in_sizes, int n_in,
                              void* d_out, int out_size)
{
    const float* x       = (const float*)d_in[0];
    const float* sinp    = (const float*)d_in[1];
    const float* cosp    = (const float*)d_in[2];
    const float* W_qkvo  = (const float*)d_in[3];
    const float* b_qkvo  = (const float*)d_in[4];
    const float* W_lepe  = (const float*)d_in[5];
    const float* b_lepe  = (const float*)d_in[6];
    const float* W_proj  = (const float*)d_in[7];
    const float* b_proj  = (const float*)d_in[8];
    float* out = (float*)d_out;

    float *qkvo_p;
    __nv_bfloat16 *xhi, *xlo, *phi, *plo, *wqhi, *wqlo, *pwhi, *pwlo;
    cudaGetSymbolAddress((void**)&qkvo_p, g_qkvo);
    cudaGetSymbolAddress((void**)&xhi, g_xhi);
    cudaGetSymbolAddress((void**)&xlo, g_xlo);
    cudaGetSymbolAddress((void**)&phi, g_phi);
    cudaGetSymbolAddress((void**)&plo, g_plo);
    cudaGetSymbolAddress((void**)&wqhi, g_wqhi);
    cudaGetSymbolAddress((void**)&wqlo, g_wqlo);
    cudaGetSymbolAddress((void**)&pwhi, g_pwhi);
    cudaGetSymbolAddress((void**)&pwlo, g_pwlo);

    cudaFuncSetAttribute(gemm_bf16_kernel,
                         cudaFuncAttributeMaxDynamicSharedMemorySize, GEMM_SMEM_BYTES);

    zero_kernel<<<(BB * HH * HD * HD + 255) / 256, 256>>>();

    // convert inputs to bf16 hi/lo
    cvt_kernel<<<(MROWS * DIMV / 4 + 255) / 256, 256>>>(x, xhi, xlo, MROWS * DIMV / 4);
    cvt_kernel<<<(QKVO_COLS * DIMV / 4 + 255) / 256, 256>>>(W_qkvo, wqhi, wqlo, QKVO_COLS * DIMV / 4);
    cvt_kernel<<<(DIMV * INTERNAL / 4 + 255) / 256, 256>>>(W_proj, pwhi, pwlo, DIMV * INTERNAL / 4);

    // GEMM1: qkvo = x @ W_qkvo^T + b_qkvo   [32768 x 1024]
    gemm_bf16_kernel<<<dim3(QKVO_COLS / 128, MROWS / 128), 256, GEMM_SMEM_BYTES>>>(
        xhi, xlo, wqhi, wqlo, b_qkvo, qkvo_p, MROWS, QKVO_COLS, DIMV);

    // per-(b,h) reductions
    stats_kernel<<<dim3(BB * HH, 32), 256>>>(qkvo_p, sinp, cosp);

    // fused epilogue -> bf16 hi/lo pre
    fuse_kernel<<<BB * (NN / TILE_ROWS), 256>>>(qkvo_p, sinp, cosp,
                                                W_lepe, b_lepe, phi, plo);

    // GEMM2: out = pre @ W_proj^T + b_proj  [32768 x 256]
    gemm_bf16_kernel<<<dim3(INTERNAL / 128, MROWS / 128), 256, GEMM_SMEM_BYTES>>>(
        phi, plo, pwhi, pwlo, b_proj, out, MROWS, INTERNAL, DIMV);
}

// round 6
// speedup vs baseline: 1.3560x; 1.0138x over previous
#include <cuda_runtime.h>
#include <cuda_bf16.h>
#include <math.h>
#include <stdint.h>

#define BB 4
#define NN 8192
#define DIMV 256
#define HH 8
#define HD 32
#define INTERNAL 256
#define MROWS (BB * NN)        // 32768
#define QKVO_COLS 1024
#define SCALE_F 0.17677669529663687f

// ---------------- persistent device scratch (no allocations) ----------------
__device__ float g_qkvo[(size_t)MROWS * QKVO_COLS];        // 134 MB fp32
__device__ __nv_bfloat16 g_xhi[(size_t)MROWS * DIMV];
__device__ __nv_bfloat16 g_xlo[(size_t)MROWS * DIMV];
__device__ __nv_bfloat16 g_phi[(size_t)MROWS * INTERNAL];
__device__ __nv_bfloat16 g_plo[(size_t)MROWS * INTERNAL];
__device__ __nv_bfloat16 g_wqhi[(size_t)QKVO_COLS * DIMV];
__device__ __nv_bfloat16 g_wqlo[(size_t)QKVO_COLS * DIMV];
__device__ __nv_bfloat16 g_pwhi[(size_t)DIMV * INTERNAL];
__device__ __nv_bfloat16 g_pwlo[(size_t)DIMV * INTERNAL];
__device__ float g_kv  [BB * HH * HD * HD];
__device__ float g_ksum[BB * HH * HD];
__device__ float g_vsum[BB * HH * HD];

__device__ __forceinline__ uint32_t smem_u32(const void* p) {
    uint32_t a;
    asm("{ .reg .u64 t; cvta.to.shared.u64 t, %1; cvt.u32.u64 %0, t; }"
        : "=r"(a) : "l"(p));
    return a;
}

__device__ __forceinline__ void split2(float a, float b, uint32_t& hi, uint32_t& lo) {
    __nv_bfloat162 h = __floats2bfloat162_rn(a, b);
    float ra = a - __bfloat162float(h.x);
    float rb = b - __bfloat162float(h.y);
    __nv_bfloat162 l = __floats2bfloat162_rn(ra, rb);
    hi = *reinterpret_cast<uint32_t*>(&h);
    lo = *reinterpret_cast<uint32_t*>(&l);
}

__device__ __forceinline__ void ldmx4(uint32_t* r, uint32_t addr) {
    asm volatile("ldmatrix.sync.aligned.m8n8.x4.shared.b16 {%0,%1,%2,%3}, [%4];"
        : "=r"(r[0]), "=r"(r[1]), "=r"(r[2]), "=r"(r[3]) : "r"(addr));
}

__device__ __forceinline__ void mma16816(float* d, const uint32_t* a,
                                         uint32_t b0, uint32_t b1) {
    asm volatile(
        "mma.sync.aligned.m16n8k16.row.col.f32.bf16.bf16.f32 "
        "{%0,%1,%2,%3}, {%4,%5,%6,%7}, {%8,%9}, {%0,%1,%2,%3};"
        : "+f"(d[0]), "+f"(d[1]), "+f"(d[2]), "+f"(d[3])
        : "r"(a[0]), "r"(a[1]), "r"(a[2]), "r"(a[3]), "r"(b0), "r"(b1));
}

__device__ __forceinline__ void cp16(uint32_t saddr, const void* gaddr) {
    asm volatile("cp.async.cg.shared.global [%0], [%1], 16;"
        :: "r"(saddr), "l"(gaddr) : "memory");
}
#define CP_COMMIT() asm volatile("cp.async.commit_group;" ::: "memory")
#define CP_WAIT(n)  asm volatile("cp.async.wait_group %0;" :: "n"(n) : "memory")

// ---------------- fp32 -> bf16 hi/lo conversion -----------------------------
__global__ void __launch_bounds__(256)
cvt_kernel(const float* __restrict__ src, __nv_bfloat16* __restrict__ hi,
           __nv_bfloat16* __restrict__ lo, int n4)
{
    int i = blockIdx.x * 256 + threadIdx.x;
    if (i >= n4) return;
    float4 v = ((const float4*)src)[i];
    uint2 h, l;
    split2(v.x, v.y, h.x, l.x);
    split2(v.z, v.w, h.y, l.y);
    ((uint2*)hi)[i] = h;
    ((uint2*)lo)[i] = l;
}

// =================== HMMA GEMM (bf16 hi/lo, 3-stage cp.async) ===============
// C[M,Nn] = (Ahi+Alo)[M,K] @ (Bhi+Blo)[Nn,K]^T + bias ; 3-term split.
// 128x128 tile, BK=32, 8 warps (4M x 2N), 3-stage pipeline, term-major MMA.
#define ROWB 80
#define ST_A_HI 0
#define ST_A_LO 10240
#define ST_B_HI 20480
#define ST_B_LO 30720
#define STAGEB 40960
#define NSTAGE 3
#define GEMM_SMEM_BYTES (NSTAGE * STAGEB)   // 120 KB

__global__ void __launch_bounds__(256)
gemm_bf16_kernel(const __nv_bfloat16* __restrict__ Ahi,
                 const __nv_bfloat16* __restrict__ Alo,
                 const __nv_bfloat16* __restrict__ Bhi,
                 const __nv_bfloat16* __restrict__ Blo,
                 const float* __restrict__ bias, float* __restrict__ C,
                 int M, int Nn, int K)
{
    extern __shared__ char sm[];
    const uint32_t smb = smem_u32(sm);
    const int tid  = threadIdx.x;
    const int wid  = tid >> 5;
    const int lane = tid & 31;
    const int m0 = blockIdx.y * 128;
    const int n0 = blockIdx.x * 128;
    const int wm0 = (wid & 3) * 32;
    const int wn0 = (wid >> 2) * 64;

    const int a_row = (lane & 7) + ((lane >> 3) & 1) * 8;
    const int a_kh  = (lane >> 4) * 8;
    const int b_row = (lane & 7) + ((lane >> 4) & 1) * 8;
    const int b_kh  = ((lane >> 3) & 1) * 8;

    float acc[2][8][4];
#pragma unroll
    for (int i = 0; i < 2; i++)
#pragma unroll
        for (int j = 0; j < 8; j++)
#pragma unroll
            for (int l = 0; l < 4; l++) acc[i][j][l] = 0.f;

    const int NCH = K / 32;             // 8
    const int row2 = tid >> 2;          // 0..63
    const int seg  = tid & 3;           // 16B segment

#define LOAD_STAGE(c, buf) do {                                              \
    int k0 = (c) * 32;                                                       \
    uint32_t base = smb + (buf) * STAGEB;                                    \
    _Pragma("unroll")                                                        \
    for (int i = 0; i < 2; i++) {                                            \
        int r = row2 + i * 64;                                               \
        uint32_t so = r * ROWB + seg * 16;                                   \
        size_t ga = (size_t)(m0 + r) * K + k0 + seg * 8;                     \
        size_t gb = (size_t)(n0 + r) * K + k0 + seg * 8;                     \
        cp16(base + ST_A_HI + so, Ahi + ga);                                 \
        cp16(base + ST_A_LO + so, Alo + ga);                                 \
        cp16(base + ST_B_HI + so, Bhi + gb);                                 \
        cp16(base + ST_B_LO + so, Blo + gb);                                 \
    }                                                                        \
    CP_COMMIT();                                                             \
} while (0)

    LOAD_STAGE(0, 0);
    LOAD_STAGE(1, 1);
    LOAD_STAGE(2, 2);

    int buf = 0;
    for (int c = 0; c < NCH; c++) {
        CP_WAIT(2);                 // stage c complete
        __syncthreads();
        const uint32_t base = smb + buf * STAGEB;

#pragma unroll
        for (int ks = 0; ks < 2; ks++) {
            uint32_t ah[2][4], al[2][4], bh[4][4], bl[4][4];
#pragma unroll
            for (int mf = 0; mf < 2; mf++) {
                uint32_t ao = base + (wm0 + mf * 16 + a_row) * ROWB
                            + (ks * 16 + a_kh) * 2;
                ldmx4(ah[mf], ao + ST_A_HI);
                ldmx4(al[mf], ao + ST_A_LO);
            }
#pragma unroll
            for (int nf2 = 0; nf2 < 4; nf2++) {
                uint32_t bo = base + (wn0 + nf2 * 16 + b_row) * ROWB
                            + (ks * 16 + b_kh) * 2;
                ldmx4(bh[nf2], bo + ST_B_HI);
                ldmx4(bl[nf2], bo + ST_B_LO);
            }
            // term-major: 3 passes of 16 independent MMAs
#pragma unroll
            for (int nf2 = 0; nf2 < 4; nf2++)
#pragma unroll
                for (int mf = 0; mf < 2; mf++)
#pragma unroll
                    for (int s = 0; s < 2; s++)
                        mma16816(acc[mf][nf2 * 2 + s], ah[mf],
                                 bh[nf2][s * 2], bh[nf2][s * 2 + 1]);
#pragma unroll
            for (int nf2 = 0; nf2 < 4; nf2++)
#pragma unroll
                for (int mf = 0; mf < 2; mf++)
#pragma unroll
                    for (int s = 0; s < 2; s++)
                        mma16816(acc[mf][nf2 * 2 + s], al[mf],
                                 bh[nf2][s * 2], bh[nf2][s * 2 + 1]);
#pragma unroll
            for (int nf2 = 0; nf2 < 4; nf2++)
#pragma unroll
                for (int mf = 0; mf < 2; mf++)
#pragma unroll
                    for (int s = 0; s < 2; s++)
                        mma16816(acc[mf][nf2 * 2 + s], ah[mf],
                                 bl[nf2][s * 2], bl[nf2][s * 2 + 1]);
        }
        __syncthreads();            // all warps done reading buf
        if (c + 3 < NCH) LOAD_STAGE(c + 3, buf);
        else CP_COMMIT();           // empty group keeps wait count aligned
        buf = (buf == NSTAGE - 1) ? 0 : buf + 1;
    }
#undef LOAD_STAGE

    const int rr = lane >> 2;
    const int cc = (lane & 3) * 2;
#pragma unroll
    for (int mf = 0; mf < 2; mf++) {
        int r0 = m0 + wm0 + mf * 16 + rr;
#pragma unroll
        for (int nf = 0; nf < 8; nf++) {
            int col = n0 + wn0 + nf * 8 + cc;
            float b0 = bias[col], b1 = bias[col + 1];
            float2 v0 = {acc[mf][nf][0] + b0, acc[mf][nf][1] + b1};
            float2 v1 = {acc[mf][nf][2] + b0, acc[mf][nf][3] + b1};
            *(float2*)&C[(size_t)r0 * Nn + col] = v0;
            *(float2*)&C[(size_t)(r0 + 8) * Nn + col] = v1;
        }
    }
}

// ---------------- zero accumulators ----------------------------------------
__global__ void zero_kernel() {
    int i = blockIdx.x * 256 + threadIdx.x;
    if (i < BB * HH * HD * HD) g_kv[i] = 0.f;
    if (i < BB * HH * HD) { g_ksum[i] = 0.f; g_vsum[i] = 0.f; }
}

// ---------------- stats: kv_state / ksum / vsum per (b,h) ------------------
__global__ void __launch_bounds__(256)
stats_kernel(const float* __restrict__ qkvo,
             const float* __restrict__ sinp, const float* __restrict__ cosp)
{
    __shared__ float sks[8][32];
    __shared__ float svh[8][32];

    const int bh = blockIdx.x;
    const int split = blockIdx.y;
    const int b = bh >> 3, h = bh & 7;
    const int w = threadIdx.x >> 5;
    const int lane = threadIdx.x & 31;
    const int n_start = split * (NN / 32);

    const int dA = threadIdx.x >> 3;
    const int e4 = (threadIdx.x & 7) * 4;

    float kv0 = 0.f, kv1 = 0.f, kv2 = 0.f, kv3 = 0.f;
    float ksum_acc = 0.f, vsum_acc = 0.f;

    for (int c0 = 0; c0 < NN / 32; c0 += 8) {
        int n = n_start + c0 + w;
        size_t row = (size_t)(b * NN + n) * QKVO_COLS;
        float kraw = qkvo[row + 256 + h * 32 + lane];
        float v    = qkvo[row + 512 + h * 32 + lane];
        float kh = (kraw > 0.f) ? (kraw + 1.f) : expf(kraw);
        ksum_acc += kh;
        vsum_acc += v;
        float partner = __shfl_xor_sync(0xffffffffu, kh, 1);
        float sv = sinp[n * HD + lane];
        float cv = cosp[n * HD + lane];
        float rot = (lane & 1) ? partner : -partner;
        float ks = kh * cv + rot * sv;
        sks[w][lane] = ks;
        svh[w][lane] = v;
        __syncthreads();
#pragma unroll
        for (int j = 0; j < 8; j++) {
            float a = sks[j][dA];
            float4 vv = *(const float4*)&svh[j][e4];
            kv0 += a * vv.x;
            kv1 += a * vv.y;
            kv2 += a * vv.z;
            kv3 += a * vv.w;
        }
        __syncthreads();
    }

    float* kvdst = &g_kv[bh * (HD * HD) + dA * HD + e4];
    atomicAdd(kvdst + 0, kv0);
    atomicAdd(kvdst + 1, kv1);
    atomicAdd(kvdst + 2, kv2);
    atomicAdd(kvdst + 3, kv3);
    atomicAdd(&g_ksum[bh * HD + lane], ksum_acc);
    atomicAdd(&g_vsum[bh * HD + lane], vsum_acc);
}

// ---------------- fused per-token epilogue -> bf16 hi/lo --------------------
#define TILE_ROWS 64
__global__ void __launch_bounds__(256)
fuse_kernel(const float* __restrict__ qkvo,
            const float* __restrict__ sinp, const float* __restrict__ cosp,
            const float* __restrict__ W_lepe, const float* __restrict__ b_lepe,
            __nv_bfloat16* __restrict__ phi, __nv_bfloat16* __restrict__ plo)
{
    __shared__ float skv[HH * HD * HD];

    const int tile = blockIdx.x;
    const int b  = tile / (NN / TILE_ROWS);
    const int t  = tile % (NN / TILE_ROWS);
    const int n0 = t * TILE_ROWS;
    const int c  = threadIdx.x;
    const int h  = c >> 5;
    const int d  = c & 31;
    const float inv_scale_n = SCALE_F / (float)NN;

    const int base_kv = b * HH * HD * HD;
    for (int i = c; i < HH * HD * HD; i += 256)
        skv[i] = g_kv[base_kv + i] * inv_scale_n;

    const float km = g_ksum[(b * HH + h) * HD + d];
    const float vm = g_vsum[(b * HH + h) * HD + d] * (1.f / NN);
    __syncthreads();

    const float w0 = W_lepe[c * 3 + 0];
    const float w1 = W_lepe[c * 3 + 1];
    const float w2 = W_lepe[c * 3 + 2];
    const float bl = b_lepe[c];

    size_t rowbase = (size_t)(b * NN + n0) * QKVO_COLS;
    float v_prev = (n0 > 0) ? qkvo[rowbase - QKVO_COLS + 512 + c] : 0.f;
    float v_cur  = qkvo[rowbase + 512 + c];

    const float* kvh = &skv[h * HD * HD];

    for (int r = 0; r < TILE_ROWS; r++) {
        int n = n0 + r;
        size_t row = (size_t)(b * NN + n) * QKVO_COLS;
        float v_next = (n + 1 < NN) ? qkvo[row + QKVO_COLS + 512 + c] : 0.f;

        float q  = qkvo[row + c];
        float qh = (q > 0.f) ? (q + 1.f) : expf(q);

        float zp = qh * km;
#pragma unroll
        for (int off = 16; off > 0; off >>= 1)
            zp += __shfl_xor_sync(0xffffffffu, zp, off);
        float z = zp * inv_scale_n;

        float partner = __shfl_xor_sync(0xffffffffu, qh, 1);
        float sv = sinp[n * HD + d];
        float cv = cosp[n * HD + d];
        float rot = (d & 1) ? partner : -partner;
        float qs = qh * cv + rot * sv;

        float acc = 0.f;
#pragma unroll
        for (int dd = 0; dd < 32; dd++) {
            float qsd = __shfl_sync(0xffffffffu, qs, dd);
            acc += qsd * kvh[dd * HD + d];
        }

        float coef = 1.f + 1.f / (z + 1e-6f);
        float res  = acc * coef - z * vm;
        float lepe = v_prev * w0 + v_cur * w1 + v_next * w2 + bl;
        float o    = qkvo[row + 768 + c];

        float val = (res + lepe) * o;
        __nv_bfloat16 vh = __float2bfloat16(val);
        __nv_bfloat16 vl = __float2bfloat16(val - __bfloat162float(vh));
        size_t oidx = (size_t)(b * NN + n) * INTERNAL + c;
        phi[oidx] = vh;
        plo[oidx] = vl;

        v_prev = v_cur;
        v_cur  = v_next;
    }
}

// ---------------- launch -----------------------------------------------------
extern "C" void kernel_launch(void* const* d_in, const int* in_sizes, int n_in,
                              void* d_out, int out_size)
{
    const float* x       = (const float*)d_in[0];
    const float* sinp    = (const float*)d_in[1];
    const float* cosp    = (const float*)d_in[2];
    const float* W_qkvo  = (const float*)d_in[3];
    const float* b_qkvo  = (const float*)d_in[4];
    const float* W_lepe  = (const float*)d_in[5];
    const float* b_lepe  = (const float*)d_in[6];
    const float* W_proj  = (const float*)d_in[7];
    const float* b_proj  = (const float*)d_in[8];
    float* out = (float*)d_out;

    float *qkvo_p;
    __nv_bfloat16 *xhi, *xlo, *phi, *plo, *wqhi, *wqlo, *pwhi, *pwlo;
    cudaGetSymbolAddress((void**)&qkvo_p, g_qkvo);
    cudaGetSymbolAddress((void**)&xhi, g_xhi);
    cudaGetSymbolAddress((void**)&xlo, g_xlo);
    cudaGetSymbolAddress((void**)&phi, g_phi);
    cudaGetSymbolAddress((void**)&plo, g_plo);
    cudaGetSymbolAddress((void**)&wqhi, g_wqhi);
    cudaGetSymbolAddress((void**)&wqlo, g_wqlo);
    cudaGetSymbolAddress((void**)&pwhi, g_pwhi);
    cudaGetSymbolAddress((void**)&pwlo, g_pwlo);

    cudaFuncSetAttribute(gemm_bf16_kernel,
                         cudaFuncAttributeMaxDynamicSharedMemorySize, GEMM_SMEM_BYTES);

    zero_kernel<<<(BB * HH * HD * HD + 255) / 256, 256>>>();

    cvt_kernel<<<(MROWS * DIMV / 4 + 255) / 256, 256>>>(x, xhi, xlo, MROWS * DIMV / 4);
    cvt_kernel<<<(QKVO_COLS * DIMV / 4 + 255) / 256, 256>>>(W_qkvo, wqhi, wqlo, QKVO_COLS * DIMV / 4);
    cvt_kernel<<<(DIMV * INTERNAL / 4 + 255) / 256, 256>>>(W_proj, pwhi, pwlo, DIMV * INTERNAL / 4);

    // GEMM1: qkvo = x @ W_qkvo^T + b_qkvo   [32768 x 1024]
    gemm_bf16_kernel<<<dim3(QKVO_COLS / 128, MROWS / 128), 256, GEMM_SMEM_BYTES>>>(
        xhi, xlo, wqhi, wqlo, b_qkvo, qkvo_p, MROWS, QKVO_COLS, DIMV);

    stats_kernel<<<dim3(BB * HH, 32), 256>>>(qkvo_p, sinp, cosp);

    fuse_kernel<<<BB * (NN / TILE_ROWS), 256>>>(qkvo_p, sinp, cosp,
                                                W_lepe, b_lepe, phi, plo);

    // GEMM2: out = pre @ W_proj^T + b_proj  [32768 x 256]
    gemm_bf16_kernel<<<dim3(INTERNAL / 128, MROWS / 128), 256, GEMM_SMEM_BYTES>>>(
        phi, plo, pwhi, pwlo, b_proj, out, MROWS, INTERNAL, DIMV);
}

// round 7
// speedup vs baseline: 1.3970x; 1.0302x over previous
#include <cuda_runtime.h>
#include <cuda_bf16.h>
#include <math.h>
#include <stdint.h>

#define BB 4
#define NN 8192
#define DIMV 256
#define HH 8
#define HD 32
#define INTERNAL 256
#define MROWS (BB * NN)        // 32768
#define QKVO_COLS 1024
#define SCALE_F 0.17677669529663687f

// ---------------- persistent device scratch (no allocations) ----------------
__device__ float g_qkvo[(size_t)MROWS * QKVO_COLS];        // 134 MB fp32
__device__ __nv_bfloat16 g_xhi[(size_t)MROWS * DIMV];
__device__ __nv_bfloat16 g_xlo[(size_t)MROWS * DIMV];
__device__ __nv_bfloat16 g_phi[(size_t)MROWS * INTERNAL];
__device__ __nv_bfloat16 g_plo[(size_t)MROWS * INTERNAL];
__device__ __nv_bfloat16 g_wqhi[(size_t)QKVO_COLS * DIMV];
__device__ __nv_bfloat16 g_wqlo[(size_t)QKVO_COLS * DIMV];
__device__ __nv_bfloat16 g_pwhi[(size_t)DIMV * INTERNAL];
__device__ __nv_bfloat16 g_pwlo[(size_t)DIMV * INTERNAL];
__device__ float g_kv  [BB * HH * HD * HD];
__device__ float g_ksum[BB * HH * HD];
__device__ float g_vsum[BB * HH * HD];

__device__ __forceinline__ uint32_t smem_u32(const void* p) {
    uint32_t a;
    asm("{ .reg .u64 t; cvta.to.shared.u64 t, %1; cvt.u32.u64 %0, t; }"
        : "=r"(a) : "l"(p));
    return a;
}

__device__ __forceinline__ void split2(float a, float b, uint32_t& hi, uint32_t& lo) {
    __nv_bfloat162 h = __floats2bfloat162_rn(a, b);
    float ra = a - __bfloat162float(h.x);
    float rb = b - __bfloat162float(h.y);
    __nv_bfloat162 l = __floats2bfloat162_rn(ra, rb);
    hi = *reinterpret_cast<uint32_t*>(&h);
    lo = *reinterpret_cast<uint32_t*>(&l);
}

__device__ __forceinline__ void ldmx4(uint32_t* r, uint32_t addr) {
    asm volatile("ldmatrix.sync.aligned.m8n8.x4.shared.b16 {%0,%1,%2,%3}, [%4];"
        : "=r"(r[0]), "=r"(r[1]), "=r"(r[2]), "=r"(r[3]) : "r"(addr));
}

__device__ __forceinline__ void mma16816(float* d, const uint32_t* a,
                                         uint32_t b0, uint32_t b1) {
    asm volatile(
        "mma.sync.aligned.m16n8k16.row.col.f32.bf16.bf16.f32 "
        "{%0,%1,%2,%3}, {%4,%5,%6,%7}, {%8,%9}, {%0,%1,%2,%3};"
        : "+f"(d[0]), "+f"(d[1]), "+f"(d[2]), "+f"(d[3])
        : "r"(a[0]), "r"(a[1]), "r"(a[2]), "r"(a[3]), "r"(b0), "r"(b1));
}

__device__ __forceinline__ void cp16(uint32_t saddr, const void* gaddr) {
    asm volatile("cp.async.cg.shared.global [%0], [%1], 16;"
        :: "r"(saddr), "l"(gaddr) : "memory");
}
#define CP_COMMIT() asm volatile("cp.async.commit_group;" ::: "memory")
#define CP_WAIT(n)  asm volatile("cp.async.wait_group %0;" :: "n"(n) : "memory")

// ---------------- fp32 -> bf16 hi/lo conversion -----------------------------
__global__ void __launch_bounds__(256)
cvt_kernel(const float* __restrict__ src, __nv_bfloat16* __restrict__ hi,
           __nv_bfloat16* __restrict__ lo, int n4)
{
    int i = blockIdx.x * 256 + threadIdx.x;
    if (i >= n4) return;
    float4 v = ((const float4*)src)[i];
    uint2 h, l;
    split2(v.x, v.y, h.x, l.x);
    split2(v.z, v.w, h.y, l.y);
    ((uint2*)hi)[i] = h;
    ((uint2*)lo)[i] = l;
}

// =================== HMMA GEMM (bf16 hi/lo, 3-stage cp.async) ===============
#define ROWB 80
#define ST_A_HI 0
#define ST_A_LO 10240
#define ST_B_HI 20480
#define ST_B_LO 30720
#define STAGEB 40960
#define NSTAGE 3
#define GEMM_SMEM_BYTES (NSTAGE * STAGEB)   // 120 KB

__global__ void __launch_bounds__(256)
gemm_bf16_kernel(const __nv_bfloat16* __restrict__ Ahi,
                 const __nv_bfloat16* __restrict__ Alo,
                 const __nv_bfloat16* __restrict__ Bhi,
                 const __nv_bfloat16* __restrict__ Blo,
                 const float* __restrict__ bias, float* __restrict__ C,
                 int M, int Nn, int K)
{
    extern __shared__ char sm[];
    const uint32_t smb = smem_u32(sm);
    const int tid  = threadIdx.x;
    const int wid  = tid >> 5;
    const int lane = tid & 31;
    const int m0 = blockIdx.y * 128;
    const int n0 = blockIdx.x * 128;
    const int wm0 = (wid & 3) * 32;
    const int wn0 = (wid >> 2) * 64;

    const int a_row = (lane & 7) + ((lane >> 3) & 1) * 8;
    const int a_kh  = (lane >> 4) * 8;
    const int b_row = (lane & 7) + ((lane >> 4) & 1) * 8;
    const int b_kh  = ((lane >> 3) & 1) * 8;

    float acc[2][8][4];
#pragma unroll
    for (int i = 0; i < 2; i++)
#pragma unroll
        for (int j = 0; j < 8; j++)
#pragma unroll
            for (int l = 0; l < 4; l++) acc[i][j][l] = 0.f;

    const int NCH = K / 32;
    const int row2 = tid >> 2;
    const int seg  = tid & 3;

#define LOAD_STAGE(c, buf) do {                                              \
    int k0 = (c) * 32;                                                       \
    uint32_t base = smb + (buf) * STAGEB;                                    \
    _Pragma("unroll")                                                        \
    for (int i = 0; i < 2; i++) {                                            \
        int r = row2 + i * 64;                                               \
        uint32_t so = r * ROWB + seg * 16;                                   \
        size_t ga = (size_t)(m0 + r) * K + k0 + seg * 8;                     \
        size_t gb = (size_t)(n0 + r) * K + k0 + seg * 8;                     \
        cp16(base + ST_A_HI + so, Ahi + ga);                                 \
        cp16(base + ST_A_LO + so, Alo + ga);                                 \
        cp16(base + ST_B_HI + so, Bhi + gb);                                 \
        cp16(base + ST_B_LO + so, Blo + gb);                                 \
    }                                                                        \
    CP_COMMIT();                                                             \
} while (0)

    LOAD_STAGE(0, 0);
    LOAD_STAGE(1, 1);
    LOAD_STAGE(2, 2);

    int buf = 0;
    for (int c = 0; c < NCH; c++) {
        CP_WAIT(2);
        __syncthreads();
        const uint32_t base = smb + buf * STAGEB;

#pragma unroll
        for (int ks = 0; ks < 2; ks++) {
            uint32_t ah[2][4], al[2][4], bh[4][4], bl[4][4];
#pragma unroll
            for (int mf = 0; mf < 2; mf++) {
                uint32_t ao = base + (wm0 + mf * 16 + a_row) * ROWB
                            + (ks * 16 + a_kh) * 2;
                ldmx4(ah[mf], ao + ST_A_HI);
                ldmx4(al[mf], ao + ST_A_LO);
            }
#pragma unroll
            for (int nf2 = 0; nf2 < 4; nf2++) {
                uint32_t bo = base + (wn0 + nf2 * 16 + b_row) * ROWB
                            + (ks * 16 + b_kh) * 2;
                ldmx4(bh[nf2], bo + ST_B_HI);
                ldmx4(bl[nf2], bo + ST_B_LO);
            }
#pragma unroll
            for (int nf2 = 0; nf2 < 4; nf2++)
#pragma unroll
                for (int mf = 0; mf < 2; mf++)
#pragma unroll
                    for (int s = 0; s < 2; s++)
                        mma16816(acc[mf][nf2 * 2 + s], ah[mf],
                                 bh[nf2][s * 2], bh[nf2][s * 2 + 1]);
#pragma unroll
            for (int nf2 = 0; nf2 < 4; nf2++)
#pragma unroll
                for (int mf = 0; mf < 2; mf++)
#pragma unroll
                    for (int s = 0; s < 2; s++)
                        mma16816(acc[mf][nf2 * 2 + s], al[mf],
                                 bh[nf2][s * 2], bh[nf2][s * 2 + 1]);
#pragma unroll
            for (int nf2 = 0; nf2 < 4; nf2++)
#pragma unroll
                for (int mf = 0; mf < 2; mf++)
#pragma unroll
                    for (int s = 0; s < 2; s++)
                        mma16816(acc[mf][nf2 * 2 + s], ah[mf],
                                 bl[nf2][s * 2], bl[nf2][s * 2 + 1]);
        }
        __syncthreads();
        if (c + 3 < NCH) LOAD_STAGE(c + 3, buf);
        else CP_COMMIT();
        buf = (buf == NSTAGE - 1) ? 0 : buf + 1;
    }
#undef LOAD_STAGE

    const int rr = lane >> 2;
    const int cc = (lane & 3) * 2;
#pragma unroll
    for (int mf = 0; mf < 2; mf++) {
        int r0 = m0 + wm0 + mf * 16 + rr;
#pragma unroll
        for (int nf = 0; nf < 8; nf++) {
            int col = n0 + wn0 + nf * 8 + cc;
            float b0 = bias[col], b1 = bias[col + 1];
            float2 v0 = {acc[mf][nf][0] + b0, acc[mf][nf][1] + b1};
            float2 v1 = {acc[mf][nf][2] + b0, acc[mf][nf][3] + b1};
            *(float2*)&C[(size_t)r0 * Nn + col] = v0;
            *(float2*)&C[(size_t)(r0 + 8) * Nn + col] = v1;
        }
    }
}

// ---------------- zero accumulators ----------------------------------------
__global__ void zero_kernel() {
    int i = blockIdx.x * 256 + threadIdx.x;
    if (i < BB * HH * HD * HD) g_kv[i] = 0.f;
    if (i < BB * HH * HD) { g_ksum[i] = 0.f; g_vsum[i] = 0.f; }
}

// ---------------- stats: kv_state / ksum / vsum per (b,h) ------------------
__global__ void __launch_bounds__(256)
stats_kernel(const float* __restrict__ qkvo,
             const float* __restrict__ sinp, const float* __restrict__ cosp)
{
    __shared__ float sks[8][32];
    __shared__ float svh[8][32];

    const int bh = blockIdx.x;
    const int split = blockIdx.y;
    const int b = bh >> 3, h = bh & 7;
    const int w = threadIdx.x >> 5;
    const int lane = threadIdx.x & 31;
    const int n_start = split * (NN / 32);

    const int dA = threadIdx.x >> 3;
    const int e4 = (threadIdx.x & 7) * 4;

    float kv0 = 0.f, kv1 = 0.f, kv2 = 0.f, kv3 = 0.f;
    float ksum_acc = 0.f, vsum_acc = 0.f;

    for (int c0 = 0; c0 < NN / 32; c0 += 8) {
        int n = n_start + c0 + w;
        size_t row = (size_t)(b * NN + n) * QKVO_COLS;
        float kraw = qkvo[row + 256 + h * 32 + lane];
        float v    = qkvo[row + 512 + h * 32 + lane];
        float kh = (kraw > 0.f) ? (kraw + 1.f) : expf(kraw);
        ksum_acc += kh;
        vsum_acc += v;
        float partner = __shfl_xor_sync(0xffffffffu, kh, 1);
        float sv = sinp[n * HD + lane];
        float cv = cosp[n * HD + lane];
        float rot = (lane & 1) ? partner : -partner;
        float ks = kh * cv + rot * sv;
        sks[w][lane] = ks;
        svh[w][lane] = v;
        __syncthreads();
#pragma unroll
        for (int j = 0; j < 8; j++) {
            float a = sks[j][dA];
            float4 vv = *(const float4*)&svh[j][e4];
            kv0 += a * vv.x;
            kv1 += a * vv.y;
            kv2 += a * vv.z;
            kv3 += a * vv.w;
        }
        __syncthreads();
    }

    float* kvdst = &g_kv[bh * (HD * HD) + dA * HD + e4];
    atomicAdd(kvdst + 0, kv0);
    atomicAdd(kvdst + 1, kv1);
    atomicAdd(kvdst + 2, kv2);
    atomicAdd(kvdst + 3, kv3);
    atomicAdd(&g_ksum[bh * HD + lane], ksum_acc);
    atomicAdd(&g_vsum[bh * HD + lane], vsum_acc);
}

// ---------------- fused per-token epilogue -> bf16 hi/lo --------------------
// TILE_ROWS=16 -> 2048 blocks -> ~6 resident blocks/SM (smem-limited), ~75% occ.
#define TILE_ROWS 16
__global__ void __launch_bounds__(256)
fuse_kernel(const float* __restrict__ qkvo,
            const float* __restrict__ sinp, const float* __restrict__ cosp,
            const float* __restrict__ W_lepe, const float* __restrict__ b_lepe,
            __nv_bfloat16* __restrict__ phi, __nv_bfloat16* __restrict__ plo)
{
    __shared__ float skv[HH * HD * HD];

    const int tile = blockIdx.x;
    const int b  = tile / (NN / TILE_ROWS);
    const int t  = tile % (NN / TILE_ROWS);
    const int n0 = t * TILE_ROWS;
    const int c  = threadIdx.x;
    const int h  = c >> 5;
    const int d  = c & 31;
    const float inv_scale_n = SCALE_F / (float)NN;

    const int base_kv = b * HH * HD * HD;
#pragma unroll
    for (int i = 0; i < HH * HD * HD / 256; i++)
        skv[i * 256 + c] = g_kv[base_kv + i * 256 + c] * inv_scale_n;

    const float km = g_ksum[(b * HH + h) * HD + d];
    const float vm = g_vsum[(b * HH + h) * HD + d] * (1.f / NN);
    __syncthreads();

    const float w0 = W_lepe[c * 3 + 0];
    const float w1 = W_lepe[c * 3 + 1];
    const float w2 = W_lepe[c * 3 + 2];
    const float bl = b_lepe[c];

    size_t rowbase = (size_t)(b * NN + n0) * QKVO_COLS;
    float v_prev = (n0 > 0) ? qkvo[rowbase - QKVO_COLS + 512 + c] : 0.f;
    float v_cur  = qkvo[rowbase + 512 + c];

    const float* kvh = &skv[h * HD * HD];

#pragma unroll 1
    for (int r = 0; r < TILE_ROWS; r++) {
        int n = n0 + r;
        size_t row = (size_t)(b * NN + n) * QKVO_COLS;
        float v_next = (n + 1 < NN) ? qkvo[row + QKVO_COLS + 512 + c] : 0.f;

        float q  = qkvo[row + c];
        float qh = (q > 0.f) ? (q + 1.f) : __expf(q);

        float zp = qh * km;
#pragma unroll
        for (int off = 16; off > 0; off >>= 1)
            zp += __shfl_xor_sync(0xffffffffu, zp, off);
        float z = zp * inv_scale_n;

        float partner = __shfl_xor_sync(0xffffffffu, qh, 1);
        float sv = sinp[n * HD + d];
        float cv = cosp[n * HD + d];
        float rot = (d & 1) ? partner : -partner;
        float qs = qh * cv + rot * sv;

        float acc = 0.f;
#pragma unroll
        for (int dd = 0; dd < 32; dd++) {
            float qsd = __shfl_sync(0xffffffffu, qs, dd);
            acc += qsd * kvh[dd * HD + d];
        }

        float coef = 1.f + 1.f / (z + 1e-6f);
        float res  = acc * coef - z * vm;
        float lepe = v_prev * w0 + v_cur * w1 + v_next * w2 + bl;
        float o    = qkvo[row + 768 + c];

        float val = (res + lepe) * o;
        __nv_bfloat16 vh = __float2bfloat16(val);
        __nv_bfloat16 vl = __float2bfloat16(val - __bfloat162float(vh));
        size_t oidx = (size_t)(b * NN + n) * INTERNAL + c;
        phi[oidx] = vh;
        plo[oidx] = vl;

        v_prev = v_cur;
        v_cur  = v_next;
    }
}

// ---------------- launch -----------------------------------------------------
extern "C" void kernel_launch(void* const* d_in, const int* in_sizes, int n_in,
                              void* d_out, int out_size)
{
    const float* x       = (const float*)d_in[0];
    const float* sinp    = (const float*)d_in[1];
    const float* cosp    = (const float*)d_in[2];
    const float* W_qkvo  = (const float*)d_in[3];
    const float* b_qkvo  = (const float*)d_in[4];
    const float* W_lepe  = (const float*)d_in[5];
    const float* b_lepe  = (const float*)d_in[6];
    const float* W_proj  = (const float*)d_in[7];
    const float* b_proj  = (const float*)d_in[8];
    float* out = (float*)d_out;

    float *qkvo_p;
    __nv_bfloat16 *xhi, *xlo, *phi, *plo, *wqhi, *wqlo, *pwhi, *pwlo;
    cudaGetSymbolAddress((void**)&qkvo_p, g_qkvo);
    cudaGetSymbolAddress((void**)&xhi, g_xhi);
    cudaGetSymbolAddress((void**)&xlo, g_xlo);
    cudaGetSymbolAddress((void**)&phi, g_phi);
    cudaGetSymbolAddress((void**)&plo, g_plo);
    cudaGetSymbolAddress((void**)&wqhi, g_wqhi);
    cudaGetSymbolAddress((void**)&wqlo, g_wqlo);
    cudaGetSymbolAddress((void**)&pwhi, g_pwhi);
    cudaGetSymbolAddress((void**)&pwlo, g_pwlo);

    cudaFuncSetAttribute(gemm_bf16_kernel,
                         cudaFuncAttributeMaxDynamicSharedMemorySize, GEMM_SMEM_BYTES);

    zero_kernel<<<(BB * HH * HD * HD + 255) / 256, 256>>>();

    cvt_kernel<<<(MROWS * DIMV / 4 + 255) / 256, 256>>>(x, xhi, xlo, MROWS * DIMV / 4);
    cvt_kernel<<<(QKVO_COLS * DIMV / 4 + 255) / 256, 256>>>(W_qkvo, wqhi, wqlo, QKVO_COLS * DIMV / 4);
    cvt_kernel<<<(DIMV * INTERNAL / 4 + 255) / 256, 256>>>(W_proj, pwhi, pwlo, DIMV * INTERNAL / 4);

    // GEMM1: qkvo = x @ W_qkvo^T + b_qkvo   [32768 x 1024]
    gemm_bf16_kernel<<<dim3(QKVO_COLS / 128, MROWS / 128), 256, GEMM_SMEM_BYTES>>>(
        xhi, xlo, wqhi, wqlo, b_qkvo, qkvo_p, MROWS, QKVO_COLS, DIMV);

    stats_kernel<<<dim3(BB * HH, 32), 256>>>(qkvo_p, sinp, cosp);

    fuse_kernel<<<BB * (NN / TILE_ROWS), 256>>>(qkvo_p, sinp, cosp,
                                                W_lepe, b_lepe, phi, plo);

    // GEMM2: out = pre @ W_proj^T + b_proj  [32768 x 256]
    gemm_bf16_kernel<<<dim3(INTERNAL / 128, MROWS / 128), 256, GEMM_SMEM_BYTES>>>(
        phi, plo, pwhi, pwlo, b_proj, out, MROWS, INTERNAL, DIMV);
}

// round 8
// speedup vs baseline: 2.1240x; 1.5204x over previous
#include <cuda_runtime.h>
#include <cuda_fp16.h>
#include <math.h>
#include <stdint.h>

#define BB 4
#define NN 8192
#define DIMV 256
#define HH 8
#define HD 32
#define INTERNAL 256
#define MROWS (BB * NN)        // 32768
#define QKVO_COLS 1024
#define SCALE_F 0.17677669529663687f

// ---------------- persistent device scratch (no allocations) ----------------
__device__ float  g_qkvo[(size_t)MROWS * QKVO_COLS];    // 134 MB fp32
__device__ __half g_xh [(size_t)MROWS * DIMV];          // fp16 x
__device__ __half g_ph [(size_t)MROWS * INTERNAL];      // fp16 pre
__device__ __half g_wqh[(size_t)QKVO_COLS * DIMV];      // fp16 W_qkvo
__device__ __half g_pwh[(size_t)DIMV * INTERNAL];       // fp16 W_proj
__device__ float g_kv  [BB * HH * HD * HD];
__device__ float g_ksum[BB * HH * HD];
__device__ float g_vsum[BB * HH * HD];

__device__ __forceinline__ uint32_t smem_u32(const void* p) {
    uint32_t a;
    asm("{ .reg .u64 t; cvta.to.shared.u64 t, %1; cvt.u32.u64 %0, t; }"
        : "=r"(a) : "l"(p));
    return a;
}

__device__ __forceinline__ void ldmx4(uint32_t* r, uint32_t addr) {
    asm volatile("ldmatrix.sync.aligned.m8n8.x4.shared.b16 {%0,%1,%2,%3}, [%4];"
        : "=r"(r[0]), "=r"(r[1]), "=r"(r[2]), "=r"(r[3]) : "r"(addr));
}

__device__ __forceinline__ void mma16816h(float* d, const uint32_t* a,
                                          uint32_t b0, uint32_t b1) {
    asm volatile(
        "mma.sync.aligned.m16n8k16.row.col.f32.f16.f16.f32 "
        "{%0,%1,%2,%3}, {%4,%5,%6,%7}, {%8,%9}, {%0,%1,%2,%3};"
        : "+f"(d[0]), "+f"(d[1]), "+f"(d[2]), "+f"(d[3])
        : "r"(a[0]), "r"(a[1]), "r"(a[2]), "r"(a[3]), "r"(b0), "r"(b1));
}

__device__ __forceinline__ void cp16(uint32_t saddr, const void* gaddr) {
    asm volatile("cp.async.cg.shared.global [%0], [%1], 16;"
        :: "r"(saddr), "l"(gaddr) : "memory");
}
#define CP_COMMIT() asm volatile("cp.async.commit_group;" ::: "memory")
#define CP_WAIT(n)  asm volatile("cp.async.wait_group %0;" :: "n"(n) : "memory")

// ---------------- fp32 -> fp16 conversion -----------------------------------
__global__ void __launch_bounds__(256)
cvt_h_kernel(const float* __restrict__ src, __half* __restrict__ dst, int n4)
{
    int i = blockIdx.x * 256 + threadIdx.x;
    if (i >= n4) return;
    float4 v = ((const float4*)src)[i];
    __half2 h0 = __floats2half2_rn(v.x, v.y);
    __half2 h1 = __floats2half2_rn(v.z, v.w);
    uint2 o = { *reinterpret_cast<uint32_t*>(&h0), *reinterpret_cast<uint32_t*>(&h1) };
    ((uint2*)dst)[i] = o;
}

// =================== HMMA GEMM (single fp16, 4-stage cp.async) ==============
// C[M,Nn] = A[M,K] @ Bw[Nn,K]^T + bias.  128x128 tile, BK=32, 8 warps (4Mx2N).
#define ROWB 80
#define ST_A 0
#define ST_B 10240
#define STAGEB 20480
#define NSTAGE 4
#define GEMM_SMEM_BYTES (NSTAGE * STAGEB)   // 80 KB

__global__ void __launch_bounds__(256)
gemm_h_kernel(const __half* __restrict__ A, const __half* __restrict__ Bw,
              const float* __restrict__ bias, float* __restrict__ C,
              int M, int Nn, int K)
{
    extern __shared__ char sm[];
    const uint32_t smb = smem_u32(sm);
    const int tid  = threadIdx.x;
    const int wid  = tid >> 5;
    const int lane = tid & 31;
    const int m0 = blockIdx.y * 128;
    const int n0 = blockIdx.x * 128;
    const int wm0 = (wid & 3) * 32;
    const int wn0 = (wid >> 2) * 64;

    const int a_row = (lane & 7) + ((lane >> 3) & 1) * 8;
    const int a_kh  = (lane >> 4) * 8;
    const int b_row = (lane & 7) + ((lane >> 4) & 1) * 8;
    const int b_kh  = ((lane >> 3) & 1) * 8;

    float acc[2][8][4];
#pragma unroll
    for (int i = 0; i < 2; i++)
#pragma unroll
        for (int j = 0; j < 8; j++)
#pragma unroll
            for (int l = 0; l < 4; l++) acc[i][j][l] = 0.f;

    const int NCH = K / 32;             // 8
    const int row2 = tid >> 2;          // 0..63
    const int seg  = tid & 3;           // 16B segment (covers 64B row)

#define LOAD_STAGE(c, buf) do {                                              \
    int k0 = (c) * 32;                                                       \
    uint32_t base = smb + (buf) * STAGEB;                                    \
    _Pragma("unroll")                                                        \
    for (int i = 0; i < 2; i++) {                                            \
        int r = row2 + i * 64;                                               \
        uint32_t so = r * ROWB + seg * 16;                                   \
        cp16(base + ST_A + so, A  + (size_t)(m0 + r) * K + k0 + seg * 8);    \
        cp16(base + ST_B + so, Bw + (size_t)(n0 + r) * K + k0 + seg * 8);    \
    }                                                                        \
    CP_COMMIT();                                                             \
} while (0)

    LOAD_STAGE(0, 0);
    LOAD_STAGE(1, 1);
    LOAD_STAGE(2, 2);

    for (int c = 0; c < NCH; c++) {
        CP_WAIT(2);                 // stage c landed
        __syncthreads();
        const uint32_t base = smb + (c & (NSTAGE - 1)) * STAGEB;

#pragma unroll
        for (int ks = 0; ks < 2; ks++) {
            uint32_t af[2][4], bf[4][4];
#pragma unroll
            for (int mf = 0; mf < 2; mf++)
                ldmx4(af[mf], base + ST_A + (wm0 + mf * 16 + a_row) * ROWB
                                        + (ks * 16 + a_kh) * 2);
#pragma unroll
            for (int nf2 = 0; nf2 < 4; nf2++)
                ldmx4(bf[nf2], base + ST_B + (wn0 + nf2 * 16 + b_row) * ROWB
                                          + (ks * 16 + b_kh) * 2);
#pragma unroll
            for (int nf2 = 0; nf2 < 4; nf2++)
#pragma unroll
                for (int mf = 0; mf < 2; mf++)
#pragma unroll
                    for (int s = 0; s < 2; s++)
                        mma16816h(acc[mf][nf2 * 2 + s], af[mf],
                                  bf[nf2][s * 2], bf[nf2][s * 2 + 1]);
        }
        __syncthreads();            // all warps done reading this stage's peers
        if (c + 3 < NCH) LOAD_STAGE(c + 3, (c + 3) & (NSTAGE - 1));
        else CP_COMMIT();           // keep group count aligned
    }
#undef LOAD_STAGE

    const int rr = lane >> 2;
    const int cc = (lane & 3) * 2;
#pragma unroll
    for (int mf = 0; mf < 2; mf++) {
        int r0 = m0 + wm0 + mf * 16 + rr;
#pragma unroll
        for (int nf = 0; nf < 8; nf++) {
            int col = n0 + wn0 + nf * 8 + cc;
            float b0 = bias[col], b1 = bias[col + 1];
            float2 v0 = {acc[mf][nf][0] + b0, acc[mf][nf][1] + b1};
            float2 v1 = {acc[mf][nf][2] + b0, acc[mf][nf][3] + b1};
            *(float2*)&C[(size_t)r0 * Nn + col] = v0;
            *(float2*)&C[(size_t)(r0 + 8) * Nn + col] = v1;
        }
    }
}

// ---------------- zero accumulators ----------------------------------------
__global__ void zero_kernel() {
    int i = blockIdx.x * 256 + threadIdx.x;
    if (i < BB * HH * HD * HD) g_kv[i] = 0.f;
    if (i < BB * HH * HD) { g_ksum[i] = 0.f; g_vsum[i] = 0.f; }
}

// ---------------- stats: kv_state / ksum / vsum per (b,h) ------------------
__global__ void __launch_bounds__(256)
stats_kernel(const float* __restrict__ qkvo,
             const float* __restrict__ sinp, const float* __restrict__ cosp)
{
    __shared__ float sks[8][32];
    __shared__ float svh[8][32];

    const int bh = blockIdx.x;
    const int split = blockIdx.y;
    const int b = bh >> 3, h = bh & 7;
    const int w = threadIdx.x >> 5;
    const int lane = threadIdx.x & 31;
    const int n_start = split * (NN / 32);

    const int dA = threadIdx.x >> 3;
    const int e4 = (threadIdx.x & 7) * 4;

    float kv0 = 0.f, kv1 = 0.f, kv2 = 0.f, kv3 = 0.f;
    float ksum_acc = 0.f, vsum_acc = 0.f;

    for (int c0 = 0; c0 < NN / 32; c0 += 8) {
        int n = n_start + c0 + w;
        size_t row = (size_t)(b * NN + n) * QKVO_COLS;
        float kraw = qkvo[row + 256 + h * 32 + lane];
        float v    = qkvo[row + 512 + h * 32 + lane];
        float kh = (kraw > 0.f) ? (kraw + 1.f) : expf(kraw);
        ksum_acc += kh;
        vsum_acc += v;
        float partner = __shfl_xor_sync(0xffffffffu, kh, 1);
        float sv = sinp[n * HD + lane];
        float cv = cosp[n * HD + lane];
        float rot = (lane & 1) ? partner : -partner;
        float ks = kh * cv + rot * sv;
        sks[w][lane] = ks;
        svh[w][lane] = v;
        __syncthreads();
#pragma unroll
        for (int j = 0; j < 8; j++) {
            float a = sks[j][dA];
            float4 vv = *(const float4*)&svh[j][e4];
            kv0 += a * vv.x;
            kv1 += a * vv.y;
            kv2 += a * vv.z;
            kv3 += a * vv.w;
        }
        __syncthreads();
    }

    float* kvdst = &g_kv[bh * (HD * HD) + dA * HD + e4];
    atomicAdd(kvdst + 0, kv0);
    atomicAdd(kvdst + 1, kv1);
    atomicAdd(kvdst + 2, kv2);
    atomicAdd(kvdst + 3, kv3);
    atomicAdd(&g_ksum[bh * HD + lane], ksum_acc);
    atomicAdd(&g_vsum[bh * HD + lane], vsum_acc);
}

// ---------------- fused per-token epilogue -> fp16 pre ----------------------
#define TILE_ROWS 16
__global__ void __launch_bounds__(256)
fuse_kernel(const float* __restrict__ qkvo,
            const float* __restrict__ sinp, const float* __restrict__ cosp,
            const float* __restrict__ W_lepe, const float* __restrict__ b_lepe,
            __half* __restrict__ ph)
{
    __shared__ float skv[HH * HD * HD];

    const int tile = blockIdx.x;
    const int b  = tile / (NN / TILE_ROWS);
    const int t  = tile % (NN / TILE_ROWS);
    const int n0 = t * TILE_ROWS;
    const int c  = threadIdx.x;
    const int h  = c >> 5;
    const int d  = c & 31;
    const float inv_scale_n = SCALE_F / (float)NN;

    const int base_kv = b * HH * HD * HD;
#pragma unroll
    for (int i = 0; i < HH * HD * HD / 256; i++)
        skv[i * 256 + c] = g_kv[base_kv + i * 256 + c] * inv_scale_n;

    const float km = g_ksum[(b * HH + h) * HD + d];
    const float vm = g_vsum[(b * HH + h) * HD + d] * (1.f / NN);
    __syncthreads();

    const float w0 = W_lepe[c * 3 + 0];
    const float w1 = W_lepe[c * 3 + 1];
    const float w2 = W_lepe[c * 3 + 2];
    const float bl = b_lepe[c];

    size_t rowbase = (size_t)(b * NN + n0) * QKVO_COLS;
    float v_prev = (n0 > 0) ? qkvo[rowbase - QKVO_COLS + 512 + c] : 0.f;
    float v_cur  = qkvo[rowbase + 512 + c];

    const float* kvh = &skv[h * HD * HD];

#pragma unroll 1
    for (int r = 0; r < TILE_ROWS; r++) {
        int n = n0 + r;
        size_t row = (size_t)(b * NN + n) * QKVO_COLS;
        float v_next = (n + 1 < NN) ? qkvo[row + QKVO_COLS + 512 + c] : 0.f;

        float q  = qkvo[row + c];
        float qh = (q > 0.f) ? (q + 1.f) : __expf(q);

        float zp = qh * km;
#pragma unroll
        for (int off = 16; off > 0; off >>= 1)
            zp += __shfl_xor_sync(0xffffffffu, zp, off);
        float z = zp * inv_scale_n;

        float partner = __shfl_xor_sync(0xffffffffu, qh, 1);
        float sv = sinp[n * HD + d];
        float cv = cosp[n * HD + d];
        float rot = (d & 1) ? partner : -partner;
        float qs = qh * cv + rot * sv;

        float acc = 0.f;
#pragma unroll
        for (int dd = 0; dd < 32; dd++) {
            float qsd = __shfl_sync(0xffffffffu, qs, dd);
            acc += qsd * kvh[dd * HD + d];
        }

        float coef = 1.f + 1.f / (z + 1e-6f);
        float res  = acc * coef - z * vm;
        float lepe = v_prev * w0 + v_cur * w1 + v_next * w2 + bl;
        float o    = qkvo[row + 768 + c];

        ph[(size_t)(b * NN + n) * INTERNAL + c] = __float2half((res + lepe) * o);

        v_prev = v_cur;
        v_cur  = v_next;
    }
}

// ---------------- launch -----------------------------------------------------
extern "C" void kernel_launch(void* const* d_in, const int* in_sizes, int n_in,
                              void* d_out, int out_size)
{
    const float* x       = (const float*)d_in[0];
    const float* sinp    = (const float*)d_in[1];
    const float* cosp    = (const float*)d_in[2];
    const float* W_qkvo  = (const float*)d_in[3];
    const float* b_qkvo  = (const float*)d_in[4];
    const float* W_lepe  = (const float*)d_in[5];
    const float* b_lepe  = (const float*)d_in[6];
    const float* W_proj  = (const float*)d_in[7];
    const float* b_proj  = (const float*)d_in[8];
    float* out = (float*)d_out;

    float *qkvo_p;
    __half *xh, *ph, *wqh, *pwh;
    cudaGetSymbolAddress((void**)&qkvo_p, g_qkvo);
    cudaGetSymbolAddress((void**)&xh,  g_xh);
    cudaGetSymbolAddress((void**)&ph,  g_ph);
    cudaGetSymbolAddress((void**)&wqh, g_wqh);
    cudaGetSymbolAddress((void**)&pwh, g_pwh);

    cudaFuncSetAttribute(gemm_h_kernel,
                         cudaFuncAttributeMaxDynamicSharedMemorySize, GEMM_SMEM_BYTES);

    zero_kernel<<<(BB * HH * HD * HD + 255) / 256, 256>>>();

    cvt_h_kernel<<<(MROWS * DIMV / 4 + 255) / 256, 256>>>(x, xh, MROWS * DIMV / 4);
    cvt_h_kernel<<<(QKVO_COLS * DIMV / 4 + 255) / 256, 256>>>(W_qkvo, wqh, QKVO_COLS * DIMV / 4);
    cvt_h_kernel<<<(DIMV * INTERNAL / 4 + 255) / 256, 256>>>(W_proj, pwh, DIMV * INTERNAL / 4);

    // GEMM1: qkvo = x @ W_qkvo^T + b_qkvo   [32768 x 1024]
    gemm_h_kernel<<<dim3(QKVO_COLS / 128, MROWS / 128), 256, GEMM_SMEM_BYTES>>>(
        xh, wqh, b_qkvo, qkvo_p, MROWS, QKVO_COLS, DIMV);

    stats_kernel<<<dim3(BB * HH, 32), 256>>>(qkvo_p, sinp, cosp);

    fuse_kernel<<<BB * (NN / TILE_ROWS), 256>>>(qkvo_p, sinp, cosp,
                                                W_lepe, b_lepe, ph);

    // GEMM2: out = pre @ W_proj^T + b_proj  [32768 x 256]
    gemm_h_kernel<<<dim3(INTERNAL / 128, MROWS / 128), 256, GEMM_SMEM_BYTES>>>(
        ph, pwh, b_proj, out, MROWS, INTERNAL, DIMV);
}

// round 9
// speedup vs baseline: 2.2461x; 1.0575x over previous
#include <cuda_runtime.h>
#include <cuda_fp16.h>
#include <math.h>
#include <stdint.h>

#define BB 4
#define NN 8192
#define DIMV 256
#define HH 8
#define HD 32
#define INTERNAL 256
#define MROWS (BB * NN)        // 32768
#define QKVO_COLS 1024
#define SCALE_F 0.17677669529663687f

// ---------------- persistent device scratch (no allocations) ----------------
__device__ float  g_qkvo[(size_t)MROWS * QKVO_COLS];    // 134 MB fp32
__device__ __half g_xh [(size_t)MROWS * DIMV];
__device__ __half g_ph [(size_t)MROWS * INTERNAL];
__device__ __half g_wqh[(size_t)QKVO_COLS * DIMV];
__device__ __half g_pwh[(size_t)DIMV * INTERNAL];
__device__ float g_kv  [BB * HH * HD * HD];
__device__ float g_ksum[BB * HH * HD];
__device__ float g_vsum[BB * HH * HD];

__device__ __forceinline__ uint32_t smem_u32(const void* p) {
    uint32_t a;
    asm("{ .reg .u64 t; cvta.to.shared.u64 t, %1; cvt.u32.u64 %0, t; }"
        : "=r"(a) : "l"(p));
    return a;
}

__device__ __forceinline__ void ldmx4(uint32_t* r, uint32_t addr) {
    asm volatile("ldmatrix.sync.aligned.m8n8.x4.shared.b16 {%0,%1,%2,%3}, [%4];"
        : "=r"(r[0]), "=r"(r[1]), "=r"(r[2]), "=r"(r[3]) : "r"(addr));
}

__device__ __forceinline__ void mma16816h(float* d, const uint32_t* a,
                                          uint32_t b0, uint32_t b1) {
    asm volatile(
        "mma.sync.aligned.m16n8k16.row.col.f32.f16.f16.f32 "
        "{%0,%1,%2,%3}, {%4,%5,%6,%7}, {%8,%9}, {%0,%1,%2,%3};"
        : "+f"(d[0]), "+f"(d[1]), "+f"(d[2]), "+f"(d[3])
        : "r"(a[0]), "r"(a[1]), "r"(a[2]), "r"(a[3]), "r"(b0), "r"(b1));
}

__device__ __forceinline__ void cp16(uint32_t saddr, const void* gaddr) {
    asm volatile("cp.async.cg.shared.global [%0], [%1], 16;"
        :: "r"(saddr), "l"(gaddr) : "memory");
}
#define CP_COMMIT() asm volatile("cp.async.commit_group;" ::: "memory")
#define CP_WAIT(n)  asm volatile("cp.async.wait_group %0;" :: "n"(n) : "memory")

// ---------------- fused fp32 -> fp16 conversion (one launch) ----------------
#define CVT_N1 (MROWS * DIMV / 4)
#define CVT_N2 (QKVO_COLS * DIMV / 4)
#define CVT_N3 (DIMV * INTERNAL / 4)
__global__ void __launch_bounds__(256)
cvt_all_kernel(const float* __restrict__ x, const float* __restrict__ wq,
               const float* __restrict__ pw, __half* __restrict__ xh,
               __half* __restrict__ wqh, __half* __restrict__ pwh)
{
    int i = blockIdx.x * 256 + threadIdx.x;
    const float* s; __half* d; int j;
    if (i < CVT_N1) { s = x; d = xh; j = i; }
    else if (i < CVT_N1 + CVT_N2) { s = wq; d = wqh; j = i - CVT_N1; }
    else if (i < CVT_N1 + CVT_N2 + CVT_N3) { s = pw; d = pwh; j = i - CVT_N1 - CVT_N2; }
    else return;
    float4 v = ((const float4*)s)[j];
    __half2 h0 = __floats2half2_rn(v.x, v.y);
    __half2 h1 = __floats2half2_rn(v.z, v.w);
    uint2 o = { *reinterpret_cast<uint32_t*>(&h0), *reinterpret_cast<uint32_t*>(&h1) };
    ((uint2*)d)[j] = o;
}

// =================== HMMA GEMM (single fp16, 4-stage cp.async) ==============
#define ROWB 80
#define ST_A 0
#define ST_B 10240
#define STAGEB 20480
#define NSTAGE 4
#define GEMM_SMEM_BYTES (NSTAGE * STAGEB)   // 80 KB

__global__ void __launch_bounds__(256)
gemm_h_kernel(const __half* __restrict__ A, const __half* __restrict__ Bw,
              const float* __restrict__ bias, float* __restrict__ C,
              int M, int Nn, int K)
{
    extern __shared__ char sm[];
    const uint32_t smb = smem_u32(sm);
    const int tid  = threadIdx.x;
    const int wid  = tid >> 5;
    const int lane = tid & 31;
    const int m0 = blockIdx.y * 128;
    const int n0 = blockIdx.x * 128;
    const int wm0 = (wid & 3) * 32;
    const int wn0 = (wid >> 2) * 64;

    const int a_row = (lane & 7) + ((lane >> 3) & 1) * 8;
    const int a_kh  = (lane >> 4) * 8;
    const int b_row = (lane & 7) + ((lane >> 4) & 1) * 8;
    const int b_kh  = ((lane >> 3) & 1) * 8;

    float acc[2][8][4];
#pragma unroll
    for (int i = 0; i < 2; i++)
#pragma unroll
        for (int j = 0; j < 8; j++)
#pragma unroll
            for (int l = 0; l < 4; l++) acc[i][j][l] = 0.f;

    const int NCH = K / 32;
    const int row2 = tid >> 2;
    const int seg  = tid & 3;

#define LOAD_STAGE(c, buf) do {                                              \
    int k0 = (c) * 32;                                                       \
    uint32_t base = smb + (buf) * STAGEB;                                    \
    _Pragma("unroll")                                                        \
    for (int i = 0; i < 2; i++) {                                            \
        int r = row2 + i * 64;                                               \
        uint32_t so = r * ROWB + seg * 16;                                   \
        cp16(base + ST_A + so, A  + (size_t)(m0 + r) * K + k0 + seg * 8);    \
        cp16(base + ST_B + so, Bw + (size_t)(n0 + r) * K + k0 + seg * 8);    \
    }                                                                        \
    CP_COMMIT();                                                             \
} while (0)

    LOAD_STAGE(0, 0);
    LOAD_STAGE(1, 1);
    LOAD_STAGE(2, 2);

    for (int c = 0; c < NCH; c++) {
        CP_WAIT(2);
        __syncthreads();
        const uint32_t base = smb + (c & (NSTAGE - 1)) * STAGEB;

#pragma unroll
        for (int ks = 0; ks < 2; ks++) {
            uint32_t af[2][4], bf[4][4];
#pragma unroll
            for (int mf = 0; mf < 2; mf++)
                ldmx4(af[mf], base + ST_A + (wm0 + mf * 16 + a_row) * ROWB
                                        + (ks * 16 + a_kh) * 2);
#pragma unroll
            for (int nf2 = 0; nf2 < 4; nf2++)
                ldmx4(bf[nf2], base + ST_B + (wn0 + nf2 * 16 + b_row) * ROWB
                                          + (ks * 16 + b_kh) * 2);
#pragma unroll
            for (int nf2 = 0; nf2 < 4; nf2++)
#pragma unroll
                for (int mf = 0; mf < 2; mf++)
#pragma unroll
                    for (int s = 0; s < 2; s++)
                        mma16816h(acc[mf][nf2 * 2 + s], af[mf],
                                  bf[nf2][s * 2], bf[nf2][s * 2 + 1]);
        }
        __syncthreads();
        if (c + 3 < NCH) LOAD_STAGE(c + 3, (c + 3) & (NSTAGE - 1));
        else CP_COMMIT();
    }
#undef LOAD_STAGE

    const int rr = lane >> 2;
    const int cc = (lane & 3) * 2;
#pragma unroll
    for (int mf = 0; mf < 2; mf++) {
        int r0 = m0 + wm0 + mf * 16 + rr;
#pragma unroll
        for (int nf = 0; nf < 8; nf++) {
            int col = n0 + wn0 + nf * 8 + cc;
            float b0 = bias[col], b1 = bias[col + 1];
            float2 v0 = {acc[mf][nf][0] + b0, acc[mf][nf][1] + b1};
            float2 v1 = {acc[mf][nf][2] + b0, acc[mf][nf][3] + b1};
            *(float2*)&C[(size_t)r0 * Nn + col] = v0;
            *(float2*)&C[(size_t)(r0 + 8) * Nn + col] = v1;
        }
    }
}

// ---------------- zero accumulators ----------------------------------------
__global__ void zero_kernel() {
    int i = blockIdx.x * 256 + threadIdx.x;
    if (i < BB * HH * HD * HD) g_kv[i] = 0.f;
    if (i < BB * HH * HD) { g_ksum[i] = 0.f; g_vsum[i] = 0.f; }
}

// ---------------- stats: kv_state / ksum / vsum per (b,h) ------------------
__global__ void __launch_bounds__(256)
stats_kernel(const float* __restrict__ qkvo,
             const float* __restrict__ sinp, const float* __restrict__ cosp)
{
    __shared__ float sks[8][32];
    __shared__ float svh[8][32];

    const int bh = blockIdx.x;
    const int split = blockIdx.y;
    const int b = bh >> 3, h = bh & 7;
    const int w = threadIdx.x >> 5;
    const int lane = threadIdx.x & 31;
    const int n_start = split * (NN / 32);

    const int dA = threadIdx.x >> 3;
    const int e4 = (threadIdx.x & 7) * 4;

    float kv0 = 0.f, kv1 = 0.f, kv2 = 0.f, kv3 = 0.f;
    float ksum_acc = 0.f, vsum_acc = 0.f;

    for (int c0 = 0; c0 < NN / 32; c0 += 8) {
        int n = n_start + c0 + w;
        size_t row = (size_t)(b * NN + n) * QKVO_COLS;
        float kraw = qkvo[row + 256 + h * 32 + lane];
        float v    = qkvo[row + 512 + h * 32 + lane];
        float kh = (kraw > 0.f) ? (kraw + 1.f) : __expf(kraw);
        ksum_acc += kh;
        vsum_acc += v;
        float partner = __shfl_xor_sync(0xffffffffu, kh, 1);
        float sv = sinp[n * HD + lane];
        float cv = cosp[n * HD + lane];
        float rot = (lane & 1) ? partner : -partner;
        float ks = kh * cv + rot * sv;
        sks[w][lane] = ks;
        svh[w][lane] = v;
        __syncthreads();
#pragma unroll
        for (int j = 0; j < 8; j++) {
            float a = sks[j][dA];
            float4 vv = *(const float4*)&svh[j][e4];
            kv0 += a * vv.x;
            kv1 += a * vv.y;
            kv2 += a * vv.z;
            kv3 += a * vv.w;
        }
        __syncthreads();
    }

    float* kvdst = &g_kv[bh * (HD * HD) + dA * HD + e4];
    atomicAdd(kvdst + 0, kv0);
    atomicAdd(kvdst + 1, kv1);
    atomicAdd(kvdst + 2, kv2);
    atomicAdd(kvdst + 3, kv3);
    atomicAdd(&g_ksum[bh * HD + lane], ksum_acc);
    atomicAdd(&g_vsum[bh * HD + lane], vsum_acc);
}

// ---------------- fused per-token epilogue (4-row ILP) -> fp16 pre ----------
#define TILE_ROWS 64
#define RG 4
__global__ void __launch_bounds__(256)
fuse_kernel(const float* __restrict__ qkvo,
            const float* __restrict__ sinp, const float* __restrict__ cosp,
            const float* __restrict__ W_lepe, const float* __restrict__ b_lepe,
            __half* __restrict__ ph)
{
    __shared__ float skv[HH * HD * HD];

    const int tile = blockIdx.x;
    const int b  = tile / (NN / TILE_ROWS);
    const int t  = tile % (NN / TILE_ROWS);
    const int n0 = t * TILE_ROWS;                 // local to batch
    const int c  = threadIdx.x;
    const int h  = c >> 5;
    const int d  = c & 31;
    const float inv_scale_n = SCALE_F / (float)NN;

    const int base_kv = b * HH * HD * HD;
#pragma unroll
    for (int i = 0; i < HH * HD * HD / 256; i++)
        skv[i * 256 + c] = g_kv[base_kv + i * 256 + c] * inv_scale_n;

    const float km = g_ksum[(b * HH + h) * HD + d];
    const float vm = g_vsum[(b * HH + h) * HD + d] * (1.f / NN);
    __syncthreads();

    const float w0 = W_lepe[c * 3 + 0];
    const float w1 = W_lepe[c * 3 + 1];
    const float w2 = W_lepe[c * 3 + 2];
    const float bl = b_lepe[c];

    const size_t rowbase = (size_t)(b * NN + n0) * QKVO_COLS;   // row n0
    // rolling v values: vp = v[n0-1], vc = v[n0]
    float vp = (n0 > 0) ? qkvo[rowbase - QKVO_COLS + 512 + c] : 0.f;
    float vc = qkvo[rowbase + 512 + c];

    const float* kvh = &skv[h * HD * HD];

#pragma unroll 1
    for (int g = 0; g < TILE_ROWS; g += RG) {
        const size_t r0 = rowbase + (size_t)g * QKVO_COLS;

        // ---- front-batched loads: v[g+1..g+4], q[0..3], o[0..3] ----
        float vn[RG];                 // vn[i] = v[n0+g+1+i]
#pragma unroll
        for (int i = 0; i < RG - 1; i++)
            vn[i] = qkvo[r0 + (size_t)(i + 1) * QKVO_COLS + 512 + c];
        vn[RG - 1] = (n0 + g + RG < NN)
                   ? qkvo[r0 + (size_t)RG * QKVO_COLS + 512 + c] : 0.f;

        float qv[RG], ov[RG];
#pragma unroll
        for (int i = 0; i < RG; i++) {
            qv[i] = qkvo[r0 + (size_t)i * QKVO_COLS + c];
            ov[i] = qkvo[r0 + (size_t)i * QKVO_COLS + 768 + c];
        }

        // ---- elu+1 ----
        float qh[RG];
#pragma unroll
        for (int i = 0; i < RG; i++)
            qh[i] = (qv[i] > 0.f) ? (qv[i] + 1.f) : __expf(qv[i]);

        // ---- z reductions (4 interleaved shfl chains) ----
        float zp[RG];
#pragma unroll
        for (int i = 0; i < RG; i++) zp[i] = qh[i] * km;
#pragma unroll
        for (int off = 16; off > 0; off >>= 1) {
#pragma unroll
            for (int i = 0; i < RG; i++)
                zp[i] += __shfl_xor_sync(0xffffffffu, zp[i], off);
        }

        // ---- theta shift ----
        float qs[RG];
#pragma unroll
        for (int i = 0; i < RG; i++) {
            float partner = __shfl_xor_sync(0xffffffffu, qh[i], 1);
            float sv = sinp[(n0 + g + i) * HD + d];
            float cv = cosp[(n0 + g + i) * HD + d];
            float rot = (d & 1) ? partner : -partner;
            qs[i] = qh[i] * cv + rot * sv;
        }

        // ---- matvec: 4 independent accumulator chains share each kv LDS ----
        float acc[RG];
#pragma unroll
        for (int i = 0; i < RG; i++) acc[i] = 0.f;
#pragma unroll
        for (int dd = 0; dd < 32; dd++) {
            float kvv = kvh[dd * HD + d];
#pragma unroll
            for (int i = 0; i < RG; i++)
                acc[i] += __shfl_sync(0xffffffffu, qs[i], dd) * kvv;
        }

        // ---- epilogue ----
#pragma unroll
        for (int i = 0; i < RG; i++) {
            float z = zp[i] * inv_scale_n;
            float coef = 1.f + 1.f / (z + 1e-6f);
            float prev = (i == 0) ? vp : ((i == 1) ? vc : vn[i - 2]);
            float cur  = (i == 0) ? vc : vn[i - 1];
            float next = vn[i];
            float res  = acc[i] * coef - z * vm;
            float lepe = prev * w0 + cur * w1 + next * w2 + bl;
            ph[(size_t)(b * NN + n0 + g + i) * INTERNAL + c] =
                __float2half((res + lepe) * ov[i]);
        }

        vp = vn[RG - 2];
        vc = vn[RG - 1];
    }
}

// ---------------- launch -----------------------------------------------------
extern "C" void kernel_launch(void* const* d_in, const int* in_sizes, int n_in,
                              void* d_out, int out_size)
{
    const float* x       = (const float*)d_in[0];
    const float* sinp    = (const float*)d_in[1];
    const float* cosp    = (const float*)d_in[2];
    const float* W_qkvo  = (const float*)d_in[3];
    const float* b_qkvo  = (const float*)d_in[4];
    const float* W_lepe  = (const float*)d_in[5];
    const float* b_lepe  = (const float*)d_in[6];
    const float* W_proj  = (const float*)d_in[7];
    const float* b_proj  = (const float*)d_in[8];
    float* out = (float*)d_out;

    float *qkvo_p;
    __half *xh, *ph, *wqh, *pwh;
    cudaGetSymbolAddress((void**)&qkvo_p, g_qkvo);
    cudaGetSymbolAddress((void**)&xh,  g_xh);
    cudaGetSymbolAddress((void**)&ph,  g_ph);
    cudaGetSymbolAddress((void**)&wqh, g_wqh);
    cudaGetSymbolAddress((void**)&pwh, g_pwh);

    cudaFuncSetAttribute(gemm_h_kernel,
                         cudaFuncAttributeMaxDynamicSharedMemorySize, GEMM_SMEM_BYTES);

    zero_kernel<<<(BB * HH * HD * HD + 255) / 256, 256>>>();

    cvt_all_kernel<<<(CVT_N1 + CVT_N2 + CVT_N3 + 255) / 256, 256>>>(
        x, W_qkvo, W_proj, xh, wqh, pwh);

    // GEMM1: qkvo = x @ W_qkvo^T + b_qkvo   [32768 x 1024]
    gemm_h_kernel<<<dim3(QKVO_COLS / 128, MROWS / 128), 256, GEMM_SMEM_BYTES>>>(
        xh, wqh, b_qkvo, qkvo_p, MROWS, QKVO_COLS, DIMV);

    stats_kernel<<<dim3(BB * HH, 32), 256>>>(qkvo_p, sinp, cosp);

    fuse_kernel<<<BB * (NN / TILE_ROWS), 256>>>(qkvo_p, sinp, cosp,
                                                W_lepe, b_lepe, ph);

    // GEMM2: out = pre @ W_proj^T + b_proj  [32768 x 256]
    gemm_h_kernel<<<dim3(INTERNAL / 128, MROWS / 128), 256, GEMM_SMEM_BYTES>>>(
        ph, pwh, b_proj, out, MROWS, INTERNAL, DIMV);
}

// round 10
// speedup vs baseline: 2.3600x; 1.0507x over previous
#include <cuda_runtime.h>
#include <cuda_fp16.h>
#include <math.h>
#include <stdint.h>

#define BB 4
#define NN 8192
#define DIMV 256
#define HH 8
#define HD 32
#define INTERNAL 256
#define MROWS (BB * NN)        // 32768
#define QKVO_COLS 1024
#define SCALE_F 0.17677669529663687f

// ---------------- persistent device scratch (no allocations) ----------------
__device__ float  g_qkvo[(size_t)MROWS * QKVO_COLS];    // 134 MB fp32
__device__ __half g_xh [(size_t)MROWS * DIMV];
__device__ __half g_ph [(size_t)MROWS * INTERNAL];
__device__ __half g_wqh[(size_t)QKVO_COLS * DIMV];
__device__ __half g_pwh[(size_t)DIMV * INTERNAL];
__device__ float g_kv  [BB * HH * HD * HD];
__device__ float g_ksum[BB * HH * HD];
__device__ float g_vsum[BB * HH * HD];

__device__ __forceinline__ uint32_t smem_u32(const void* p) {
    uint32_t a;
    asm("{ .reg .u64 t; cvta.to.shared.u64 t, %1; cvt.u32.u64 %0, t; }"
        : "=r"(a) : "l"(p));
    return a;
}

__device__ __forceinline__ void ldmx4(uint32_t* r, uint32_t addr) {
    asm volatile("ldmatrix.sync.aligned.m8n8.x4.shared.b16 {%0,%1,%2,%3}, [%4];"
        : "=r"(r[0]), "=r"(r[1]), "=r"(r[2]), "=r"(r[3]) : "r"(addr));
}

__device__ __forceinline__ void mma16816h(float* d, const uint32_t* a,
                                          uint32_t b0, uint32_t b1) {
    asm volatile(
        "mma.sync.aligned.m16n8k16.row.col.f32.f16.f16.f32 "
        "{%0,%1,%2,%3}, {%4,%5,%6,%7}, {%8,%9}, {%0,%1,%2,%3};"
        : "+f"(d[0]), "+f"(d[1]), "+f"(d[2]), "+f"(d[3])
        : "r"(a[0]), "r"(a[1]), "r"(a[2]), "r"(a[3]), "r"(b0), "r"(b1));
}

__device__ __forceinline__ void cp16(uint32_t saddr, const void* gaddr) {
    asm volatile("cp.async.cg.shared.global [%0], [%1], 16;"
        :: "r"(saddr), "l"(gaddr) : "memory");
}
#define CP_COMMIT() asm volatile("cp.async.commit_group;" ::: "memory")
#define CP_WAIT(n)  asm volatile("cp.async.wait_group %0;" :: "n"(n) : "memory")

// ---------------- fused fp32 -> fp16 conversion (one launch) ----------------
#define CVT_N1 (MROWS * DIMV / 4)
#define CVT_N2 (QKVO_COLS * DIMV / 4)
#define CVT_N3 (DIMV * INTERNAL / 4)
__global__ void __launch_bounds__(256)
cvt_all_kernel(const float* __restrict__ x, const float* __restrict__ wq,
               const float* __restrict__ pw, __half* __restrict__ xh,
               __half* __restrict__ wqh, __half* __restrict__ pwh)
{
    int i = blockIdx.x * 256 + threadIdx.x;
    const float* s; __half* d; int j;
    if (i < CVT_N1) { s = x; d = xh; j = i; }
    else if (i < CVT_N1 + CVT_N2) { s = wq; d = wqh; j = i - CVT_N1; }
    else if (i < CVT_N1 + CVT_N2 + CVT_N3) { s = pw; d = pwh; j = i - CVT_N1 - CVT_N2; }
    else return;
    float4 v = ((const float4*)s)[j];
    __half2 h0 = __floats2half2_rn(v.x, v.y);
    __half2 h1 = __floats2half2_rn(v.z, v.w);
    uint2 o = { *reinterpret_cast<uint32_t*>(&h0), *reinterpret_cast<uint32_t*>(&h1) };
    ((uint2*)d)[j] = o;
}

// =================== HMMA GEMM (single fp16, 4-stage cp.async) ==============
#define ROWB 80
#define ST_A 0
#define ST_B 10240
#define STAGEB 20480
#define NSTAGE 4
#define GEMM_SMEM_BYTES (NSTAGE * STAGEB)   // 80 KB

__global__ void __launch_bounds__(256)
gemm_h_kernel(const __half* __restrict__ A, const __half* __restrict__ Bw,
              const float* __restrict__ bias, float* __restrict__ C,
              int M, int Nn, int K)
{
    extern __shared__ char sm[];
    const uint32_t smb = smem_u32(sm);
    const int tid  = threadIdx.x;
    const int wid  = tid >> 5;
    const int lane = tid & 31;
    const int m0 = blockIdx.y * 128;
    const int n0 = blockIdx.x * 128;
    const int wm0 = (wid & 3) * 32;
    const int wn0 = (wid >> 2) * 64;

    const int a_row = (lane & 7) + ((lane >> 3) & 1) * 8;
    const int a_kh  = (lane >> 4) * 8;
    const int b_row = (lane & 7) + ((lane >> 4) & 1) * 8;
    const int b_kh  = ((lane >> 3) & 1) * 8;

    float acc[2][8][4];
#pragma unroll
    for (int i = 0; i < 2; i++)
#pragma unroll
        for (int j = 0; j < 8; j++)
#pragma unroll
            for (int l = 0; l < 4; l++) acc[i][j][l] = 0.f;

    const int NCH = K / 32;
    const int row2 = tid >> 2;
    const int seg  = tid & 3;

#define LOAD_STAGE(c, buf) do {                                              \
    int k0 = (c) * 32;                                                       \
    uint32_t base = smb + (buf) * STAGEB;                                    \
    _Pragma("unroll")                                                        \
    for (int i = 0; i < 2; i++) {                                            \
        int r = row2 + i * 64;                                               \
        uint32_t so = r * ROWB + seg * 16;                                   \
        cp16(base + ST_A + so, A  + (size_t)(m0 + r) * K + k0 + seg * 8);    \
        cp16(base + ST_B + so, Bw + (size_t)(n0 + r) * K + k0 + seg * 8);    \
    }                                                                        \
    CP_COMMIT();                                                             \
} while (0)

    LOAD_STAGE(0, 0);
    LOAD_STAGE(1, 1);
    LOAD_STAGE(2, 2);

    for (int c = 0; c < NCH; c++) {
        CP_WAIT(2);
        __syncthreads();
        const uint32_t base = smb + (c & (NSTAGE - 1)) * STAGEB;

#pragma unroll
        for (int ks = 0; ks < 2; ks++) {
            uint32_t af[2][4], bf[4][4];
#pragma unroll
            for (int mf = 0; mf < 2; mf++)
                ldmx4(af[mf], base + ST_A + (wm0 + mf * 16 + a_row) * ROWB
                                        + (ks * 16 + a_kh) * 2);
#pragma unroll
            for (int nf2 = 0; nf2 < 4; nf2++)
                ldmx4(bf[nf2], base + ST_B + (wn0 + nf2 * 16 + b_row) * ROWB
                                          + (ks * 16 + b_kh) * 2);
#pragma unroll
            for (int nf2 = 0; nf2 < 4; nf2++)
#pragma unroll
                for (int mf = 0; mf < 2; mf++)
#pragma unroll
                    for (int s = 0; s < 2; s++)
                        mma16816h(acc[mf][nf2 * 2 + s], af[mf],
                                  bf[nf2][s * 2], bf[nf2][s * 2 + 1]);
        }
        __syncthreads();
        if (c + 3 < NCH) LOAD_STAGE(c + 3, (c + 3) & (NSTAGE - 1));
        else CP_COMMIT();
    }
#undef LOAD_STAGE

    const int rr = lane >> 2;
    const int cc = (lane & 3) * 2;
#pragma unroll
    for (int mf = 0; mf < 2; mf++) {
        int r0 = m0 + wm0 + mf * 16 + rr;
#pragma unroll
        for (int nf = 0; nf < 8; nf++) {
            int col = n0 + wn0 + nf * 8 + cc;
            float b0 = bias[col], b1 = bias[col + 1];
            float2 v0 = {acc[mf][nf][0] + b0, acc[mf][nf][1] + b1};
            float2 v1 = {acc[mf][nf][2] + b0, acc[mf][nf][3] + b1};
            *(float2*)&C[(size_t)r0 * Nn + col] = v0;
            *(float2*)&C[(size_t)(r0 + 8) * Nn + col] = v1;
        }
    }
}

// ---------------- zero accumulators ----------------------------------------
__global__ void zero_kernel() {
    int i = blockIdx.x * 256 + threadIdx.x;
    if (i < BB * HH * HD * HD) g_kv[i] = 0.f;
    if (i < BB * HH * HD) { g_ksum[i] = 0.f; g_vsum[i] = 0.f; }
}

// ---------------- stats v2: 32-row chunks, front-batched loads --------------
// grid (32 bh, 32 splits), 256 threads. Warp w produces rows w*4..w*4+3.
__global__ void __launch_bounds__(256)
stats_kernel(const float* __restrict__ qkvo,
             const float* __restrict__ sinp, const float* __restrict__ cosp)
{
    __shared__ float sks[32][32];
    __shared__ float svh[32][32];

    const int bh = blockIdx.x;          // 0..31
    const int split = blockIdx.y;       // 0..31
    const int b = bh >> 3, h = bh & 7;
    const int w = threadIdx.x >> 5;
    const int lane = threadIdx.x & 31;
    const int n_start = split * (NN / 32);   // 256 rows per split

    const int dA = threadIdx.x >> 3;        // kv row   0..31
    const int e4 = (threadIdx.x & 7) * 4;   // kv col base

    float kv0 = 0.f, kv1 = 0.f, kv2 = 0.f, kv3 = 0.f;
    float ksum_acc = 0.f, vsum_acc = 0.f;

    for (int c0 = 0; c0 < NN / 32; c0 += 32) {
        const int nb = n_start + c0 + w * 4;         // this warp's 4 rows
        // ---- front-batched global loads (MLP ~16) ----
        float kraw[4], vv[4], sv[4], cv[4];
#pragma unroll
        for (int i = 0; i < 4; i++) {
            size_t row = (size_t)(b * NN + nb + i) * QKVO_COLS;
            kraw[i] = qkvo[row + 256 + h * 32 + lane];
            vv[i]   = qkvo[row + 512 + h * 32 + lane];
        }
#pragma unroll
        for (int i = 0; i < 4; i++) {
            sv[i] = sinp[(nb + i) * HD + lane];
            cv[i] = cosp[(nb + i) * HD + lane];
        }
        // ---- elu+1, theta shift, stage to smem ----
#pragma unroll
        for (int i = 0; i < 4; i++) {
            float kh = (kraw[i] > 0.f) ? (kraw[i] + 1.f) : __expf(kraw[i]);
            ksum_acc += kh;
            vsum_acc += vv[i];
            float partner = __shfl_xor_sync(0xffffffffu, kh, 1);
            float rot = (lane & 1) ? partner : -partner;
            sks[w * 4 + i][lane] = kh * cv[i] + rot * sv[i];
            svh[w * 4 + i][lane] = vv[i];
        }
        __syncthreads();
        // ---- accumulate 32 outer products ----
#pragma unroll
        for (int j = 0; j < 32; j++) {
            float a = sks[j][dA];
            float4 v4 = *(const float4*)&svh[j][e4];
            kv0 += a * v4.x;
            kv1 += a * v4.y;
            kv2 += a * v4.z;
            kv3 += a * v4.w;
        }
        __syncthreads();
    }

    float* kvdst = &g_kv[bh * (HD * HD) + dA * HD + e4];
    atomicAdd(kvdst + 0, kv0);
    atomicAdd(kvdst + 1, kv1);
    atomicAdd(kvdst + 2, kv2);
    atomicAdd(kvdst + 3, kv3);
    atomicAdd(&g_ksum[bh * HD + lane], ksum_acc);
    atomicAdd(&g_vsum[bh * HD + lane], vsum_acc);
}

// ---------------- fused per-token epilogue (4-row ILP) -> fp16 pre ----------
#define TILE_ROWS 64
#define RG 4
__global__ void __launch_bounds__(256)
fuse_kernel(const float* __restrict__ qkvo,
            const float* __restrict__ sinp, const float* __restrict__ cosp,
            const float* __restrict__ W_lepe, const float* __restrict__ b_lepe,
            __half* __restrict__ ph)
{
    __shared__ float skv[HH * HD * HD];

    const int tile = blockIdx.x;
    const int b  = tile / (NN / TILE_ROWS);
    const int t  = tile % (NN / TILE_ROWS);
    const int n0 = t * TILE_ROWS;
    const int c  = threadIdx.x;
    const int h  = c >> 5;
    const int d  = c & 31;
    const float inv_scale_n = SCALE_F / (float)NN;

    const int base_kv = b * HH * HD * HD;
#pragma unroll
    for (int i = 0; i < HH * HD * HD / 256; i++)
        skv[i * 256 + c] = g_kv[base_kv + i * 256 + c] * inv_scale_n;

    const float km = g_ksum[(b * HH + h) * HD + d];
    const float vm = g_vsum[(b * HH + h) * HD + d] * (1.f / NN);
    __syncthreads();

    const float w0 = W_lepe[c * 3 + 0];
    const float w1 = W_lepe[c * 3 + 1];
    const float w2 = W_lepe[c * 3 + 2];
    const float bl = b_lepe[c];

    const size_t rowbase = (size_t)(b * NN + n0) * QKVO_COLS;
    float vp = (n0 > 0) ? qkvo[rowbase - QKVO_COLS + 512 + c] : 0.f;
    float vc = qkvo[rowbase + 512 + c];

    const float* kvh = &skv[h * HD * HD];

#pragma unroll 1
    for (int g = 0; g < TILE_ROWS; g += RG) {
        const size_t r0 = rowbase + (size_t)g * QKVO_COLS;

        float vn[RG];
#pragma unroll
        for (int i = 0; i < RG - 1; i++)
            vn[i] = qkvo[r0 + (size_t)(i + 1) * QKVO_COLS + 512 + c];
        vn[RG - 1] = (n0 + g + RG < NN)
                   ? qkvo[r0 + (size_t)RG * QKVO_COLS + 512 + c] : 0.f;

        float qv[RG], ov[RG];
#pragma unroll
        for (int i = 0; i < RG; i++) {
            qv[i] = qkvo[r0 + (size_t)i * QKVO_COLS + c];
            ov[i] = qkvo[r0 + (size_t)i * QKVO_COLS + 768 + c];
        }

        float qh[RG];
#pragma unroll
        for (int i = 0; i < RG; i++)
            qh[i] = (qv[i] > 0.f) ? (qv[i] + 1.f) : __expf(qv[i]);

        float zp[RG];
#pragma unroll
        for (int i = 0; i < RG; i++) zp[i] = qh[i] * km;
#pragma unroll
        for (int off = 16; off > 0; off >>= 1) {
#pragma unroll
            for (int i = 0; i < RG; i++)
                zp[i] += __shfl_xor_sync(0xffffffffu, zp[i], off);
        }

        float qs[RG];
#pragma unroll
        for (int i = 0; i < RG; i++) {
            float partner = __shfl_xor_sync(0xffffffffu, qh[i], 1);
            float sv = sinp[(n0 + g + i) * HD + d];
            float cv = cosp[(n0 + g + i) * HD + d];
            float rot = (d & 1) ? partner : -partner;
            qs[i] = qh[i] * cv + rot * sv;
        }

        float acc[RG];
#pragma unroll
        for (int i = 0; i < RG; i++) acc[i] = 0.f;
#pragma unroll
        for (int dd = 0; dd < 32; dd++) {
            float kvv = kvh[dd * HD + d];
#pragma unroll
            for (int i = 0; i < RG; i++)
                acc[i] += __shfl_sync(0xffffffffu, qs[i], dd) * kvv;
        }

#pragma unroll
        for (int i = 0; i < RG; i++) {
            float z = zp[i] * inv_scale_n;
            float coef = 1.f + 1.f / (z + 1e-6f);
            float prev = (i == 0) ? vp : ((i == 1) ? vc : vn[i - 2]);
            float cur  = (i == 0) ? vc : vn[i - 1];
            float next = vn[i];
            float res  = acc[i] * coef - z * vm;
            float lepe = prev * w0 + cur * w1 + next * w2 + bl;
            ph[(size_t)(b * NN + n0 + g + i) * INTERNAL + c] =
                __float2half((res + lepe) * ov[i]);
        }

        vp = vn[RG - 2];
        vc = vn[RG - 1];
    }
}

// ---------------- launch -----------------------------------------------------
extern "C" void kernel_launch(void* const* d_in, const int* in_sizes, int n_in,
                              void* d_out, int out_size)
{
    const float* x       = (const float*)d_in[0];
    const float* sinp    = (const float*)d_in[1];
    const float* cosp    = (const float*)d_in[2];
    const float* W_qkvo  = (const float*)d_in[3];
    const float* b_qkvo  = (const float*)d_in[4];
    const float* W_lepe  = (const float*)d_in[5];
    const float* b_lepe  = (const float*)d_in[6];
    const float* W_proj  = (const float*)d_in[7];
    const float* b_proj  = (const float*)d_in[8];
    float* out = (float*)d_out;

    float *qkvo_p;
    __half *xh, *ph, *wqh, *pwh;
    cudaGetSymbolAddress((void**)&qkvo_p, g_qkvo);
    cudaGetSymbolAddress((void**)&xh,  g_xh);
    cudaGetSymbolAddress((void**)&ph,  g_ph);
    cudaGetSymbolAddress((void**)&wqh, g_wqh);
    cudaGetSymbolAddress((void**)&pwh, g_pwh);

    cudaFuncSetAttribute(gemm_h_kernel,
                         cudaFuncAttributeMaxDynamicSharedMemorySize, GEMM_SMEM_BYTES);

    zero_kernel<<<(BB * HH * HD * HD + 255) / 256, 256>>>();

    cvt_all_kernel<<<(CVT_N1 + CVT_N2 + CVT_N3 + 255) / 256, 256>>>(
        x, W_qkvo, W_proj, xh, wqh, pwh);

    // GEMM1: qkvo = x @ W_qkvo^T + b_qkvo   [32768 x 1024]
    gemm_h_kernel<<<dim3(QKVO_COLS / 128, MROWS / 128), 256, GEMM_SMEM_BYTES>>>(
        xh, wqh, b_qkvo, qkvo_p, MROWS, QKVO_COLS, DIMV);

    stats_kernel<<<dim3(BB * HH, 32), 256>>>(qkvo_p, sinp, cosp);

    fuse_kernel<<<BB * (NN / TILE_ROWS), 256>>>(qkvo_p, sinp, cosp,
                                                W_lepe, b_lepe, ph);

    // GEMM2: out = pre @ W_proj^T + b_proj  [32768 x 256]
    gemm_h_kernel<<<dim3(INTERNAL / 128, MROWS / 128), 256, GEMM_SMEM_BYTES>>>(
        ph, pwh, b_proj, out, MROWS, INTERNAL, DIMV);
}

// round 11
// speedup vs baseline: 2.4439x; 1.0356x over previous
#include <cuda_runtime.h>
#include <cuda_fp16.h>
#include <math.h>
#include <stdint.h>

#define BB 4
#define NN 8192
#define DIMV 256
#define HH 8
#define HD 32
#define INTERNAL 256
#define MROWS (BB * NN)        // 32768
#define QKVO_COLS 1024
#define SCALE_F 0.17677669529663687f

// ---------------- persistent device scratch (no allocations) ----------------
__device__ __half g_qkvo[(size_t)MROWS * QKVO_COLS];    // 67 MB fp16
__device__ __half g_xh [(size_t)MROWS * DIMV];
__device__ __half g_ph [(size_t)MROWS * INTERNAL];
__device__ __half g_wqh[(size_t)QKVO_COLS * DIMV];
__device__ __half g_pwh[(size_t)DIMV * INTERNAL];
__device__ float g_kv  [BB * HH * HD * HD];
__device__ float g_ksum[BB * HH * HD];
__device__ float g_vsum[BB * HH * HD];

__device__ __forceinline__ uint32_t smem_u32(const void* p) {
    uint32_t a;
    asm("{ .reg .u64 t; cvta.to.shared.u64 t, %1; cvt.u32.u64 %0, t; }"
        : "=r"(a) : "l"(p));
    return a;
}

__device__ __forceinline__ void ldmx4(uint32_t* r, uint32_t addr) {
    asm volatile("ldmatrix.sync.aligned.m8n8.x4.shared.b16 {%0,%1,%2,%3}, [%4];"
        : "=r"(r[0]), "=r"(r[1]), "=r"(r[2]), "=r"(r[3]) : "r"(addr));
}

__device__ __forceinline__ void mma16816h(float* d, const uint32_t* a,
                                          uint32_t b0, uint32_t b1) {
    asm volatile(
        "mma.sync.aligned.m16n8k16.row.col.f32.f16.f16.f32 "
        "{%0,%1,%2,%3}, {%4,%5,%6,%7}, {%8,%9}, {%0,%1,%2,%3};"
        : "+f"(d[0]), "+f"(d[1]), "+f"(d[2]), "+f"(d[3])
        : "r"(a[0]), "r"(a[1]), "r"(a[2]), "r"(a[3]), "r"(b0), "r"(b1));
}

__device__ __forceinline__ void cp16(uint32_t saddr, const void* gaddr) {
    asm volatile("cp.async.cg.shared.global [%0], [%1], 16;"
        :: "r"(saddr), "l"(gaddr) : "memory");
}
#define CP_COMMIT() asm volatile("cp.async.commit_group;" ::: "memory")
#define CP_WAIT(n)  asm volatile("cp.async.wait_group %0;" :: "n"(n) : "memory")

// ---------------- fused fp32 -> fp16 conversion (one launch) ----------------
#define CVT_N1 (MROWS * DIMV / 4)
#define CVT_N2 (QKVO_COLS * DIMV / 4)
#define CVT_N3 (DIMV * INTERNAL / 4)
__global__ void __launch_bounds__(256)
cvt_all_kernel(const float* __restrict__ x, const float* __restrict__ wq,
               const float* __restrict__ pw, __half* __restrict__ xh,
               __half* __restrict__ wqh, __half* __restrict__ pwh)
{
    int i = blockIdx.x * 256 + threadIdx.x;
    const float* s; __half* d; int j;
    if (i < CVT_N1) { s = x; d = xh; j = i; }
    else if (i < CVT_N1 + CVT_N2) { s = wq; d = wqh; j = i - CVT_N1; }
    else if (i < CVT_N1 + CVT_N2 + CVT_N3) { s = pw; d = pwh; j = i - CVT_N1 - CVT_N2; }
    else return;
    float4 v = ((const float4*)s)[j];
    __half2 h0 = __floats2half2_rn(v.x, v.y);
    __half2 h1 = __floats2half2_rn(v.z, v.w);
    uint2 o = { *reinterpret_cast<uint32_t*>(&h0), *reinterpret_cast<uint32_t*>(&h1) };
    ((uint2*)d)[j] = o;
}

// =================== HMMA GEMM (single fp16, 4-stage cp.async) ==============
// Output type templated: __half for qkvo intermediate, float for final out.
#define ROWB 80
#define ST_A 0
#define ST_B 10240
#define STAGEB 20480
#define NSTAGE 4
#define GEMM_SMEM_BYTES (NSTAGE * STAGEB)   // 80 KB

template <typename OutT>
__global__ void __launch_bounds__(256)
gemm_h_kernel(const __half* __restrict__ A, const __half* __restrict__ Bw,
              const float* __restrict__ bias, OutT* __restrict__ C,
              int M, int Nn, int K)
{
    extern __shared__ char sm[];
    const uint32_t smb = smem_u32(sm);
    const int tid  = threadIdx.x;
    const int wid  = tid >> 5;
    const int lane = tid & 31;
    const int m0 = blockIdx.y * 128;
    const int n0 = blockIdx.x * 128;
    const int wm0 = (wid & 3) * 32;
    const int wn0 = (wid >> 2) * 64;

    const int a_row = (lane & 7) + ((lane >> 3) & 1) * 8;
    const int a_kh  = (lane >> 4) * 8;
    const int b_row = (lane & 7) + ((lane >> 4) & 1) * 8;
    const int b_kh  = ((lane >> 3) & 1) * 8;

    float acc[2][8][4];
#pragma unroll
    for (int i = 0; i < 2; i++)
#pragma unroll
        for (int j = 0; j < 8; j++)
#pragma unroll
            for (int l = 0; l < 4; l++) acc[i][j][l] = 0.f;

    const int NCH = K / 32;
    const int row2 = tid >> 2;
    const int seg  = tid & 3;

#define LOAD_STAGE(c, buf) do {                                              \
    int k0 = (c) * 32;                                                       \
    uint32_t base = smb + (buf) * STAGEB;                                    \
    _Pragma("unroll")                                                        \
    for (int i = 0; i < 2; i++) {                                            \
        int r = row2 + i * 64;                                               \
        uint32_t so = r * ROWB + seg * 16;                                   \
        cp16(base + ST_A + so, A  + (size_t)(m0 + r) * K + k0 + seg * 8);    \
        cp16(base + ST_B + so, Bw + (size_t)(n0 + r) * K + k0 + seg * 8);    \
    }                                                                        \
    CP_COMMIT();                                                             \
} while (0)

    LOAD_STAGE(0, 0);
    LOAD_STAGE(1, 1);
    LOAD_STAGE(2, 2);

    for (int c = 0; c < NCH; c++) {
        CP_WAIT(2);
        __syncthreads();
        const uint32_t base = smb + (c & (NSTAGE - 1)) * STAGEB;

#pragma unroll
        for (int ks = 0; ks < 2; ks++) {
            uint32_t af[2][4], bf[4][4];
#pragma unroll
            for (int mf = 0; mf < 2; mf++)
                ldmx4(af[mf], base + ST_A + (wm0 + mf * 16 + a_row) * ROWB
                                        + (ks * 16 + a_kh) * 2);
#pragma unroll
            for (int nf2 = 0; nf2 < 4; nf2++)
                ldmx4(bf[nf2], base + ST_B + (wn0 + nf2 * 16 + b_row) * ROWB
                                          + (ks * 16 + b_kh) * 2);
#pragma unroll
            for (int nf2 = 0; nf2 < 4; nf2++)
#pragma unroll
                for (int mf = 0; mf < 2; mf++)
#pragma unroll
                    for (int s = 0; s < 2; s++)
                        mma16816h(acc[mf][nf2 * 2 + s], af[mf],
                                  bf[nf2][s * 2], bf[nf2][s * 2 + 1]);
        }
        __syncthreads();
        if (c + 3 < NCH) LOAD_STAGE(c + 3, (c + 3) & (NSTAGE - 1));
        else CP_COMMIT();
    }
#undef LOAD_STAGE

    const int rr = lane >> 2;
    const int cc = (lane & 3) * 2;
#pragma unroll
    for (int mf = 0; mf < 2; mf++) {
        int r0 = m0 + wm0 + mf * 16 + rr;
#pragma unroll
        for (int nf = 0; nf < 8; nf++) {
            int col = n0 + wn0 + nf * 8 + cc;
            float b0 = bias[col], b1 = bias[col + 1];
            float o00 = acc[mf][nf][0] + b0, o01 = acc[mf][nf][1] + b1;
            float o10 = acc[mf][nf][2] + b0, o11 = acc[mf][nf][3] + b1;
            if (sizeof(OutT) == 2) {
                __half2 p0 = __floats2half2_rn(o00, o01);
                __half2 p1 = __floats2half2_rn(o10, o11);
                *(__half2*)&C[(size_t)r0 * Nn + col] = p0;
                *(__half2*)&C[(size_t)(r0 + 8) * Nn + col] = p1;
            } else {
                float2 v0 = {o00, o01}, v1 = {o10, o11};
                *(float2*)&C[(size_t)r0 * Nn + col] = v0;
                *(float2*)&C[(size_t)(r0 + 8) * Nn + col] = v1;
            }
        }
    }
}

// ---------------- zero accumulators ----------------------------------------
__global__ void zero_kernel() {
    int i = blockIdx.x * 256 + threadIdx.x;
    if (i < BB * HH * HD * HD) g_kv[i] = 0.f;
    if (i < BB * HH * HD) { g_ksum[i] = 0.f; g_vsum[i] = 0.f; }
}

// ---------------- stats v3: fp16 qkvo, 32-row chunks ------------------------
__global__ void __launch_bounds__(256)
stats_kernel(const __half* __restrict__ qkvo,
             const float* __restrict__ sinp, const float* __restrict__ cosp)
{
    __shared__ float sks[32][32];
    __shared__ float svh[32][32];

    const int bh = blockIdx.x;
    const int split = blockIdx.y;
    const int b = bh >> 3, h = bh & 7;
    const int w = threadIdx.x >> 5;
    const int lane = threadIdx.x & 31;
    const int n_start = split * (NN / 32);

    const int dA = threadIdx.x >> 3;
    const int e4 = (threadIdx.x & 7) * 4;

    float kv0 = 0.f, kv1 = 0.f, kv2 = 0.f, kv3 = 0.f;
    float ksum_acc = 0.f, vsum_acc = 0.f;

    for (int c0 = 0; c0 < NN / 32; c0 += 32) {
        const int nb = n_start + c0 + w * 4;
        float kraw[4], vv[4], sv[4], cv[4];
#pragma unroll
        for (int i = 0; i < 4; i++) {
            size_t row = (size_t)(b * NN + nb + i) * QKVO_COLS;
            kraw[i] = __half2float(qkvo[row + 256 + h * 32 + lane]);
            vv[i]   = __half2float(qkvo[row + 512 + h * 32 + lane]);
        }
#pragma unroll
        for (int i = 0; i < 4; i++) {
            sv[i] = sinp[(nb + i) * HD + lane];
            cv[i] = cosp[(nb + i) * HD + lane];
        }
#pragma unroll
        for (int i = 0; i < 4; i++) {
            float kh = (kraw[i] > 0.f) ? (kraw[i] + 1.f) : __expf(kraw[i]);
            ksum_acc += kh;
            vsum_acc += vv[i];
            float partner = __shfl_xor_sync(0xffffffffu, kh, 1);
            float rot = (lane & 1) ? partner : -partner;
            sks[w * 4 + i][lane] = kh * cv[i] + rot * sv[i];
            svh[w * 4 + i][lane] = vv[i];
        }
        __syncthreads();
#pragma unroll
        for (int j = 0; j < 32; j++) {
            float a = sks[j][dA];
            float4 v4 = *(const float4*)&svh[j][e4];
            kv0 += a * v4.x;
            kv1 += a * v4.y;
            kv2 += a * v4.z;
            kv3 += a * v4.w;
        }
        __syncthreads();
    }

    float* kvdst = &g_kv[bh * (HD * HD) + dA * HD + e4];
    atomicAdd(kvdst + 0, kv0);
    atomicAdd(kvdst + 1, kv1);
    atomicAdd(kvdst + 2, kv2);
    atomicAdd(kvdst + 3, kv3);
    atomicAdd(&g_ksum[bh * HD + lane], ksum_acc);
    atomicAdd(&g_vsum[bh * HD + lane], vsum_acc);
}

// ---------------- fused per-token epilogue (4-row ILP, fp16 qkvo) -----------
#define TILE_ROWS 64
#define RG 4
__global__ void __launch_bounds__(256)
fuse_kernel(const __half* __restrict__ qkvo,
            const float* __restrict__ sinp, const float* __restrict__ cosp,
            const float* __restrict__ W_lepe, const float* __restrict__ b_lepe,
            __half* __restrict__ ph)
{
    __shared__ float skv[HH * HD * HD];

    const int tile = blockIdx.x;
    const int b  = tile / (NN / TILE_ROWS);
    const int t  = tile % (NN / TILE_ROWS);
    const int n0 = t * TILE_ROWS;
    const int c  = threadIdx.x;
    const int h  = c >> 5;
    const int d  = c & 31;
    const float inv_scale_n = SCALE_F / (float)NN;

    const int base_kv = b * HH * HD * HD;
#pragma unroll
    for (int i = 0; i < HH * HD * HD / 256; i++)
        skv[i * 256 + c] = g_kv[base_kv + i * 256 + c] * inv_scale_n;

    const float km = g_ksum[(b * HH + h) * HD + d];
    const float vm = g_vsum[(b * HH + h) * HD + d] * (1.f / NN);
    __syncthreads();

    const float w0 = W_lepe[c * 3 + 0];
    const float w1 = W_lepe[c * 3 + 1];
    const float w2 = W_lepe[c * 3 + 2];
    const float bl = b_lepe[c];

    const size_t rowbase = (size_t)(b * NN + n0) * QKVO_COLS;
    float vp = (n0 > 0) ? __half2float(qkvo[rowbase - QKVO_COLS + 512 + c]) : 0.f;
    float vc = __half2float(qkvo[rowbase + 512 + c]);

    const float* kvh = &skv[h * HD * HD];

#pragma unroll 1
    for (int g = 0; g < TILE_ROWS; g += RG) {
        const size_t r0 = rowbase + (size_t)g * QKVO_COLS;

        float vn[RG];
#pragma unroll
        for (int i = 0; i < RG - 1; i++)
            vn[i] = __half2float(qkvo[r0 + (size_t)(i + 1) * QKVO_COLS + 512 + c]);
        vn[RG - 1] = (n0 + g + RG < NN)
                   ? __half2float(qkvo[r0 + (size_t)RG * QKVO_COLS + 512 + c]) : 0.f;

        float qv[RG], ov[RG];
#pragma unroll
        for (int i = 0; i < RG; i++) {
            qv[i] = __half2float(qkvo[r0 + (size_t)i * QKVO_COLS + c]);
            ov[i] = __half2float(qkvo[r0 + (size_t)i * QKVO_COLS + 768 + c]);
        }

        float qh[RG];
#pragma unroll
        for (int i = 0; i < RG; i++)
            qh[i] = (qv[i] > 0.f) ? (qv[i] + 1.f) : __expf(qv[i]);

        float zp[RG];
#pragma unroll
        for (int i = 0; i < RG; i++) zp[i] = qh[i] * km;
#pragma unroll
        for (int off = 16; off > 0; off >>= 1) {
#pragma unroll
            for (int i = 0; i < RG; i++)
                zp[i] += __shfl_xor_sync(0xffffffffu, zp[i], off);
        }

        float qs[RG];
#pragma unroll
        for (int i = 0; i < RG; i++) {
            float partner = __shfl_xor_sync(0xffffffffu, qh[i], 1);
            float sv = sinp[(n0 + g + i) * HD + d];
            float cv = cosp[(n0 + g + i) * HD + d];
            float rot = (d & 1) ? partner : -partner;
            qs[i] = qh[i] * cv + rot * sv;
        }

        float acc[RG];
#pragma unroll
        for (int i = 0; i < RG; i++) acc[i] = 0.f;
#pragma unroll
        for (int dd = 0; dd < 32; dd++) {
            float kvv = kvh[dd * HD + d];
#pragma unroll
            for (int i = 0; i < RG; i++)
                acc[i] += __shfl_sync(0xffffffffu, qs[i], dd) * kvv;
        }

#pragma unroll
        for (int i = 0; i < RG; i++) {
            float z = zp[i] * inv_scale_n;
            float coef = 1.f + 1.f / (z + 1e-6f);
            float prev = (i == 0) ? vp : ((i == 1) ? vc : vn[i - 2]);
            float cur  = (i == 0) ? vc : vn[i - 1];
            float next = vn[i];
            float res  = acc[i] * coef - z * vm;
            float lepe = prev * w0 + cur * w1 + next * w2 + bl;
            ph[(size_t)(b * NN + n0 + g + i) * INTERNAL + c] =
                __float2half((res + lepe) * ov[i]);
        }

        vp = vn[RG - 2];
        vc = vn[RG - 1];
    }
}

// ---------------- launch -----------------------------------------------------
extern "C" void kernel_launch(void* const* d_in, const int* in_sizes, int n_in,
                              void* d_out, int out_size)
{
    const float* x       = (const float*)d_in[0];
    const float* sinp    = (const float*)d_in[1];
    const float* cosp    = (const float*)d_in[2];
    const float* W_qkvo  = (const float*)d_in[3];
    const float* b_qkvo  = (const float*)d_in[4];
    const float* W_lepe  = (const float*)d_in[5];
    const float* b_lepe  = (const float*)d_in[6];
    const float* W_proj  = (const float*)d_in[7];
    const float* b_proj  = (const float*)d_in[8];
    float* out = (float*)d_out;

    __half *qkvo_p, *xh, *ph, *wqh, *pwh;
    cudaGetSymbolAddress((void**)&qkvo_p, g_qkvo);
    cudaGetSymbolAddress((void**)&xh,  g_xh);
    cudaGetSymbolAddress((void**)&ph,  g_ph);
    cudaGetSymbolAddress((void**)&wqh, g_wqh);
    cudaGetSymbolAddress((void**)&pwh, g_pwh);

    cudaFuncSetAttribute(gemm_h_kernel<__half>,
                         cudaFuncAttributeMaxDynamicSharedMemorySize, GEMM_SMEM_BYTES);
    cudaFuncSetAttribute(gemm_h_kernel<float>,
                         cudaFuncAttributeMaxDynamicSharedMemorySize, GEMM_SMEM_BYTES);

    zero_kernel<<<(BB * HH * HD * HD + 255) / 256, 256>>>();

    cvt_all_kernel<<<(CVT_N1 + CVT_N2 + CVT_N3 + 255) / 256, 256>>>(
        x, W_qkvo, W_proj, xh, wqh, pwh);

    // GEMM1: qkvo = x @ W_qkvo^T + b_qkvo   [32768 x 1024] -> fp16
    gemm_h_kernel<__half><<<dim3(QKVO_COLS / 128, MROWS / 128), 256, GEMM_SMEM_BYTES>>>(
        xh, wqh, b_qkvo, qkvo_p, MROWS, QKVO_COLS, DIMV);

    stats_kernel<<<dim3(BB * HH, 32), 256>>>(qkvo_p, sinp, cosp);

    fuse_kernel<<<BB * (NN / TILE_ROWS), 256>>>(qkvo_p, sinp, cosp,
                                                W_lepe, b_lepe, ph);

    // GEMM2: out = pre @ W_proj^T + b_proj  [32768 x 256] -> fp32
    gemm_h_kernel<float><<<dim3(INTERNAL / 128, MROWS / 128), 256, GEMM_SMEM_BYTES>>>(
        ph, pwh, b_proj, out, MROWS, INTERNAL, DIMV);
}

// round 12
// speedup vs baseline: 2.7144x; 1.1107x over previous
#include <cuda_runtime.h>
#include <cuda_fp16.h>
#include <math.h>
#include <stdint.h>

#define BB 4
#define NN 8192
#define DIMV 256
#define HH 8
#define HD 32
#define INTERNAL 256
#define MROWS (BB * NN)        // 32768
#define QKVO_COLS 1024
#define SCALE_F 0.17677669529663687f

// ---------------- persistent device scratch (no allocations) ----------------
__device__ __half g_qkvo[(size_t)MROWS * QKVO_COLS];    // 67 MB fp16
__device__ __half g_xh [(size_t)MROWS * DIMV];
__device__ __half g_ph [(size_t)MROWS * INTERNAL];
__device__ __half g_wqh[(size_t)QKVO_COLS * DIMV];
__device__ __half g_pwh[(size_t)DIMV * INTERNAL];
__device__ float g_kv  [BB * HH * HD * HD];
__device__ float g_ksum[BB * HH * HD];
__device__ float g_vsum[BB * HH * HD];

__device__ __forceinline__ uint32_t smem_u32(const void* p) {
    uint32_t a;
    asm("{ .reg .u64 t; cvta.to.shared.u64 t, %1; cvt.u32.u64 %0, t; }"
        : "=r"(a) : "l"(p));
    return a;
}

__device__ __forceinline__ void ldmx4(uint32_t* r, uint32_t addr) {
    asm volatile("ldmatrix.sync.aligned.m8n8.x4.shared.b16 {%0,%1,%2,%3}, [%4];"
        : "=r"(r[0]), "=r"(r[1]), "=r"(r[2]), "=r"(r[3]) : "r"(addr));
}
__device__ __forceinline__ void ldmx2(uint32_t* r, uint32_t addr) {
    asm volatile("ldmatrix.sync.aligned.m8n8.x2.shared.b16 {%0,%1}, [%2];"
        : "=r"(r[0]), "=r"(r[1]) : "r"(addr));
}

__device__ __forceinline__ void mma16816h(float* d, const uint32_t* a,
                                          uint32_t b0, uint32_t b1) {
    asm volatile(
        "mma.sync.aligned.m16n8k16.row.col.f32.f16.f16.f32 "
        "{%0,%1,%2,%3}, {%4,%5,%6,%7}, {%8,%9}, {%0,%1,%2,%3};"
        : "+f"(d[0]), "+f"(d[1]), "+f"(d[2]), "+f"(d[3])
        : "r"(a[0]), "r"(a[1]), "r"(a[2]), "r"(a[3]), "r"(b0), "r"(b1));
}

__device__ __forceinline__ void cp16(uint32_t saddr, const void* gaddr) {
    asm volatile("cp.async.cg.shared.global [%0], [%1], 16;"
        :: "r"(saddr), "l"(gaddr) : "memory");
}
#define CP_COMMIT() asm volatile("cp.async.commit_group;" ::: "memory")
#define CP_WAIT(n)  asm volatile("cp.async.wait_group %0;" :: "n"(n) : "memory")

// ---------------- fused fp32 -> fp16 conversion (one launch) ----------------
#define CVT_N1 (MROWS * DIMV / 4)
#define CVT_N2 (QKVO_COLS * DIMV / 4)
#define CVT_N3 (DIMV * INTERNAL / 4)
__global__ void __launch_bounds__(256)
cvt_all_kernel(const float* __restrict__ x, const float* __restrict__ wq,
               const float* __restrict__ pw, __half* __restrict__ xh,
               __half* __restrict__ wqh, __half* __restrict__ pwh)
{
    int i = blockIdx.x * 256 + threadIdx.x;
    const float* s; __half* d; int j;
    if (i < CVT_N1) { s = x; d = xh; j = i; }
    else if (i < CVT_N1 + CVT_N2) { s = wq; d = wqh; j = i - CVT_N1; }
    else if (i < CVT_N1 + CVT_N2 + CVT_N3) { s = pw; d = pwh; j = i - CVT_N1 - CVT_N2; }
    else return;
    float4 v = ((const float4*)s)[j];
    __half2 h0 = __floats2half2_rn(v.x, v.y);
    __half2 h1 = __floats2half2_rn(v.z, v.w);
    uint2 o = { *reinterpret_cast<uint32_t*>(&h0), *reinterpret_cast<uint32_t*>(&h1) };
    ((uint2*)d)[j] = o;
}

// =================== HMMA GEMM (single fp16, 4-stage cp.async) ==============
#define ROWB 80
#define ST_A 0
#define ST_B 10240
#define STAGEB 20480
#define NSTAGE 4
#define GEMM_SMEM_BYTES (NSTAGE * STAGEB)   // 80 KB

template <typename OutT>
__global__ void __launch_bounds__(256)
gemm_h_kernel(const __half* __restrict__ A, const __half* __restrict__ Bw,
              const float* __restrict__ bias, OutT* __restrict__ C,
              int M, int Nn, int K)
{
    extern __shared__ char sm[];
    const uint32_t smb = smem_u32(sm);
    const int tid  = threadIdx.x;
    const int wid  = tid >> 5;
    const int lane = tid & 31;
    const int m0 = blockIdx.y * 128;
    const int n0 = blockIdx.x * 128;
    const int wm0 = (wid & 3) * 32;
    const int wn0 = (wid >> 2) * 64;

    const int a_row = (lane & 7) + ((lane >> 3) & 1) * 8;
    const int a_kh  = (lane >> 4) * 8;
    const int b_row = (lane & 7) + ((lane >> 4) & 1) * 8;
    const int b_kh  = ((lane >> 3) & 1) * 8;

    float acc[2][8][4];
#pragma unroll
    for (int i = 0; i < 2; i++)
#pragma unroll
        for (int j = 0; j < 8; j++)
#pragma unroll
            for (int l = 0; l < 4; l++) acc[i][j][l] = 0.f;

    const int NCH = K / 32;
    const int row2 = tid >> 2;
    const int seg  = tid & 3;

#define LOAD_STAGE(c, buf) do {                                              \
    int k0 = (c) * 32;                                                       \
    uint32_t base = smb + (buf) * STAGEB;                                    \
    _Pragma("unroll")                                                        \
    for (int i = 0; i < 2; i++) {                                            \
        int r = row2 + i * 64;                                               \
        uint32_t so = r * ROWB + seg * 16;                                   \
        cp16(base + ST_A + so, A  + (size_t)(m0 + r) * K + k0 + seg * 8);    \
        cp16(base + ST_B + so, Bw + (size_t)(n0 + r) * K + k0 + seg * 8);    \
    }                                                                        \
    CP_COMMIT();                                                             \
} while (0)

    LOAD_STAGE(0, 0);
    LOAD_STAGE(1, 1);
    LOAD_STAGE(2, 2);

    for (int c = 0; c < NCH; c++) {
        CP_WAIT(2);
        __syncthreads();
        const uint32_t base = smb + (c & (NSTAGE - 1)) * STAGEB;

#pragma unroll
        for (int ks = 0; ks < 2; ks++) {
            uint32_t af[2][4], bf[4][4];
#pragma unroll
            for (int mf = 0; mf < 2; mf++)
                ldmx4(af[mf], base + ST_A + (wm0 + mf * 16 + a_row) * ROWB
                                        + (ks * 16 + a_kh) * 2);
#pragma unroll
            for (int nf2 = 0; nf2 < 4; nf2++)
                ldmx4(bf[nf2], base + ST_B + (wn0 + nf2 * 16 + b_row) * ROWB
                                          + (ks * 16 + b_kh) * 2);
#pragma unroll
            for (int nf2 = 0; nf2 < 4; nf2++)
#pragma unroll
                for (int mf = 0; mf < 2; mf++)
#pragma unroll
                    for (int s = 0; s < 2; s++)
                        mma16816h(acc[mf][nf2 * 2 + s], af[mf],
                                  bf[nf2][s * 2], bf[nf2][s * 2 + 1]);
        }
        __syncthreads();
        if (c + 3 < NCH) LOAD_STAGE(c + 3, (c + 3) & (NSTAGE - 1));
        else CP_COMMIT();
    }
#undef LOAD_STAGE

    const int rr = lane >> 2;
    const int cc = (lane & 3) * 2;
#pragma unroll
    for (int mf = 0; mf < 2; mf++) {
        int r0 = m0 + wm0 + mf * 16 + rr;
#pragma unroll
        for (int nf = 0; nf < 8; nf++) {
            int col = n0 + wn0 + nf * 8 + cc;
            float b0 = bias[col], b1 = bias[col + 1];
            float o00 = acc[mf][nf][0] + b0, o01 = acc[mf][nf][1] + b1;
            float o10 = acc[mf][nf][2] + b0, o11 = acc[mf][nf][3] + b1;
            if (sizeof(OutT) == 2) {
                __half2 p0 = __floats2half2_rn(o00, o01);
                __half2 p1 = __floats2half2_rn(o10, o11);
                *(__half2*)&C[(size_t)r0 * Nn + col] = p0;
                *(__half2*)&C[(size_t)(r0 + 8) * Nn + col] = p1;
            } else {
                float2 v0 = {o00, o01}, v1 = {o10, o11};
                *(float2*)&C[(size_t)r0 * Nn + col] = v0;
                *(float2*)&C[(size_t)(r0 + 8) * Nn + col] = v1;
            }
        }
    }
}

// ---------------- zero accumulators ----------------------------------------
__global__ void zero_kernel() {
    int i = blockIdx.x * 256 + threadIdx.x;
    if (i < BB * HH * HD * HD) g_kv[i] = 0.f;
    if (i < BB * HH * HD) { g_ksum[i] = 0.f; g_vsum[i] = 0.f; }
}

// ---------------- stats v4: tensor-core kv_state ----------------------------
// grid (32 bh, 32 splits), 256 threads = 8 warps. Warp-private 32-row chunk:
// stage ksT[d][n], vT[e][n] (fp16, 80B stride), 16x mma.m16n8k16, then
// one cross-warp smem reduction. No block barriers in the main phase.
#define STW 5120                   // per-warp staging bytes (2 x 32 x 40 halves)
#define KVS_OFF 40960              // 8 warps x STW
#define KVROW 34                   // padded fp32 row stride for partials
#define STATS_SMEM (KVS_OFF + 8 * 32 * KVROW * 4)   // 75776 B

__global__ void __launch_bounds__(256)
stats_kernel(const __half* __restrict__ qkvo,
             const float* __restrict__ sinp, const float* __restrict__ cosp)
{
    extern __shared__ char ssm[];
    const int tid  = threadIdx.x;
    const int w    = tid >> 5;
    const int lane = tid & 31;
    const int bh = blockIdx.x;          // 0..31
    const int b = bh >> 3, h = bh & 7;
    const int nb = blockIdx.y * 256 + w * 32;    // this warp's 32-row chunk

    char* smw = ssm + w * STW;                       // ksT tile
    char* smv = smw + 2560;                          // vT tile
    const uint32_t ks_u = smem_u32(smw);
    const uint32_t v_u  = smem_u32(smv);

    const __half* kbase = qkvo + (size_t)(b * NN + nb) * QKVO_COLS + 256 + h * 32 + lane;
    const __half* vbase = kbase + 256;

    float ksum_acc = 0.f, vsum_acc = 0.f;

    // ---- stage 32 rows, transposed, in groups of 8 ----
#pragma unroll
    for (int g = 0; g < 4; g++) {
        float kr[8], vr[8], sv[8], cv[8];
#pragma unroll
        for (int i = 0; i < 8; i++) {
            kr[i] = __half2float(kbase[(size_t)(g * 8 + i) * QKVO_COLS]);
            vr[i] = __half2float(vbase[(size_t)(g * 8 + i) * QKVO_COLS]);
        }
#pragma unroll
        for (int i = 0; i < 8; i++) {
            sv[i] = sinp[(nb + g * 8 + i) * HD + lane];
            cv[i] = cosp[(nb + g * 8 + i) * HD + lane];
        }
        __half ksh[8], vh[8];
#pragma unroll
        for (int i = 0; i < 8; i++) {
            float kh = (kr[i] > 0.f) ? (kr[i] + 1.f) : __expf(kr[i]);
            ksum_acc += kh;
            vsum_acc += vr[i];
            float partner = __shfl_xor_sync(0xffffffffu, kh, 1);
            float rot = (lane & 1) ? partner : -partner;
            ksh[i] = __float2half(kh * cv[i] + rot * sv[i]);
            vh[i]  = __float2half(vr[i]);
        }
#pragma unroll
        for (int i = 0; i < 8; i += 2) {
            int n = g * 8 + i;
            __half2 pk = {ksh[i], ksh[i + 1]};
            __half2 pv = {vh[i],  vh[i + 1]};
            *(__half2*)(smw + lane * 80 + n * 2) = pk;
            *(__half2*)(smv + lane * 80 + n * 2) = pv;
        }
    }
    __syncwarp();

    // ---- 32x32x32 HMMA: kv[d][e] = sum_n ksT[d][n] * vT[e][n] ----
    float kv[2][4][4];
#pragma unroll
    for (int mt = 0; mt < 2; mt++)
#pragma unroll
        for (int et = 0; et < 4; et++)
#pragma unroll
            for (int l = 0; l < 4; l++) kv[mt][et][l] = 0.f;

#pragma unroll
    for (int ks = 0; ks < 2; ks++) {
        const int k0 = ks * 16;
        uint32_t af[2][4];
#pragma unroll
        for (int mt = 0; mt < 2; mt++)
            ldmx4(af[mt], ks_u + (mt * 16 + (lane & 7) + ((lane >> 3) & 1) * 8) * 80
                               + (k0 + (lane >> 4) * 8) * 2);
#pragma unroll
        for (int et = 0; et < 4; et++) {
            uint32_t bf[2];
            ldmx2(bf, v_u + (et * 8 + (lane & 7)) * 80
                          + (k0 + ((lane >> 3) & 1) * 8) * 2);
#pragma unroll
            for (int mt = 0; mt < 2; mt++)
                mma16816h(kv[mt][et], af[mt], bf[0], bf[1]);
        }
    }

    // ---- write warp partials to smem ----
    float* kvw = (float*)(ssm + KVS_OFF) + w * 32 * KVROW;
    const int dm = lane >> 2;
    const int de = (lane & 3) * 2;
#pragma unroll
    for (int mt = 0; mt < 2; mt++)
#pragma unroll
        for (int et = 0; et < 4; et++) {
            float2 lo = {kv[mt][et][0], kv[mt][et][1]};
            float2 hi = {kv[mt][et][2], kv[mt][et][3]};
            *(float2*)&kvw[(mt * 16 + dm) * KVROW + et * 8 + de] = lo;
            *(float2*)&kvw[(mt * 16 + dm + 8) * KVROW + et * 8 + de] = hi;
        }

    atomicAdd(&g_ksum[bh * HD + lane], ksum_acc);
    atomicAdd(&g_vsum[bh * HD + lane], vsum_acc);

    __syncthreads();

    // ---- cross-warp reduce + global atomics (1024 outputs / 256 threads) ----
    const float* kvs = (const float*)(ssm + KVS_OFF);
#pragma unroll
    for (int o = 0; o < 4; o++) {
        int idx = o * 256 + tid;
        int m = idx >> 5, e = idx & 31;
        float s = 0.f;
#pragma unroll
        for (int ww = 0; ww < 8; ww++)
            s += kvs[ww * 32 * KVROW + m * KVROW + e];
        atomicAdd(&g_kv[bh * (HD * HD) + m * HD + e], s);
    }
}

// ---------------- fused per-token epilogue (4-row ILP, fp16 qkvo) -----------
#define TILE_ROWS 64
#define RG 4
__global__ void __launch_bounds__(256)
fuse_kernel(const __half* __restrict__ qkvo,
            const float* __restrict__ sinp, const float* __restrict__ cosp,
            const float* __restrict__ W_lepe, const float* __restrict__ b_lepe,
            __half* __restrict__ ph)
{
    __shared__ float skv[HH * HD * HD];

    const int tile = blockIdx.x;
    const int b  = tile / (NN / TILE_ROWS);
    const int t  = tile % (NN / TILE_ROWS);
    const int n0 = t * TILE_ROWS;
    const int c  = threadIdx.x;
    const int h  = c >> 5;
    const int d  = c & 31;
    const float inv_scale_n = SCALE_F / (float)NN;

    const int base_kv = b * HH * HD * HD;
#pragma unroll
    for (int i = 0; i < HH * HD * HD / 256; i++)
        skv[i * 256 + c] = g_kv[base_kv + i * 256 + c] * inv_scale_n;

    const float km = g_ksum[(b * HH + h) * HD + d];
    const float vm = g_vsum[(b * HH + h) * HD + d] * (1.f / NN);
    __syncthreads();

    const float w0 = W_lepe[c * 3 + 0];
    const float w1 = W_lepe[c * 3 + 1];
    const float w2 = W_lepe[c * 3 + 2];
    const float bl = b_lepe[c];

    const size_t rowbase = (size_t)(b * NN + n0) * QKVO_COLS;
    float vp = (n0 > 0) ? __half2float(qkvo[rowbase - QKVO_COLS + 512 + c]) : 0.f;
    float vc = __half2float(qkvo[rowbase + 512 + c]);

    const float* kvh = &skv[h * HD * HD];

#pragma unroll 1
    for (int g = 0; g < TILE_ROWS; g += RG) {
        const size_t r0 = rowbase + (size_t)g * QKVO_COLS;

        float vn[RG];
#pragma unroll
        for (int i = 0; i < RG - 1; i++)
            vn[i] = __half2float(qkvo[r0 + (size_t)(i + 1) * QKVO_COLS + 512 + c]);
        vn[RG - 1] = (n0 + g + RG < NN)
                   ? __half2float(qkvo[r0 + (size_t)RG * QKVO_COLS + 512 + c]) : 0.f;

        float qv[RG], ov[RG];
#pragma unroll
        for (int i = 0; i < RG; i++) {
            qv[i] = __half2float(qkvo[r0 + (size_t)i * QKVO_COLS + c]);
            ov[i] = __half2float(qkvo[r0 + (size_t)i * QKVO_COLS + 768 + c]);
        }

        float qh[RG];
#pragma unroll
        for (int i = 0; i < RG; i++)
            qh[i] = (qv[i] > 0.f) ? (qv[i] + 1.f) : __expf(qv[i]);

        float zp[RG];
#pragma unroll
        for (int i = 0; i < RG; i++) zp[i] = qh[i] * km;
#pragma unroll
        for (int off = 16; off > 0; off >>= 1) {
#pragma unroll
            for (int i = 0; i < RG; i++)
                zp[i] += __shfl_xor_sync(0xffffffffu, zp[i], off);
        }

        float qs[RG];
#pragma unroll
        for (int i = 0; i < RG; i++) {
            float partner = __shfl_xor_sync(0xffffffffu, qh[i], 1);
            float sv = sinp[(n0 + g + i) * HD + d];
            float cv = cosp[(n0 + g + i) * HD + d];
            float rot = (d & 1) ? partner : -partner;
            qs[i] = qh[i] * cv + rot * sv;
        }

        float acc[RG];
#pragma unroll
        for (int i = 0; i < RG; i++) acc[i] = 0.f;
#pragma unroll
        for (int dd = 0; dd < 32; dd++) {
            float kvv = kvh[dd * HD + d];
#pragma unroll
            for (int i = 0; i < RG; i++)
                acc[i] += __shfl_sync(0xffffffffu, qs[i], dd) * kvv;
        }

#pragma unroll
        for (int i = 0; i < RG; i++) {
            float z = zp[i] * inv_scale_n;
            float coef = 1.f + 1.f / (z + 1e-6f);
            float prev = (i == 0) ? vp : ((i == 1) ? vc : vn[i - 2]);
            float cur  = (i == 0) ? vc : vn[i - 1];
            float next = vn[i];
            float res  = acc[i] * coef - z * vm;
            float lepe = prev * w0 + cur * w1 + next * w2 + bl;
            ph[(size_t)(b * NN + n0 + g + i) * INTERNAL + c] =
                __float2half((res + lepe) * ov[i]);
        }

        vp = vn[RG - 2];
        vc = vn[RG - 1];
    }
}

// ---------------- launch -----------------------------------------------------
extern "C" void kernel_launch(void* const* d_in, const int* in_sizes, int n_in,
                              void* d_out, int out_size)
{
    const float* x       = (const float*)d_in[0];
    const float* sinp    = (const float*)d_in[1];
    const float* cosp    = (const float*)d_in[2];
    const float* W_qkvo  = (const float*)d_in[3];
    const float* b_qkvo  = (const float*)d_in[4];
    const float* W_lepe  = (const float*)d_in[5];
    const float* b_lepe  = (const float*)d_in[6];
    const float* W_proj  = (const float*)d_in[7];
    const float* b_proj  = (const float*)d_in[8];
    float* out = (float*)d_out;

    __half *qkvo_p, *xh, *ph, *wqh, *pwh;
    cudaGetSymbolAddress((void**)&qkvo_p, g_qkvo);
    cudaGetSymbolAddress((void**)&xh,  g_xh);
    cudaGetSymbolAddress((void**)&ph,  g_ph);
    cudaGetSymbolAddress((void**)&wqh, g_wqh);
    cudaGetSymbolAddress((void**)&pwh, g_pwh);

    cudaFuncSetAttribute(gemm_h_kernel<__half>,
                         cudaFuncAttributeMaxDynamicSharedMemorySize, GEMM_SMEM_BYTES);
    cudaFuncSetAttribute(gemm_h_kernel<float>,
                         cudaFuncAttributeMaxDynamicSharedMemorySize, GEMM_SMEM_BYTES);
    cudaFuncSetAttribute(stats_kernel,
                         cudaFuncAttributeMaxDynamicSharedMemorySize, STATS_SMEM);

    zero_kernel<<<(BB * HH * HD * HD + 255) / 256, 256>>>();

    cvt_all_kernel<<<(CVT_N1 + CVT_N2 + CVT_N3 + 255) / 256, 256>>>(
        x, W_qkvo, W_proj, xh, wqh, pwh);

    // GEMM1: qkvo = x @ W_qkvo^T + b_qkvo   [32768 x 1024] -> fp16
    gemm_h_kernel<__half><<<dim3(QKVO_COLS / 128, MROWS / 128), 256, GEMM_SMEM_BYTES>>>(
        xh, wqh, b_qkvo, qkvo_p, MROWS, QKVO_COLS, DIMV);

    stats_kernel<<<dim3(BB * HH, 32), 256, STATS_SMEM>>>(qkvo_p, sinp, cosp);

    fuse_kernel<<<BB * (NN / TILE_ROWS), 256>>>(qkvo_p, sinp, cosp,
                                                W_lepe, b_lepe, ph);

    // GEMM2: out = pre @ W_proj^T + b_proj  [32768 x 256] -> fp32
    gemm_h_kernel<float><<<dim3(INTERNAL / 128, MROWS / 128), 256, GEMM_SMEM_BYTES>>>(
        ph, pwh, b_proj, out, MROWS, INTERNAL, DIMV);
}

// round 13
// speedup vs baseline: 3.0427x; 1.1210x over previous
#include <cuda_runtime.h>
#include <cuda_fp16.h>
#include <math.h>
#include <stdint.h>

#define BB 4
#define NN 8192
#define DIMV 256
#define HH 8
#define HD 32
#define INTERNAL 256
#define MROWS (BB * NN)        // 32768
#define QKVO_COLS 1024
#define SCALE_F 0.17677669529663687f

// ---------------- persistent device scratch (no allocations) ----------------
__device__ __half g_qkvo[(size_t)MROWS * QKVO_COLS];    // 67 MB fp16
__device__ __half g_xh [(size_t)MROWS * DIMV];
__device__ __half g_ph [(size_t)MROWS * INTERNAL];
__device__ __half g_wqh[(size_t)QKVO_COLS * DIMV];
__device__ __half g_pwh[(size_t)DIMV * INTERNAL];
__device__ float g_kv  [BB * HH * HD * HD];
__device__ float g_ksum[BB * HH * HD];
__device__ float g_vsum[BB * HH * HD];

__device__ __forceinline__ uint32_t smem_u32(const void* p) {
    uint32_t a;
    asm("{ .reg .u64 t; cvta.to.shared.u64 t, %1; cvt.u32.u64 %0, t; }"
        : "=r"(a) : "l"(p));
    return a;
}

__device__ __forceinline__ void ldmx4(uint32_t* r, uint32_t addr) {
    asm volatile("ldmatrix.sync.aligned.m8n8.x4.shared.b16 {%0,%1,%2,%3}, [%4];"
        : "=r"(r[0]), "=r"(r[1]), "=r"(r[2]), "=r"(r[3]) : "r"(addr));
}
__device__ __forceinline__ void ldmx2(uint32_t* r, uint32_t addr) {
    asm volatile("ldmatrix.sync.aligned.m8n8.x2.shared.b16 {%0,%1}, [%2];"
        : "=r"(r[0]), "=r"(r[1]) : "r"(addr));
}

__device__ __forceinline__ void mma16816h(float* d, const uint32_t* a,
                                          uint32_t b0, uint32_t b1) {
    asm volatile(
        "mma.sync.aligned.m16n8k16.row.col.f32.f16.f16.f32 "
        "{%0,%1,%2,%3}, {%4,%5,%6,%7}, {%8,%9}, {%0,%1,%2,%3};"
        : "+f"(d[0]), "+f"(d[1]), "+f"(d[2]), "+f"(d[3])
        : "r"(a[0]), "r"(a[1]), "r"(a[2]), "r"(a[3]), "r"(b0), "r"(b1));
}

__device__ __forceinline__ void cp16(uint32_t saddr, const void* gaddr) {
    asm volatile("cp.async.cg.shared.global [%0], [%1], 16;"
        :: "r"(saddr), "l"(gaddr) : "memory");
}
#define CP_COMMIT() asm volatile("cp.async.commit_group;" ::: "memory")
#define CP_WAIT(n)  asm volatile("cp.async.wait_group %0;" :: "n"(n) : "memory")

// ---------------- fused fp32 -> fp16 conversion (one launch) ----------------
#define CVT_N1 (MROWS * DIMV / 4)
#define CVT_N2 (QKVO_COLS * DIMV / 4)
#define CVT_N3 (DIMV * INTERNAL / 4)
__global__ void __launch_bounds__(256)
cvt_all_kernel(const float* __restrict__ x, const float* __restrict__ wq,
               const float* __restrict__ pw, __half* __restrict__ xh,
               __half* __restrict__ wqh, __half* __restrict__ pwh)
{
    int i = blockIdx.x * 256 + threadIdx.x;
    const float* s; __half* d; int j;
    if (i < CVT_N1) { s = x; d = xh; j = i; }
    else if (i < CVT_N1 + CVT_N2) { s = wq; d = wqh; j = i - CVT_N1; }
    else if (i < CVT_N1 + CVT_N2 + CVT_N3) { s = pw; d = pwh; j = i - CVT_N1 - CVT_N2; }
    else return;
    float4 v = ((const float4*)s)[j];
    __half2 h0 = __floats2half2_rn(v.x, v.y);
    __half2 h1 = __floats2half2_rn(v.z, v.w);
    uint2 o = { *reinterpret_cast<uint32_t*>(&h0), *reinterpret_cast<uint32_t*>(&h1) };
    ((uint2*)d)[j] = o;
}

// =================== HMMA GEMM (single fp16, 4-stage cp.async) ==============
#define ROWB 80
#define ST_A 0
#define ST_B 10240
#define STAGEB 20480
#define NSTAGE 4
#define GEMM_SMEM_BYTES (NSTAGE * STAGEB)   // 80 KB

template <typename OutT>
__global__ void __launch_bounds__(256)
gemm_h_kernel(const __half* __restrict__ A, const __half* __restrict__ Bw,
              const float* __restrict__ bias, OutT* __restrict__ C,
              int M, int Nn, int K)
{
    extern __shared__ char sm[];
    const uint32_t smb = smem_u32(sm);
    const int tid  = threadIdx.x;
    const int wid  = tid >> 5;
    const int lane = tid & 31;
    const int m0 = blockIdx.y * 128;
    const int n0 = blockIdx.x * 128;
    const int wm0 = (wid & 3) * 32;
    const int wn0 = (wid >> 2) * 64;

    const int a_row = (lane & 7) + ((lane >> 3) & 1) * 8;
    const int a_kh  = (lane >> 4) * 8;
    const int b_row = (lane & 7) + ((lane >> 4) & 1) * 8;
    const int b_kh  = ((lane >> 3) & 1) * 8;

    float acc[2][8][4];
#pragma unroll
    for (int i = 0; i < 2; i++)
#pragma unroll
        for (int j = 0; j < 8; j++)
#pragma unroll
            for (int l = 0; l < 4; l++) acc[i][j][l] = 0.f;

    const int NCH = K / 32;
    const int row2 = tid >> 2;
    const int seg  = tid & 3;

#define LOAD_STAGE(c, buf) do {                                              \
    int k0 = (c) * 32;                                                       \
    uint32_t base = smb + (buf) * STAGEB;                                    \
    _Pragma("unroll")                                                        \
    for (int i = 0; i < 2; i++) {                                            \
        int r = row2 + i * 64;                                               \
        uint32_t so = r * ROWB + seg * 16;                                   \
        cp16(base + ST_A + so, A  + (size_t)(m0 + r) * K + k0 + seg * 8);    \
        cp16(base + ST_B + so, Bw + (size_t)(n0 + r) * K + k0 + seg * 8);    \
    }                                                                        \
    CP_COMMIT();                                                             \
} while (0)

    LOAD_STAGE(0, 0);
    LOAD_STAGE(1, 1);
    LOAD_STAGE(2, 2);

    for (int c = 0; c < NCH; c++) {
        CP_WAIT(2);
        __syncthreads();
        const uint32_t base = smb + (c & (NSTAGE - 1)) * STAGEB;

#pragma unroll
        for (int ks = 0; ks < 2; ks++) {
            uint32_t af[2][4], bf[4][4];
#pragma unroll
            for (int mf = 0; mf < 2; mf++)
                ldmx4(af[mf], base + ST_A + (wm0 + mf * 16 + a_row) * ROWB
                                        + (ks * 16 + a_kh) * 2);
#pragma unroll
            for (int nf2 = 0; nf2 < 4; nf2++)
                ldmx4(bf[nf2], base + ST_B + (wn0 + nf2 * 16 + b_row) * ROWB
                                          + (ks * 16 + b_kh) * 2);
#pragma unroll
            for (int nf2 = 0; nf2 < 4; nf2++)
#pragma unroll
                for (int mf = 0; mf < 2; mf++)
#pragma unroll
                    for (int s = 0; s < 2; s++)
                        mma16816h(acc[mf][nf2 * 2 + s], af[mf],
                                  bf[nf2][s * 2], bf[nf2][s * 2 + 1]);
        }
        __syncthreads();
        if (c + 3 < NCH) LOAD_STAGE(c + 3, (c + 3) & (NSTAGE - 1));
        else CP_COMMIT();
    }
#undef LOAD_STAGE

    const int rr = lane >> 2;
    const int cc = (lane & 3) * 2;
#pragma unroll
    for (int mf = 0; mf < 2; mf++) {
        int r0 = m0 + wm0 + mf * 16 + rr;
#pragma unroll
        for (int nf = 0; nf < 8; nf++) {
            int col = n0 + wn0 + nf * 8 + cc;
            float b0 = bias[col], b1 = bias[col + 1];
            float o00 = acc[mf][nf][0] + b0, o01 = acc[mf][nf][1] + b1;
            float o10 = acc[mf][nf][2] + b0, o11 = acc[mf][nf][3] + b1;
            if (sizeof(OutT) == 2) {
                __half2 p0 = __floats2half2_rn(o00, o01);
                __half2 p1 = __floats2half2_rn(o10, o11);
                *(__half2*)&C[(size_t)r0 * Nn + col] = p0;
                *(__half2*)&C[(size_t)(r0 + 8) * Nn + col] = p1;
            } else {
                float2 v0 = {o00, o01}, v1 = {o10, o11};
                *(float2*)&C[(size_t)r0 * Nn + col] = v0;
                *(float2*)&C[(size_t)(r0 + 8) * Nn + col] = v1;
            }
        }
    }
}

// ---------------- zero accumulators ----------------------------------------
__global__ void zero_kernel() {
    int i = blockIdx.x * 256 + threadIdx.x;
    if (i < BB * HH * HD * HD) g_kv[i] = 0.f;
    if (i < BB * HH * HD) { g_ksum[i] = 0.f; g_vsum[i] = 0.f; }
}

// ---------------- stats v5: tensor-core kv_state, smem reuse ----------------
// Warp-private staging (5120 B/warp) is reused for the fp32 partials after the
// MMAs complete -> total smem 40 KB -> 5 blocks/SM.
#define STW 5120                   // per-warp staging bytes
#define KVROW 34                   // padded fp32 row stride for partials
#define STATS_SMEM (8 * STW)       // 40960 B

__global__ void __launch_bounds__(256)
stats_kernel(const __half* __restrict__ qkvo,
             const float* __restrict__ sinp, const float* __restrict__ cosp)
{
    extern __shared__ char ssm[];
    const int tid  = threadIdx.x;
    const int w    = tid >> 5;
    const int lane = tid & 31;
    const int bh = blockIdx.x;          // 0..31
    const int b = bh >> 3, h = bh & 7;
    const int nb = blockIdx.y * 256 + w * 32;    // this warp's 32-row chunk

    char* smw = ssm + w * STW;                       // ksT tile
    char* smv = smw + 2560;                          // vT tile
    const uint32_t ks_u = smem_u32(smw);
    const uint32_t v_u  = smem_u32(smv);

    const __half* kbase = qkvo + (size_t)(b * NN + nb) * QKVO_COLS + 256 + h * 32 + lane;
    const __half* vbase = kbase + 256;

    float ksum_acc = 0.f, vsum_acc = 0.f;

    // ---- stage 32 rows, transposed, in groups of 8 ----
#pragma unroll
    for (int g = 0; g < 4; g++) {
        float kr[8], vr[8], sv[8], cv[8];
#pragma unroll
        for (int i = 0; i < 8; i++) {
            kr[i] = __half2float(kbase[(size_t)(g * 8 + i) * QKVO_COLS]);
            vr[i] = __half2float(vbase[(size_t)(g * 8 + i) * QKVO_COLS]);
        }
#pragma unroll
        for (int i = 0; i < 8; i++) {
            sv[i] = sinp[(nb + g * 8 + i) * HD + lane];
            cv[i] = cosp[(nb + g * 8 + i) * HD + lane];
        }
        __half ksh[8], vh[8];
#pragma unroll
        for (int i = 0; i < 8; i++) {
            float kh = (kr[i] > 0.f) ? (kr[i] + 1.f) : __expf(kr[i]);
            ksum_acc += kh;
            vsum_acc += vr[i];
            float partner = __shfl_xor_sync(0xffffffffu, kh, 1);
            float rot = (lane & 1) ? partner : -partner;
            ksh[i] = __float2half(kh * cv[i] + rot * sv[i]);
            vh[i]  = __float2half(vr[i]);
        }
#pragma unroll
        for (int i = 0; i < 8; i += 2) {
            int n = g * 8 + i;
            __half2 pk = {ksh[i], ksh[i + 1]};
            __half2 pv = {vh[i],  vh[i + 1]};
            *(__half2*)(smw + lane * 80 + n * 2) = pk;
            *(__half2*)(smv + lane * 80 + n * 2) = pv;
        }
    }
    __syncwarp();

    // ---- 32x32x32 HMMA: kv[d][e] = sum_n ksT[d][n] * vT[e][n] ----
    float kv[2][4][4];
#pragma unroll
    for (int mt = 0; mt < 2; mt++)
#pragma unroll
        for (int et = 0; et < 4; et++)
#pragma unroll
            for (int l = 0; l < 4; l++) kv[mt][et][l] = 0.f;

#pragma unroll
    for (int ks = 0; ks < 2; ks++) {
        const int k0 = ks * 16;
        uint32_t af[2][4];
#pragma unroll
        for (int mt = 0; mt < 2; mt++)
            ldmx4(af[mt], ks_u + (mt * 16 + (lane & 7) + ((lane >> 3) & 1) * 8) * 80
                               + (k0 + (lane >> 4) * 8) * 2);
#pragma unroll
        for (int et = 0; et < 4; et++) {
            uint32_t bf[2];
            ldmx2(bf, v_u + (et * 8 + (lane & 7)) * 80
                          + (k0 + ((lane >> 3) & 1) * 8) * 2);
#pragma unroll
            for (int mt = 0; mt < 2; mt++)
                mma16816h(kv[mt][et], af[mt], bf[0], bf[1]);
        }
    }
    __syncwarp();

    // ---- write warp partials into OWN staging region (now dead) ----
    float* kvw = (float*)(ssm + w * STW);
    const int dm = lane >> 2;
    const int de = (lane & 3) * 2;
#pragma unroll
    for (int mt = 0; mt < 2; mt++)
#pragma unroll
        for (int et = 0; et < 4; et++) {
            float2 lo = {kv[mt][et][0], kv[mt][et][1]};
            float2 hi = {kv[mt][et][2], kv[mt][et][3]};
            *(float2*)&kvw[(mt * 16 + dm) * KVROW + et * 8 + de] = lo;
            *(float2*)&kvw[(mt * 16 + dm + 8) * KVROW + et * 8 + de] = hi;
        }

    atomicAdd(&g_ksum[bh * HD + lane], ksum_acc);
    atomicAdd(&g_vsum[bh * HD + lane], vsum_acc);

    __syncthreads();

    // ---- cross-warp reduce + global atomics (1024 outputs / 256 threads) ----
    const float* kvs = (const float*)ssm;
#pragma unroll
    for (int o = 0; o < 4; o++) {
        int idx = o * 256 + tid;
        int m = idx >> 5, e = idx & 31;
        float s = 0.f;
#pragma unroll
        for (int ww = 0; ww < 8; ww++)
            s += kvs[ww * (STW / 4) + m * KVROW + e];
        atomicAdd(&g_kv[bh * (HD * HD) + m * HD + e], s);
    }
}

// ---------------- fused per-token epilogue (smem matvec, fp16 qkvo) ---------
// kv staged TRANSPOSED (kvT[h][e][dd], stride 36 -> conflict-free LDS.128);
// qs staged to warp-private smem -> matvec uses 40 MIO ops per 4-row group
// instead of 160 (shfl version).
#define TILE_ROWS 64
#define RG 4
#define KVT_ROW 36
__global__ void __launch_bounds__(256)
fuse_kernel(const __half* __restrict__ qkvo,
            const float* __restrict__ sinp, const float* __restrict__ cosp,
            const float* __restrict__ W_lepe, const float* __restrict__ b_lepe,
            __half* __restrict__ ph)
{
    __shared__ float skvT[HH * HD * KVT_ROW];   // 36864 B: kvT[h][e][dd]
    __shared__ float sqs[HH][RG][HD];           // 4096 B

    const int tile = blockIdx.x;
    const int b  = tile / (NN / TILE_ROWS);
    const int t  = tile % (NN / TILE_ROWS);
    const int n0 = t * TILE_ROWS;
    const int c  = threadIdx.x;
    const int h  = c >> 5;
    const int d  = c & 31;
    const float inv_scale_n = SCALE_F / (float)NN;

    const int base_kv = b * HH * HD * HD;
#pragma unroll
    for (int ii = 0; ii < HH * HD * HD / 256; ii++) {
        int i = ii * 256 + c;
        int hh = i >> 10, dd = (i >> 5) & 31, e = i & 31;
        skvT[hh * (HD * KVT_ROW) + e * KVT_ROW + dd] =
            g_kv[base_kv + i] * inv_scale_n;
    }

    const float km = g_ksum[(b * HH + h) * HD + d];
    const float vm = g_vsum[(b * HH + h) * HD + d] * (1.f / NN);
    __syncthreads();

    const float w0 = W_lepe[c * 3 + 0];
    const float w1 = W_lepe[c * 3 + 1];
    const float w2 = W_lepe[c * 3 + 2];
    const float bl = b_lepe[c];

    const size_t rowbase = (size_t)(b * NN + n0) * QKVO_COLS;
    float vp = (n0 > 0) ? __half2float(qkvo[rowbase - QKVO_COLS + 512 + c]) : 0.f;
    float vc = __half2float(qkvo[rowbase + 512 + c]);

    const float* kvT = &skvT[h * (HD * KVT_ROW) + d * KVT_ROW];

#pragma unroll 1
    for (int g = 0; g < TILE_ROWS; g += RG) {
        const size_t r0 = rowbase + (size_t)g * QKVO_COLS;

        float vn[RG];
#pragma unroll
        for (int i = 0; i < RG - 1; i++)
            vn[i] = __half2float(qkvo[r0 + (size_t)(i + 1) * QKVO_COLS + 512 + c]);
        vn[RG - 1] = (n0 + g + RG < NN)
                   ? __half2float(qkvo[r0 + (size_t)RG * QKVO_COLS + 512 + c]) : 0.f;

        float qv[RG], ov[RG];
#pragma unroll
        for (int i = 0; i < RG; i++) {
            qv[i] = __half2float(qkvo[r0 + (size_t)i * QKVO_COLS + c]);
            ov[i] = __half2float(qkvo[r0 + (size_t)i * QKVO_COLS + 768 + c]);
        }

        float qh[RG];
#pragma unroll
        for (int i = 0; i < RG; i++)
            qh[i] = (qv[i] > 0.f) ? (qv[i] + 1.f) : __expf(qv[i]);

        float zp[RG];
#pragma unroll
        for (int i = 0; i < RG; i++) zp[i] = qh[i] * km;
#pragma unroll
        for (int off = 16; off > 0; off >>= 1) {
#pragma unroll
            for (int i = 0; i < RG; i++)
                zp[i] += __shfl_xor_sync(0xffffffffu, zp[i], off);
        }

        // theta shift + stage qs to warp-private smem
#pragma unroll
        for (int i = 0; i < RG; i++) {
            float partner = __shfl_xor_sync(0xffffffffu, qh[i], 1);
            float sv = sinp[(n0 + g + i) * HD + d];
            float cv = cosp[(n0 + g + i) * HD + d];
            float rot = (d & 1) ? partner : -partner;
            sqs[h][i][d] = qh[i] * cv + rot * sv;
        }
        __syncwarp();

        // matvec: acc[i][e=d] = sum_dd qs[i][dd] * kvT[d][dd]
        float acc[RG];
#pragma unroll
        for (int i = 0; i < RG; i++) acc[i] = 0.f;
#pragma unroll
        for (int dq = 0; dq < 32; dq += 4) {
            float4 kvv = *(const float4*)&kvT[dq];
#pragma unroll
            for (int i = 0; i < RG; i++) {
                float4 qq = *(const float4*)&sqs[h][i][dq];
                acc[i] += qq.x * kvv.x + qq.y * kvv.y
                        + qq.z * kvv.z + qq.w * kvv.w;
            }
        }
        __syncwarp();   // before next group's sqs overwrite

#pragma unroll
        for (int i = 0; i < RG; i++) {
            float z = zp[i] * inv_scale_n;
            float coef = 1.f + 1.f / (z + 1e-6f);
            float prev = (i == 0) ? vp : ((i == 1) ? vc : vn[i - 2]);
            float cur  = (i == 0) ? vc : vn[i - 1];
            float next = vn[i];
            float res  = acc[i] * coef - z * vm;
            float lepe = prev * w0 + cur * w1 + next * w2 + bl;
            ph[(size_t)(b * NN + n0 + g + i) * INTERNAL + c] =
                __float2half((res + lepe) * ov[i]);
        }

        vp = vn[RG - 2];
        vc = vn[RG - 1];
    }
}

// ---------------- launch -----------------------------------------------------
extern "C" void kernel_launch(void* const* d_in, const int* in_sizes, int n_in,
                              void* d_out, int out_size)
{
    const float* x       = (const float*)d_in[0];
    const float* sinp    = (const float*)d_in[1];
    const float* cosp    = (const float*)d_in[2];
    const float* W_qkvo  = (const float*)d_in[3];
    const float* b_qkvo  = (const float*)d_in[4];
    const float* W_lepe  = (const float*)d_in[5];
    const float* b_lepe  = (const float*)d_in[6];
    const float* W_proj  = (const float*)d_in[7];
    const float* b_proj  = (const float*)d_in[8];
    float* out = (float*)d_out;

    __half *qkvo_p, *xh, *ph, *wqh, *pwh;
    cudaGetSymbolAddress((void**)&qkvo_p, g_qkvo);
    cudaGetSymbolAddress((void**)&xh,  g_xh);
    cudaGetSymbolAddress((void**)&ph,  g_ph);
    cudaGetSymbolAddress((void**)&wqh, g_wqh);
    cudaGetSymbolAddress((void**)&pwh, g_pwh);

    cudaFuncSetAttribute(gemm_h_kernel<__half>,
                         cudaFuncAttributeMaxDynamicSharedMemorySize, GEMM_SMEM_BYTES);
    cudaFuncSetAttribute(gemm_h_kernel<float>,
                         cudaFuncAttributeMaxDynamicSharedMemorySize, GEMM_SMEM_BYTES);
    cudaFuncSetAttribute(stats_kernel,
                         cudaFuncAttributeMaxDynamicSharedMemorySize, STATS_SMEM);

    zero_kernel<<<(BB * HH * HD * HD + 255) / 256, 256>>>();

    cvt_all_kernel<<<(CVT_N1 + CVT_N2 + CVT_N3 + 255) / 256, 256>>>(
        x, W_qkvo, W_proj, xh, wqh, pwh);

    // GEMM1: qkvo = x @ W_qkvo^T + b_qkvo   [32768 x 1024] -> fp16
    gemm_h_kernel<__half><<<dim3(QKVO_COLS / 128, MROWS / 128), 256, GEMM_SMEM_BYTES>>>(
        xh, wqh, b_qkvo, qkvo_p, MROWS, QKVO_COLS, DIMV);

    stats_kernel<<<dim3(BB * HH, 32), 256, STATS_SMEM>>>(qkvo_p, sinp, cosp);

    fuse_kernel<<<BB * (NN / TILE_ROWS), 256>>>(qkvo_p, sinp, cosp,
                                                W_lepe, b_lepe, ph);

    // GEMM2: out = pre @ W_proj^T + b_proj  [32768 x 256] -> fp32
    gemm_h_kernel<float><<<dim3(INTERNAL / 128, MROWS / 128), 256, GEMM_SMEM_BYTES>>>(
        ph, pwh, b_proj, out, MROWS, INTERNAL, DIMV);
}

// round 14
// speedup vs baseline: 3.1121x; 1.0228x over previous
#include <cuda_runtime.h>
#include <cuda_fp16.h>
#include <math.h>
#include <stdint.h>

#define BB 4
#define NN 8192
#define DIMV 256
#define HH 8
#define HD 32
#define INTERNAL 256
#define MROWS (BB * NN)        // 32768
#define QKVO_COLS 1024
#define SCALE_F 0.17677669529663687f

// ---------------- persistent device scratch (no allocations) ----------------
__device__ __half g_qkvo[(size_t)MROWS * QKVO_COLS];    // 67 MB fp16
__device__ __half g_xh [(size_t)MROWS * DIMV];
__device__ __half g_ph [(size_t)MROWS * INTERNAL];
__device__ __half g_wqh[(size_t)QKVO_COLS * DIMV];
__device__ __half g_pwh[(size_t)DIMV * INTERNAL];
__device__ float g_kv  [BB * HH * HD * HD];
__device__ float g_ksum[BB * HH * HD];
__device__ float g_vsum[BB * HH * HD];

__device__ __forceinline__ uint32_t smem_u32(const void* p) {
    uint32_t a;
    asm("{ .reg .u64 t; cvta.to.shared.u64 t, %1; cvt.u32.u64 %0, t; }"
        : "=r"(a) : "l"(p));
    return a;
}

__device__ __forceinline__ void ldmx4(uint32_t* r, uint32_t addr) {
    asm volatile("ldmatrix.sync.aligned.m8n8.x4.shared.b16 {%0,%1,%2,%3}, [%4];"
        : "=r"(r[0]), "=r"(r[1]), "=r"(r[2]), "=r"(r[3]) : "r"(addr));
}
__device__ __forceinline__ void ldmx2(uint32_t* r, uint32_t addr) {
    asm volatile("ldmatrix.sync.aligned.m8n8.x2.shared.b16 {%0,%1}, [%2];"
        : "=r"(r[0]), "=r"(r[1]) : "r"(addr));
}

__device__ __forceinline__ void mma16816h(float* d, const uint32_t* a,
                                          uint32_t b0, uint32_t b1) {
    asm volatile(
        "mma.sync.aligned.m16n8k16.row.col.f32.f16.f16.f32 "
        "{%0,%1,%2,%3}, {%4,%5,%6,%7}, {%8,%9}, {%0,%1,%2,%3};"
        : "+f"(d[0]), "+f"(d[1]), "+f"(d[2]), "+f"(d[3])
        : "r"(a[0]), "r"(a[1]), "r"(a[2]), "r"(a[3]), "r"(b0), "r"(b1));
}

__device__ __forceinline__ void cp16(uint32_t saddr, const void* gaddr) {
    asm volatile("cp.async.cg.shared.global [%0], [%1], 16;"
        :: "r"(saddr), "l"(gaddr) : "memory");
}
#define CP_COMMIT() asm volatile("cp.async.commit_group;" ::: "memory")
#define CP_WAIT(n)  asm volatile("cp.async.wait_group %0;" :: "n"(n) : "memory")

// ---------------- fused fp32->fp16 conversion + accumulator zeroing ---------
#define CVT_N1 (MROWS * DIMV / 4)
#define CVT_N2 (QKVO_COLS * DIMV / 4)
#define CVT_N3 (DIMV * INTERNAL / 4)
__global__ void __launch_bounds__(256)
cvt_all_kernel(const float* __restrict__ x, const float* __restrict__ wq,
               const float* __restrict__ pw, __half* __restrict__ xh,
               __half* __restrict__ wqh, __half* __restrict__ pwh)
{
    int i = blockIdx.x * 256 + threadIdx.x;
    // fold accumulator zeroing into the first blocks
    if (i < BB * HH * HD * HD) g_kv[i] = 0.f;
    if (i < BB * HH * HD) { g_ksum[i] = 0.f; g_vsum[i] = 0.f; }

    const float* s; __half* d; int j;
    if (i < CVT_N1) { s = x; d = xh; j = i; }
    else if (i < CVT_N1 + CVT_N2) { s = wq; d = wqh; j = i - CVT_N1; }
    else if (i < CVT_N1 + CVT_N2 + CVT_N3) { s = pw; d = pwh; j = i - CVT_N1 - CVT_N2; }
    else return;
    float4 v = ((const float4*)s)[j];
    __half2 h0 = __floats2half2_rn(v.x, v.y);
    __half2 h1 = __floats2half2_rn(v.z, v.w);
    uint2 o = { *reinterpret_cast<uint32_t*>(&h0), *reinterpret_cast<uint32_t*>(&h1) };
    ((uint2*)d)[j] = o;
}

// =================== HMMA GEMM (single fp16, 4-stage cp.async) ==============
#define ROWB 80
#define ST_A 0
#define ST_B 10240
#define STAGEB 20480
#define NSTAGE 4
#define GEMM_SMEM_BYTES (NSTAGE * STAGEB)   // 80 KB

template <typename OutT>
__global__ void __launch_bounds__(256)
gemm_h_kernel(const __half* __restrict__ A, const __half* __restrict__ Bw,
              const float* __restrict__ bias, OutT* __restrict__ C,
              int M, int Nn, int K)
{
    extern __shared__ char sm[];
    const uint32_t smb = smem_u32(sm);
    const int tid  = threadIdx.x;
    const int wid  = tid >> 5;
    const int lane = tid & 31;
    const int m0 = blockIdx.y * 128;
    const int n0 = blockIdx.x * 128;
    const int wm0 = (wid & 3) * 32;
    const int wn0 = (wid >> 2) * 64;

    const int a_row = (lane & 7) + ((lane >> 3) & 1) * 8;
    const int a_kh  = (lane >> 4) * 8;
    const int b_row = (lane & 7) + ((lane >> 4) & 1) * 8;
    const int b_kh  = ((lane >> 3) & 1) * 8;

    float acc[2][8][4];
#pragma unroll
    for (int i = 0; i < 2; i++)
#pragma unroll
        for (int j = 0; j < 8; j++)
#pragma unroll
            for (int l = 0; l < 4; l++) acc[i][j][l] = 0.f;

    const int NCH = K / 32;
    const int row2 = tid >> 2;
    const int seg  = tid & 3;

#define LOAD_STAGE(c, buf) do {                                              \
    int k0 = (c) * 32;                                                       \
    uint32_t base = smb + (buf) * STAGEB;                                    \
    _Pragma("unroll")                                                        \
    for (int i = 0; i < 2; i++) {                                            \
        int r = row2 + i * 64;                                               \
        uint32_t so = r * ROWB + seg * 16;                                   \
        cp16(base + ST_A + so, A  + (size_t)(m0 + r) * K + k0 + seg * 8);    \
        cp16(base + ST_B + so, Bw + (size_t)(n0 + r) * K + k0 + seg * 8);    \
    }                                                                        \
    CP_COMMIT();                                                             \
} while (0)

    LOAD_STAGE(0, 0);
    LOAD_STAGE(1, 1);
    LOAD_STAGE(2, 2);

    for (int c = 0; c < NCH; c++) {
        CP_WAIT(2);
        __syncthreads();   // all warps past iter c-1's MMAs; stage c visible
        const uint32_t base = smb + (c & (NSTAGE - 1)) * STAGEB;

#pragma unroll
        for (int ks = 0; ks < 2; ks++) {
            uint32_t af[2][4], bf[4][4];
#pragma unroll
            for (int mf = 0; mf < 2; mf++)
                ldmx4(af[mf], base + ST_A + (wm0 + mf * 16 + a_row) * ROWB
                                        + (ks * 16 + a_kh) * 2);
#pragma unroll
            for (int nf2 = 0; nf2 < 4; nf2++)
                ldmx4(bf[nf2], base + ST_B + (wn0 + nf2 * 16 + b_row) * ROWB
                                          + (ks * 16 + b_kh) * 2);
#pragma unroll
            for (int nf2 = 0; nf2 < 4; nf2++)
#pragma unroll
                for (int mf = 0; mf < 2; mf++)
#pragma unroll
                    for (int s = 0; s < 2; s++)
                        mma16816h(acc[mf][nf2 * 2 + s], af[mf],
                                  bf[nf2][s * 2], bf[nf2][s * 2 + 1]);
        }
        // No second barrier: LOAD(c+3) writes buf (c-1)&3, which no warp can
        // be reading (readers <=c-1 are barred by the top sync; readers >=c+3
        // are unreachable until this warp passes future syncs).
        if (c + 3 < NCH) LOAD_STAGE(c + 3, (c + 3) & (NSTAGE - 1));
        else CP_COMMIT();
    }
#undef LOAD_STAGE

    const int rr = lane >> 2;
    const int cc = (lane & 3) * 2;
#pragma unroll
    for (int mf = 0; mf < 2; mf++) {
        int r0 = m0 + wm0 + mf * 16 + rr;
#pragma unroll
        for (int nf = 0; nf < 8; nf++) {
            int col = n0 + wn0 + nf * 8 + cc;
            float b0 = bias[col], b1 = bias[col + 1];
            float o00 = acc[mf][nf][0] + b0, o01 = acc[mf][nf][1] + b1;
            float o10 = acc[mf][nf][2] + b0, o11 = acc[mf][nf][3] + b1;
            if (sizeof(OutT) == 2) {
                __half2 p0 = __floats2half2_rn(o00, o01);
                __half2 p1 = __floats2half2_rn(o10, o11);
                *(__half2*)&C[(size_t)r0 * Nn + col] = p0;
                *(__half2*)&C[(size_t)(r0 + 8) * Nn + col] = p1;
            } else {
                float2 v0 = {o00, o01}, v1 = {o10, o11};
                *(float2*)&C[(size_t)r0 * Nn + col] = v0;
                *(float2*)&C[(size_t)(r0 + 8) * Nn + col] = v1;
            }
        }
    }
}

// ---------------- stats v5: tensor-core kv_state, smem reuse ----------------
#define STW 5120
#define KVROW 34
#define STATS_SMEM (8 * STW)       // 40960 B

__global__ void __launch_bounds__(256)
stats_kernel(const __half* __restrict__ qkvo,
             const float* __restrict__ sinp, const float* __restrict__ cosp)
{
    extern __shared__ char ssm[];
    const int tid  = threadIdx.x;
    const int w    = tid >> 5;
    const int lane = tid & 31;
    const int bh = blockIdx.x;
    const int b = bh >> 3, h = bh & 7;
    const int nb = blockIdx.y * 256 + w * 32;

    char* smw = ssm + w * STW;
    char* smv = smw + 2560;
    const uint32_t ks_u = smem_u32(smw);
    const uint32_t v_u  = smem_u32(smv);

    const __half* kbase = qkvo + (size_t)(b * NN + nb) * QKVO_COLS + 256 + h * 32 + lane;
    const __half* vbase = kbase + 256;

    float ksum_acc = 0.f, vsum_acc = 0.f;

#pragma unroll
    for (int g = 0; g < 4; g++) {
        float kr[8], vr[8], sv[8], cv[8];
#pragma unroll
        for (int i = 0; i < 8; i++) {
            kr[i] = __half2float(kbase[(size_t)(g * 8 + i) * QKVO_COLS]);
            vr[i] = __half2float(vbase[(size_t)(g * 8 + i) * QKVO_COLS]);
        }
#pragma unroll
        for (int i = 0; i < 8; i++) {
            sv[i] = sinp[(nb + g * 8 + i) * HD + lane];
            cv[i] = cosp[(nb + g * 8 + i) * HD + lane];
        }
        __half ksh[8], vh[8];
#pragma unroll
        for (int i = 0; i < 8; i++) {
            float kh = (kr[i] > 0.f) ? (kr[i] + 1.f) : __expf(kr[i]);
            ksum_acc += kh;
            vsum_acc += vr[i];
            float partner = __shfl_xor_sync(0xffffffffu, kh, 1);
            float rot = (lane & 1) ? partner : -partner;
            ksh[i] = __float2half(kh * cv[i] + rot * sv[i]);
            vh[i]  = __float2half(vr[i]);
        }
#pragma unroll
        for (int i = 0; i < 8; i += 2) {
            int n = g * 8 + i;
            __half2 pk = {ksh[i], ksh[i + 1]};
            __half2 pv = {vh[i],  vh[i + 1]};
            *(__half2*)(smw + lane * 80 + n * 2) = pk;
            *(__half2*)(smv + lane * 80 + n * 2) = pv;
        }
    }
    __syncwarp();

    float kv[2][4][4];
#pragma unroll
    for (int mt = 0; mt < 2; mt++)
#pragma unroll
        for (int et = 0; et < 4; et++)
#pragma unroll
            for (int l = 0; l < 4; l++) kv[mt][et][l] = 0.f;

#pragma unroll
    for (int ks = 0; ks < 2; ks++) {
        const int k0 = ks * 16;
        uint32_t af[2][4];
#pragma unroll
        for (int mt = 0; mt < 2; mt++)
            ldmx4(af[mt], ks_u + (mt * 16 + (lane & 7) + ((lane >> 3) & 1) * 8) * 80
                               + (k0 + (lane >> 4) * 8) * 2);
#pragma unroll
        for (int et = 0; et < 4; et++) {
            uint32_t bf[2];
            ldmx2(bf, v_u + (et * 8 + (lane & 7)) * 80
                          + (k0 + ((lane >> 3) & 1) * 8) * 2);
#pragma unroll
            for (int mt = 0; mt < 2; mt++)
                mma16816h(kv[mt][et], af[mt], bf[0], bf[1]);
        }
    }
    __syncwarp();

    float* kvw = (float*)(ssm + w * STW);
    const int dm = lane >> 2;
    const int de = (lane & 3) * 2;
#pragma unroll
    for (int mt = 0; mt < 2; mt++)
#pragma unroll
        for (int et = 0; et < 4; et++) {
            float2 lo = {kv[mt][et][0], kv[mt][et][1]};
            float2 hi = {kv[mt][et][2], kv[mt][et][3]};
            *(float2*)&kvw[(mt * 16 + dm) * KVROW + et * 8 + de] = lo;
            *(float2*)&kvw[(mt * 16 + dm + 8) * KVROW + et * 8 + de] = hi;
        }

    atomicAdd(&g_ksum[bh * HD + lane], ksum_acc);
    atomicAdd(&g_vsum[bh * HD + lane], vsum_acc);

    __syncthreads();

    const float* kvs = (const float*)ssm;
#pragma unroll
    for (int o = 0; o < 4; o++) {
        int idx = o * 256 + tid;
        int m = idx >> 5, e = idx & 31;
        float s = 0.f;
#pragma unroll
        for (int ww = 0; ww < 8; ww++)
            s += kvs[ww * (STW / 4) + m * KVROW + e];
        atomicAdd(&g_kv[bh * (HD * HD) + m * HD + e], s);
    }
}

// ---------------- fused per-token epilogue (smem matvec, fp16 qkvo) ---------
// TILE_ROWS=32 -> grid 1024 -> occupancy reaches the 5-CTA/SM smem cap.
#define TILE_ROWS 32
#define RG 4
#define KVT_ROW 36
__global__ void __launch_bounds__(256)
fuse_kernel(const __half* __restrict__ qkvo,
            const float* __restrict__ sinp, const float* __restrict__ cosp,
            const float* __restrict__ W_lepe, const float* __restrict__ b_lepe,
            __half* __restrict__ ph)
{
    __shared__ float skvT[HH * HD * KVT_ROW];   // 36864 B
    __shared__ float sqs[HH][RG][HD];           // 4096 B

    const int tile = blockIdx.x;
    const int b  = tile / (NN / TILE_ROWS);
    const int t  = tile % (NN / TILE_ROWS);
    const int n0 = t * TILE_ROWS;
    const int c  = threadIdx.x;
    const int h  = c >> 5;
    const int d  = c & 31;
    const float inv_scale_n = SCALE_F / (float)NN;

    const int base_kv = b * HH * HD * HD;
#pragma unroll
    for (int ii = 0; ii < HH * HD * HD / 256; ii++) {
        int i = ii * 256 + c;
        int hh = i >> 10, dd = (i >> 5) & 31, e = i & 31;
        skvT[hh * (HD * KVT_ROW) + e * KVT_ROW + dd] =
            g_kv[base_kv + i] * inv_scale_n;
    }

    const float km = g_ksum[(b * HH + h) * HD + d];
    const float vm = g_vsum[(b * HH + h) * HD + d] * (1.f / NN);
    __syncthreads();

    const float w0 = W_lepe[c * 3 + 0];
    const float w1 = W_lepe[c * 3 + 1];
    const float w2 = W_lepe[c * 3 + 2];
    const float bl = b_lepe[c];

    const size_t rowbase = (size_t)(b * NN + n0) * QKVO_COLS;
    float vp = (n0 > 0) ? __half2float(qkvo[rowbase - QKVO_COLS + 512 + c]) : 0.f;
    float vc = __half2float(qkvo[rowbase + 512 + c]);

    const float* kvT = &skvT[h * (HD * KVT_ROW) + d * KVT_ROW];

#pragma unroll 1
    for (int g = 0; g < TILE_ROWS; g += RG) {
        const size_t r0 = rowbase + (size_t)g * QKVO_COLS;

        float vn[RG];
#pragma unroll
        for (int i = 0; i < RG - 1; i++)
            vn[i] = __half2float(qkvo[r0 + (size_t)(i + 1) * QKVO_COLS + 512 + c]);
        vn[RG - 1] = (n0 + g + RG < NN)
                   ? __half2float(qkvo[r0 + (size_t)RG * QKVO_COLS + 512 + c]) : 0.f;

        float qv[RG], ov[RG];
#pragma unroll
        for (int i = 0; i < RG; i++) {
            qv[i] = __half2float(qkvo[r0 + (size_t)i * QKVO_COLS + c]);
            ov[i] = __half2float(qkvo[r0 + (size_t)i * QKVO_COLS + 768 + c]);
        }

        float qh[RG];
#pragma unroll
        for (int i = 0; i < RG; i++)
            qh[i] = (qv[i] > 0.f) ? (qv[i] + 1.f) : __expf(qv[i]);

        float zp[RG];
#pragma unroll
        for (int i = 0; i < RG; i++) zp[i] = qh[i] * km;
#pragma unroll
        for (int off = 16; off > 0; off >>= 1) {
#pragma unroll
            for (int i = 0; i < RG; i++)
                zp[i] += __shfl_xor_sync(0xffffffffu, zp[i], off);
        }

#pragma unroll
        for (int i = 0; i < RG; i++) {
            float partner = __shfl_xor_sync(0xffffffffu, qh[i], 1);
            float sv = sinp[(n0 + g + i) * HD + d];
            float cv = cosp[(n0 + g + i) * HD + d];
            float rot = (d & 1) ? partner : -partner;
            sqs[h][i][d] = qh[i] * cv + rot * sv;
        }
        __syncwarp();

        float acc[RG];
#pragma unroll
        for (int i = 0; i < RG; i++) acc[i] = 0.f;
#pragma unroll
        for (int dq = 0; dq < 32; dq += 4) {
            float4 kvv = *(const float4*)&kvT[dq];
#pragma unroll
            for (int i = 0; i < RG; i++) {
                float4 qq = *(const float4*)&sqs[h][i][dq];
                acc[i] += qq.x * kvv.x + qq.y * kvv.y
                        + qq.z * kvv.z + qq.w * kvv.w;
            }
        }
        __syncwarp();

#pragma unroll
        for (int i = 0; i < RG; i++) {
            float z = zp[i] * inv_scale_n;
            float coef = 1.f + 1.f / (z + 1e-6f);
            float prev = (i == 0) ? vp : ((i == 1) ? vc : vn[i - 2]);
            float cur  = (i == 0) ? vc : vn[i - 1];
            float next = vn[i];
            float res  = acc[i] * coef - z * vm;
            float lepe = prev * w0 + cur * w1 + next * w2 + bl;
            ph[(size_t)(b * NN + n0 + g + i) * INTERNAL + c] =
                __float2half((res + lepe) * ov[i]);
        }

        vp = vn[RG - 2];
        vc = vn[RG - 1];
    }
}

// ---------------- launch -----------------------------------------------------
extern "C" void kernel_launch(void* const* d_in, const int* in_sizes, int n_in,
                              void* d_out, int out_size)
{
    const float* x       = (const float*)d_in[0];
    const float* sinp    = (const float*)d_in[1];
    const float* cosp    = (const float*)d_in[2];
    const float* W_qkvo  = (const float*)d_in[3];
    const float* b_qkvo  = (const float*)d_in[4];
    const float* W_lepe  = (const float*)d_in[5];
    const float* b_lepe  = (const float*)d_in[6];
    const float* W_proj  = (const float*)d_in[7];
    const float* b_proj  = (const float*)d_in[8];
    float* out = (float*)d_out;

    __half *qkvo_p, *xh, *ph, *wqh, *pwh;
    cudaGetSymbolAddress((void**)&qkvo_p, g_qkvo);
    cudaGetSymbolAddress((void**)&xh,  g_xh);
    cudaGetSymbolAddress((void**)&ph,  g_ph);
    cudaGetSymbolAddress((void**)&wqh, g_wqh);
    cudaGetSymbolAddress((void**)&pwh, g_pwh);

    cudaFuncSetAttribute(gemm_h_kernel<__half>,
                         cudaFuncAttributeMaxDynamicSharedMemorySize, GEMM_SMEM_BYTES);
    cudaFuncSetAttribute(gemm_h_kernel<float>,
                         cudaFuncAttributeMaxDynamicSharedMemorySize, GEMM_SMEM_BYTES);
    cudaFuncSetAttribute(stats_kernel,
                         cudaFuncAttributeMaxDynamicSharedMemorySize, STATS_SMEM);

    // conversion + accumulator zeroing in one launch
    cvt_all_kernel<<<(CVT_N1 + CVT_N2 + CVT_N3 + 255) / 256, 256>>>(
        x, W_qkvo, W_proj, xh, wqh, pwh);

    // GEMM1: qkvo = x @ W_qkvo^T + b_qkvo   [32768 x 1024] -> fp16
    gemm_h_kernel<__half><<<dim3(QKVO_COLS / 128, MROWS / 128), 256, GEMM_SMEM_BYTES>>>(
        xh, wqh, b_qkvo, qkvo_p, MROWS, QKVO_COLS, DIMV);

    stats_kernel<<<dim3(BB * HH, 32), 256, STATS_SMEM>>>(qkvo_p, sinp, cosp);

    fuse_kernel<<<BB * (NN / TILE_ROWS), 256>>>(qkvo_p, sinp, cosp,
                                                W_lepe, b_lepe, ph);

    // GEMM2: out = pre @ W_proj^T + b_proj  [32768 x 256] -> fp32
    gemm_h_kernel<float><<<dim3(INTERNAL / 128, MROWS / 128), 256, GEMM_SMEM_BYTES>>>(
        ph, pwh, b_proj, out, MROWS, INTERNAL, DIMV);
}

// round 15
// speedup vs baseline: 3.1353x; 1.0074x over previous
#include <cuda_runtime.h>
#include <cuda_fp16.h>
#include <math.h>
#include <stdint.h>

#define BB 4
#define NN 8192
#define DIMV 256
#define HH 8
#define HD 32
#define INTERNAL 256
#define MROWS (BB * NN)        // 32768
#define QKVO_COLS 1024
#define SCALE_F 0.17677669529663687f

// ---------------- persistent device scratch (no allocations) ----------------
__device__ __half g_qkvo[(size_t)MROWS * QKVO_COLS];    // 67 MB fp16
__device__ __half g_xh [(size_t)MROWS * DIMV];
__device__ __half g_ph [(size_t)MROWS * INTERNAL];
__device__ __half g_wqh[(size_t)QKVO_COLS * DIMV];
__device__ __half g_pwh[(size_t)DIMV * INTERNAL];
__device__ float g_kv  [BB * HH * HD * HD];
__device__ float g_ksum[BB * HH * HD];
__device__ float g_vsum[BB * HH * HD];

__device__ __forceinline__ uint32_t smem_u32(const void* p) {
    uint32_t a;
    asm("{ .reg .u64 t; cvta.to.shared.u64 t, %1; cvt.u32.u64 %0, t; }"
        : "=r"(a) : "l"(p));
    return a;
}

__device__ __forceinline__ void ldmx4(uint32_t* r, uint32_t addr) {
    asm volatile("ldmatrix.sync.aligned.m8n8.x4.shared.b16 {%0,%1,%2,%3}, [%4];"
        : "=r"(r[0]), "=r"(r[1]), "=r"(r[2]), "=r"(r[3]) : "r"(addr));
}
__device__ __forceinline__ void ldmx2(uint32_t* r, uint32_t addr) {
    asm volatile("ldmatrix.sync.aligned.m8n8.x2.shared.b16 {%0,%1}, [%2];"
        : "=r"(r[0]), "=r"(r[1]) : "r"(addr));
}

__device__ __forceinline__ void mma16816h(float* d, const uint32_t* a,
                                          uint32_t b0, uint32_t b1) {
    asm volatile(
        "mma.sync.aligned.m16n8k16.row.col.f32.f16.f16.f32 "
        "{%0,%1,%2,%3}, {%4,%5,%6,%7}, {%8,%9}, {%0,%1,%2,%3};"
        : "+f"(d[0]), "+f"(d[1]), "+f"(d[2]), "+f"(d[3])
        : "r"(a[0]), "r"(a[1]), "r"(a[2]), "r"(a[3]), "r"(b0), "r"(b1));
}

__device__ __forceinline__ void cp16(uint32_t saddr, const void* gaddr) {
    asm volatile("cp.async.cg.shared.global [%0], [%1], 16;"
        :: "r"(saddr), "l"(gaddr) : "memory");
}
#define CP_COMMIT() asm volatile("cp.async.commit_group;" ::: "memory")
#define CP_WAIT(n)  asm volatile("cp.async.wait_group %0;" :: "n"(n) : "memory")

// ---------------- fused fp32->fp16 conversion + accumulator zeroing ---------
#define CVT_N1 (MROWS * DIMV / 4)
#define CVT_N2 (QKVO_COLS * DIMV / 4)
#define CVT_N3 (DIMV * INTERNAL / 4)
__global__ void __launch_bounds__(256)
cvt_all_kernel(const float* __restrict__ x, const float* __restrict__ wq,
               const float* __restrict__ pw, __half* __restrict__ xh,
               __half* __restrict__ wqh, __half* __restrict__ pwh)
{
    int i = blockIdx.x * 256 + threadIdx.x;
    if (i < BB * HH * HD * HD) g_kv[i] = 0.f;
    if (i < BB * HH * HD) { g_ksum[i] = 0.f; g_vsum[i] = 0.f; }

    const float* s; __half* d; int j;
    if (i < CVT_N1) { s = x; d = xh; j = i; }
    else if (i < CVT_N1 + CVT_N2) { s = wq; d = wqh; j = i - CVT_N1; }
    else if (i < CVT_N1 + CVT_N2 + CVT_N3) { s = pw; d = pwh; j = i - CVT_N1 - CVT_N2; }
    else return;
    float4 v = ((const float4*)s)[j];
    __half2 h0 = __floats2half2_rn(v.x, v.y);
    __half2 h1 = __floats2half2_rn(v.z, v.w);
    uint2 o = { *reinterpret_cast<uint32_t*>(&h0), *reinterpret_cast<uint32_t*>(&h1) };
    ((uint2*)d)[j] = o;
}

// =================== HMMA GEMM (single fp16, 4-stage cp.async) ==============
#define ROWB 80
#define ST_A 0
#define ST_B 10240
#define STAGEB 20480
#define NSTAGE 4
#define GEMM_SMEM_BYTES (NSTAGE * STAGEB)   // 80 KB

template <typename OutT>
__global__ void __launch_bounds__(256)
gemm_h_kernel(const __half* __restrict__ A, const __half* __restrict__ Bw,
              const float* __restrict__ bias, OutT* __restrict__ C,
              int M, int Nn, int K)
{
    extern __shared__ char sm[];
    const uint32_t smb = smem_u32(sm);
    const int tid  = threadIdx.x;
    const int wid  = tid >> 5;
    const int lane = tid & 31;
    const int m0 = blockIdx.y * 128;
    const int n0 = blockIdx.x * 128;
    const int wm0 = (wid & 3) * 32;
    const int wn0 = (wid >> 2) * 64;

    const int a_row = (lane & 7) + ((lane >> 3) & 1) * 8;
    const int a_kh  = (lane >> 4) * 8;
    const int b_row = (lane & 7) + ((lane >> 4) & 1) * 8;
    const int b_kh  = ((lane >> 3) & 1) * 8;

    float acc[2][8][4];
#pragma unroll
    for (int i = 0; i < 2; i++)
#pragma unroll
        for (int j = 0; j < 8; j++)
#pragma unroll
            for (int l = 0; l < 4; l++) acc[i][j][l] = 0.f;

    const int NCH = K / 32;
    const int row2 = tid >> 2;
    const int seg  = tid & 3;

#define LOAD_STAGE(c, buf) do {                                              \
    int k0 = (c) * 32;                                                       \
    uint32_t base = smb + (buf) * STAGEB;                                    \
    _Pragma("unroll")                                                        \
    for (int i = 0; i < 2; i++) {                                            \
        int r = row2 + i * 64;                                               \
        uint32_t so = r * ROWB + seg * 16;                                   \
        cp16(base + ST_A + so, A  + (size_t)(m0 + r) * K + k0 + seg * 8);    \
        cp16(base + ST_B + so, Bw + (size_t)(n0 + r) * K + k0 + seg * 8);    \
    }                                                                        \
    CP_COMMIT();                                                             \
} while (0)

    LOAD_STAGE(0, 0);
    LOAD_STAGE(1, 1);
    LOAD_STAGE(2, 2);

    for (int c = 0; c < NCH; c++) {
        CP_WAIT(2);
        __syncthreads();   // all warps past iter c-1's MMAs; stage c visible
        const uint32_t base = smb + (c & (NSTAGE - 1)) * STAGEB;

#pragma unroll
        for (int ks = 0; ks < 2; ks++) {
            uint32_t af[2][4], bf[4][4];
#pragma unroll
            for (int mf = 0; mf < 2; mf++)
                ldmx4(af[mf], base + ST_A + (wm0 + mf * 16 + a_row) * ROWB
                                        + (ks * 16 + a_kh) * 2);
#pragma unroll
            for (int nf2 = 0; nf2 < 4; nf2++)
                ldmx4(bf[nf2], base + ST_B + (wn0 + nf2 * 16 + b_row) * ROWB
                                          + (ks * 16 + b_kh) * 2);
#pragma unroll
            for (int nf2 = 0; nf2 < 4; nf2++)
#pragma unroll
                for (int mf = 0; mf < 2; mf++)
#pragma unroll
                    for (int s = 0; s < 2; s++)
                        mma16816h(acc[mf][nf2 * 2 + s], af[mf],
                                  bf[nf2][s * 2], bf[nf2][s * 2 + 1]);
        }
        // No second barrier: LOAD(c+3) writes buf (c-1)&3, which no warp can
        // still be reading (readers <=c-1 are barred by the top sync).
        if (c + 3 < NCH) LOAD_STAGE(c + 3, (c + 3) & (NSTAGE - 1));
        else CP_COMMIT();
    }
#undef LOAD_STAGE

    const int rr = lane >> 2;
    const int cc = (lane & 3) * 2;
#pragma unroll
    for (int mf = 0; mf < 2; mf++) {
        int r0 = m0 + wm0 + mf * 16 + rr;
#pragma unroll
        for (int nf = 0; nf < 8; nf++) {
            int col = n0 + wn0 + nf * 8 + cc;
            float b0 = bias[col], b1 = bias[col + 1];
            float o00 = acc[mf][nf][0] + b0, o01 = acc[mf][nf][1] + b1;
            float o10 = acc[mf][nf][2] + b0, o11 = acc[mf][nf][3] + b1;
            if (sizeof(OutT) == 2) {
                __half2 p0 = __floats2half2_rn(o00, o01);
                __half2 p1 = __floats2half2_rn(o10, o11);
                *(__half2*)&C[(size_t)r0 * Nn + col] = p0;
                *(__half2*)&C[(size_t)(r0 + 8) * Nn + col] = p1;
            } else {
                float2 v0 = {o00, o01}, v1 = {o10, o11};
                *(float2*)&C[(size_t)r0 * Nn + col] = v0;
                *(float2*)&C[(size_t)(r0 + 8) * Nn + col] = v1;
            }
        }
    }
}

// ---------------- stats v5: tensor-core kv_state, smem reuse ----------------
#define STW 5120
#define KVROW 34
#define STATS_SMEM (8 * STW)       // 40960 B

__global__ void __launch_bounds__(256)
stats_kernel(const __half* __restrict__ qkvo,
             const float* __restrict__ sinp, const float* __restrict__ cosp)
{
    extern __shared__ char ssm[];
    const int tid  = threadIdx.x;
    const int w    = tid >> 5;
    const int lane = tid & 31;
    const int bh = blockIdx.x;
    const int b = bh >> 3, h = bh & 7;
    const int nb = blockIdx.y * 256 + w * 32;

    char* smw = ssm + w * STW;
    char* smv = smw + 2560;
    const uint32_t ks_u = smem_u32(smw);
    const uint32_t v_u  = smem_u32(smv);

    const __half* kbase = qkvo + (size_t)(b * NN + nb) * QKVO_COLS + 256 + h * 32 + lane;
    const __half* vbase = kbase + 256;

    float ksum_acc = 0.f, vsum_acc = 0.f;

#pragma unroll
    for (int g = 0; g < 4; g++) {
        float kr[8], vr[8], sv[8], cv[8];
#pragma unroll
        for (int i = 0; i < 8; i++) {
            kr[i] = __half2float(kbase[(size_t)(g * 8 + i) * QKVO_COLS]);
            vr[i] = __half2float(vbase[(size_t)(g * 8 + i) * QKVO_COLS]);
        }
#pragma unroll
        for (int i = 0; i < 8; i++) {
            sv[i] = sinp[(nb + g * 8 + i) * HD + lane];
            cv[i] = cosp[(nb + g * 8 + i) * HD + lane];
        }
        __half ksh[8], vh[8];
#pragma unroll
        for (int i = 0; i < 8; i++) {
            float kh = (kr[i] > 0.f) ? (kr[i] + 1.f) : __expf(kr[i]);
            ksum_acc += kh;
            vsum_acc += vr[i];
            float partner = __shfl_xor_sync(0xffffffffu, kh, 1);
            float rot = (lane & 1) ? partner : -partner;
            ksh[i] = __float2half(kh * cv[i] + rot * sv[i]);
            vh[i]  = __float2half(vr[i]);
        }
#pragma unroll
        for (int i = 0; i < 8; i += 2) {
            int n = g * 8 + i;
            __half2 pk = {ksh[i], ksh[i + 1]};
            __half2 pv = {vh[i],  vh[i + 1]};
            *(__half2*)(smw + lane * 80 + n * 2) = pk;
            *(__half2*)(smv + lane * 80 + n * 2) = pv;
        }
    }
    __syncwarp();

    float kv[2][4][4];
#pragma unroll
    for (int mt = 0; mt < 2; mt++)
#pragma unroll
        for (int et = 0; et < 4; et++)
#pragma unroll
            for (int l = 0; l < 4; l++) kv[mt][et][l] = 0.f;

#pragma unroll
    for (int ks = 0; ks < 2; ks++) {
        const int k0 = ks * 16;
        uint32_t af[2][4];
#pragma unroll
        for (int mt = 0; mt < 2; mt++)
            ldmx4(af[mt], ks_u + (mt * 16 + (lane & 7) + ((lane >> 3) & 1) * 8) * 80
                               + (k0 + (lane >> 4) * 8) * 2);
#pragma unroll
        for (int et = 0; et < 4; et++) {
            uint32_t bf[2];
            ldmx2(bf, v_u + (et * 8 + (lane & 7)) * 80
                          + (k0 + ((lane >> 3) & 1) * 8) * 2);
#pragma unroll
            for (int mt = 0; mt < 2; mt++)
                mma16816h(kv[mt][et], af[mt], bf[0], bf[1]);
        }
    }
    __syncwarp();

    float* kvw = (float*)(ssm + w * STW);
    const int dm = lane >> 2;
    const int de = (lane & 3) * 2;
#pragma unroll
    for (int mt = 0; mt < 2; mt++)
#pragma unroll
        for (int et = 0; et < 4; et++) {
            float2 lo = {kv[mt][et][0], kv[mt][et][1]};
            float2 hi = {kv[mt][et][2], kv[mt][et][3]};
            *(float2*)&kvw[(mt * 16 + dm) * KVROW + et * 8 + de] = lo;
            *(float2*)&kvw[(mt * 16 + dm + 8) * KVROW + et * 8 + de] = hi;
        }

    atomicAdd(&g_ksum[bh * HD + lane], ksum_acc);
    atomicAdd(&g_vsum[bh * HD + lane], vsum_acc);

    __syncthreads();

    const float* kvs = (const float*)ssm;
#pragma unroll
    for (int o = 0; o < 4; o++) {
        int idx = o * 256 + tid;
        int m = idx >> 5, e = idx & 31;
        float s = 0.f;
#pragma unroll
        for (int ww = 0; ww < 8; ww++)
            s += kvs[ww * (STW / 4) + m * KVROW + e];
        atomicAdd(&g_kv[bh * (HD * HD) + m * HD + e], s);
    }
}

// ---------------- fused per-token epilogue (smem matvec, fp16 qkvo) ---------
// TILE_ROWS=64 (measured-best): 512 blocks amortize the kv staging 2x better
// than 32-row tiles; staging cost dominates over residency here.
#define TILE_ROWS 64
#define RG 4
#define KVT_ROW 36
__global__ void __launch_bounds__(256)
fuse_kernel(const __half* __restrict__ qkvo,
            const float* __restrict__ sinp, const float* __restrict__ cosp,
            const float* __restrict__ W_lepe, const float* __restrict__ b_lepe,
            __half* __restrict__ ph)
{
    __shared__ float skvT[HH * HD * KVT_ROW];   // 36864 B
    __shared__ float sqs[HH][RG][HD];           // 4096 B

    const int tile = blockIdx.x;
    const int b  = tile / (NN / TILE_ROWS);
    const int t  = tile % (NN / TILE_ROWS);
    const int n0 = t * TILE_ROWS;
    const int c  = threadIdx.x;
    const int h  = c >> 5;
    const int d  = c & 31;
    const float inv_scale_n = SCALE_F / (float)NN;

    const int base_kv = b * HH * HD * HD;
#pragma unroll
    for (int ii = 0; ii < HH * HD * HD / 256; ii++) {
        int i = ii * 256 + c;
        int hh = i >> 10, dd = (i >> 5) & 31, e = i & 31;
        skvT[hh * (HD * KVT_ROW) + e * KVT_ROW + dd] =
            g_kv[base_kv + i] * inv_scale_n;
    }

    const float km = g_ksum[(b * HH + h) * HD + d];
    const float vm = g_vsum[(b * HH + h) * HD + d] * (1.f / NN);
    __syncthreads();

    const float w0 = W_lepe[c * 3 + 0];
    const float w1 = W_lepe[c * 3 + 1];
    const float w2 = W_lepe[c * 3 + 2];
    const float bl = b_lepe[c];

    const size_t rowbase = (size_t)(b * NN + n0) * QKVO_COLS;
    float vp = (n0 > 0) ? __half2float(qkvo[rowbase - QKVO_COLS + 512 + c]) : 0.f;
    float vc = __half2float(qkvo[rowbase + 512 + c]);

    const float* kvT = &skvT[h * (HD * KVT_ROW) + d * KVT_ROW];

#pragma unroll 1
    for (int g = 0; g < TILE_ROWS; g += RG) {
        const size_t r0 = rowbase + (size_t)g * QKVO_COLS;

        float vn[RG];
#pragma unroll
        for (int i = 0; i < RG - 1; i++)
            vn[i] = __half2float(qkvo[r0 + (size_t)(i + 1) * QKVO_COLS + 512 + c]);
        vn[RG - 1] = (n0 + g + RG < NN)
                   ? __half2float(qkvo[r0 + (size_t)RG * QKVO_COLS + 512 + c]) : 0.f;

        float qv[RG], ov[RG];
#pragma unroll
        for (int i = 0; i < RG; i++) {
            qv[i] = __half2float(qkvo[r0 + (size_t)i * QKVO_COLS + c]);
            ov[i] = __half2float(qkvo[r0 + (size_t)i * QKVO_COLS + 768 + c]);
        }

        float qh[RG];
#pragma unroll
        for (int i = 0; i < RG; i++)
            qh[i] = (qv[i] > 0.f) ? (qv[i] + 1.f) : __expf(qv[i]);

        float zp[RG];
#pragma unroll
        for (int i = 0; i < RG; i++) zp[i] = qh[i] * km;
#pragma unroll
        for (int off = 16; off > 0; off >>= 1) {
#pragma unroll
            for (int i = 0; i < RG; i++)
                zp[i] += __shfl_xor_sync(0xffffffffu, zp[i], off);
        }

#pragma unroll
        for (int i = 0; i < RG; i++) {
            float partner = __shfl_xor_sync(0xffffffffu, qh[i], 1);
            float sv = sinp[(n0 + g + i) * HD + d];
            float cv = cosp[(n0 + g + i) * HD + d];
            float rot = (d & 1) ? partner : -partner;
            sqs[h][i][d] = qh[i] * cv + rot * sv;
        }
        __syncwarp();

        float acc[RG];
#pragma unroll
        for (int i = 0; i < RG; i++) acc[i] = 0.f;
#pragma unroll
        for (int dq = 0; dq < 32; dq += 4) {
            float4 kvv = *(const float4*)&kvT[dq];
#pragma unroll
            for (int i = 0; i < RG; i++) {
                float4 qq = *(const float4*)&sqs[h][i][dq];
                acc[i] += qq.x * kvv.x + qq.y * kvv.y
                        + qq.z * kvv.z + qq.w * kvv.w;
            }
        }
        __syncwarp();

#pragma unroll
        for (int i = 0; i < RG; i++) {
            float z = zp[i] * inv_scale_n;
            float coef = 1.f + 1.f / (z + 1e-6f);
            float prev = (i == 0) ? vp : ((i == 1) ? vc : vn[i - 2]);
            float cur  = (i == 0) ? vc : vn[i - 1];
            float next = vn[i];
            float res  = acc[i] * coef - z * vm;
            float lepe = prev * w0 + cur * w1 + next * w2 + bl;
            ph[(size_t)(b * NN + n0 + g + i) * INTERNAL + c] =
                __float2half((res + lepe) * ov[i]);
        }

        vp = vn[RG - 2];
        vc = vn[RG - 1];
    }
}

// ---------------- launch -----------------------------------------------------
extern "C" void kernel_launch(void* const* d_in, const int* in_sizes, int n_in,
                              void* d_out, int out_size)
{
    const float* x       = (const float*)d_in[0];
    const float* sinp    = (const float*)d_in[1];
    const float* cosp    = (const float*)d_in[2];
    const float* W_qkvo  = (const float*)d_in[3];
    const float* b_qkvo  = (const float*)d_in[4];
    const float* W_lepe  = (const float*)d_in[5];
    const float* b_lepe  = (const float*)d_in[6];
    const float* W_proj  = (const float*)d_in[7];
    const float* b_proj  = (const float*)d_in[8];
    float* out = (float*)d_out;

    __half *qkvo_p, *xh, *ph, *wqh, *pwh;
    cudaGetSymbolAddress((void**)&qkvo_p, g_qkvo);
    cudaGetSymbolAddress((void**)&xh,  g_xh);
    cudaGetSymbolAddress((void**)&ph,  g_ph);
    cudaGetSymbolAddress((void**)&wqh, g_wqh);
    cudaGetSymbolAddress((void**)&pwh, g_pwh);

    cudaFuncSetAttribute(gemm_h_kernel<__half>,
                         cudaFuncAttributeMaxDynamicSharedMemorySize, GEMM_SMEM_BYTES);
    cudaFuncSetAttribute(gemm_h_kernel<float>,
                         cudaFuncAttributeMaxDynamicSharedMemorySize, GEMM_SMEM_BYTES);
    cudaFuncSetAttribute(stats_kernel,
                         cudaFuncAttributeMaxDynamicSharedMemorySize, STATS_SMEM);

    cvt_all_kernel<<<(CVT_N1 + CVT_N2 + CVT_N3 + 255) / 256, 256>>>(
        x, W_qkvo, W_proj, xh, wqh, pwh);

    // GEMM1: qkvo = x @ W_qkvo^T + b_qkvo   [32768 x 1024] -> fp16
    gemm_h_kernel<__half><<<dim3(QKVO_COLS / 128, MROWS / 128), 256, GEMM_SMEM_BYTES>>>(
        xh, wqh, b_qkvo, qkvo_p, MROWS, QKVO_COLS, DIMV);

    stats_kernel<<<dim3(BB * HH, 32), 256, STATS_SMEM>>>(qkvo_p, sinp, cosp);

    fuse_kernel<<<BB * (NN / TILE_ROWS), 256>>>(qkvo_p, sinp, cosp,
                                                W_lepe, b_lepe, ph);

    // GEMM2: out = pre @ W_proj^T + b_proj  [32768 x 256] -> fp32
    gemm_h_kernel<float><<<dim3(INTERNAL / 128, MROWS / 128), 256, GEMM_SMEM_BYTES>>>(
        ph, pwh, b_proj, out, MROWS, INTERNAL, DIMV);
}